// round 3
// baseline (speedup 1.0000x reference)
#include <cuda_runtime.h>
#include <cstdint>

#define BB  4
#define NN  4096
#define NBK 16
#define CD  128
#define HID 64
#define ROWS (BB*NN)            // 16384
#define PAIRS (BB*NBK)          // 64
#define NSPLIT 8

// ---------------- scratch (device globals; no allocation allowed) ----------
__device__ float g_qkv [ROWS*3*CD];          // [b][n][384]   25 MB
__device__ float g_invq[ROWS];
__device__ float g_kvp [NSPLIT][PAIRS*CD*CD];// split partials 32 MB; [0]=reduced
__device__ float g_agg [ROWS*CD];            // 8 MB
__device__ float g_hid [ROWS*4*CD];          // 33 MB
__device__ int   g_idx64;

__device__ __forceinline__ float4 ld4(const float* p) { return *(const float4*)p; }
__device__ __forceinline__ void   st4(float* p, float4 v) { *(float4*)p = v; }

__device__ __forceinline__ int ld_idx(const void* p, size_t pos) {
    if (g_idx64) return (int)((const long long*)p)[pos];
    return ((const int*)p)[pos];
}

// ---------------- idx dtype autodetect -------------------------------------
// If idx is int64 with values < 4096, every odd 32-bit word is 0.
__global__ void k_detect(const unsigned int* __restrict__ w) {
    __shared__ int any;
    if (threadIdx.x == 0) any = 0;
    __syncthreads();
    unsigned int v = w[1 + 2 * threadIdx.x];
    if (v != 0u) any = 1;  // benign race
    __syncthreads();
    if (threadIdx.x == 0) g_idx64 = (any ? 0 : 1);
}

// ---------------- K1: qkv = x^T @ Wqkv^T  ([B,N,384]) ----------------------
__global__ void __launch_bounds__(256) k_qkv(const float* __restrict__ x,
                                             const float* __restrict__ Wqkv) {
    __shared__ float As[32][64];   // [cc][n]
    __shared__ float Bs[32][68];   // [cc][o] padded
    const int b  = blockIdx.z;
    const int n0 = blockIdx.y * 64;
    const int o0 = blockIdx.x * 64;
    const int tid = threadIdx.x;
    const int tx = tid & 15, ty = tid >> 4;
    float acc[4][4] = {};
    for (int c0 = 0; c0 < CD; c0 += 32) {
#pragma unroll
        for (int p = 0; p < 8; p++) {
            int v = tid + p * 256;
            int cc = v >> 6, i = v & 63;
            As[cc][i] = x[((size_t)b * CD + c0 + cc) * NN + n0 + i];
        }
#pragma unroll
        for (int p = 0; p < 8; p++) {
            int v = tid + p * 256;
            int cc = v & 31, j = v >> 5;
            Bs[cc][j] = Wqkv[(size_t)(o0 + j) * CD + c0 + cc];
        }
        __syncthreads();
#pragma unroll
        for (int kk = 0; kk < 32; kk++) {
            float4 a = ld4(&As[kk][ty * 4]);
            float4 w = ld4(&Bs[kk][tx * 4]);
            float av[4] = {a.x, a.y, a.z, a.w};
            float wv[4] = {w.x, w.y, w.z, w.w};
#pragma unroll
            for (int i = 0; i < 4; i++)
#pragma unroll
                for (int j = 0; j < 4; j++) acc[i][j] += av[i] * wv[j];
        }
        __syncthreads();
    }
#pragma unroll
    for (int i = 0; i < 4; i++) {
        size_t ob = ((size_t)b * NN + n0 + ty * 4 + i) * (3 * CD) + o0 + tx * 4;
        st4(&g_qkv[ob], make_float4(acc[i][0], acc[i][1], acc[i][2], acc[i][3]));
    }
}

// ---------------- K1b: 1/||Q_row|| ----------------------------------------
__global__ void __launch_bounds__(256) k_invq() {
    int row  = blockIdx.x * 8 + (threadIdx.x >> 5);
    int lane = threadIdx.x & 31;
    float4 q = ld4(&g_qkv[(size_t)row * (3 * CD) + lane * 4]);
    float s = q.x * q.x + q.y * q.y + q.z * q.z + q.w * q.w;
#pragma unroll
    for (int o = 16; o; o >>= 1) s += __shfl_xor_sync(0xffffffffu, s, o);
    if (lane == 0) g_invq[row] = 1.0f / fmaxf(sqrtf(s), 1e-12f);
}

// ---------------- K2: FUSED pos-MLP + gather + norm + kv outer product -----
// grid (NSPLIT, PAIRS); block owns pair p=(b,k), n-range of NN/NSPLIT rows.
// Per 8-row step: feats -> MLP1 -> MLP2+gather+l2norm/relu into As/Bs smem
// tiles -> 128x128 rank-8 outer-product accumulation (8x8 per thread).
__global__ void __launch_bounds__(256) k_kvfused(
    const float* __restrict__ pos, const void* __restrict__ idx,
    const float* __restrict__ dist,
    const float* __restrict__ W1, const float* __restrict__ b1,
    const float* __restrict__ W2, const float* __restrict__ b2) {
    __shared__ float W2s[HID * CD];     // [j][c]  32 KB
    __shared__ float W1s[HID * 10];
    __shared__ float b1s[HID];
    __shared__ float b2s[CD];
    __shared__ float feats[8][12];
    __shared__ float hs[8][HID];
    __shared__ int   jr[8];
    __shared__ float As[8][CD];         // Knorm rows
    __shared__ float Bs[8][CD];         // Vrel rows

    const int p = blockIdx.y;           // pair: b = p>>4, k = p&15
    const int s = blockIdx.x;           // n-split
    const int b = p >> 4, kslot = p & 15;
    const int tid = threadIdx.x;
    const int tx = tid & 15, ty = tid >> 4;
    const int cb = ty * 8, db = tx * 8;          // outer-product tile coords
    const int lane = tid & 31, warp = tid >> 5;  // MLP2: 1 warp per row
    const int c4 = lane * 4;

    for (int v = tid; v < HID * 10; v += 256) W1s[v] = W1[v];
    if (tid < HID) b1s[tid] = b1[tid];
    if (tid < CD)  b2s[tid] = b2[tid];
    for (int v = tid; v < CD * HID; v += 256) {
        int c = v / HID, j = v % HID;   // coalesced read of W2[c][j]
        W2s[j * CD + c] = W2[v];
    }

    float acc[8][8] = {};
    const int n0 = s * (NN / NSPLIT);
    const int NSTEP = (NN / NSPLIT) / 8;
    for (int step = 0; step < NSTEP; step++) {
        const int nbase = n0 + step * 8;
        __syncthreads();                 // prev-iter As/Bs reads done
        if (tid < 8) {
            int n = nbase + tid;
            size_t g = ((size_t)(b * NN + n)) * NBK + kslot;
            int j = ld_idx(idx, g);
            jr[tid] = j;
            const float* pc = &pos[((size_t)b * NN + n) * 3];
            const float* pn = &pos[((size_t)b * NN + j) * 3];
            float a0 = pc[0], a1 = pc[1], a2 = pc[2];
            float q0 = pn[0], q1 = pn[1], q2 = pn[2];
            feats[tid][0] = a0;  feats[tid][1] = a1;  feats[tid][2] = a2;
            feats[tid][3] = q0;  feats[tid][4] = q1;  feats[tid][5] = q2;
            feats[tid][6] = a0 - q0; feats[tid][7] = a1 - q1; feats[tid][8] = a2 - q2;
            feats[tid][9] = dist[g];
        }
        __syncthreads();
        // MLP1: 8 rows x 64 hid over 256 threads (2 each)
#pragma unroll
        for (int pp = 0; pp < 2; pp++) {
            int v = tid + pp * 256;
            int r = v >> 6, j = v & 63;
            float sa = b1s[j];
#pragma unroll
            for (int i = 0; i < 10; i++) sa += feats[r][i] * W1s[j * 10 + i];
            hs[r][j] = fmaxf(sa, 0.0f);
        }
        __syncthreads();
        // MLP2 + gather + norm: warp = row, lane covers 4 cols
        {
            float pe0 = b2s[c4], pe1 = b2s[c4 + 1], pe2 = b2s[c4 + 2], pe3 = b2s[c4 + 3];
#pragma unroll 8
            for (int j = 0; j < HID; j++) {
                float4 w = ld4(&W2s[j * CD + c4]);
                float h = hs[warp][j];
                pe0 += h * w.x; pe1 += h * w.y; pe2 += h * w.z; pe3 += h * w.w;
            }
            const float* qrow = &g_qkv[((size_t)b * NN + jr[warp]) * (3 * CD)];
            float4 kg = ld4(&qrow[CD + c4]);
            float4 vg = ld4(&qrow[2 * CD + c4]);
            float k0 = kg.x + pe0, k1 = kg.y + pe1, k2 = kg.z + pe2, k3 = kg.w + pe3;
            float v0 = fmaxf(vg.x + pe0, 0.f), v1 = fmaxf(vg.y + pe1, 0.f);
            float v2 = fmaxf(vg.z + pe2, 0.f), v3 = fmaxf(vg.w + pe3, 0.f);
            float ss = k0 * k0 + k1 * k1 + k2 * k2 + k3 * k3;
#pragma unroll
            for (int o = 16; o; o >>= 1) ss += __shfl_xor_sync(0xffffffffu, ss, o);
            float sc = 1.0f / fmaxf(sqrtf(ss), 1e-12f);
            st4(&As[warp][c4], make_float4(k0 * sc, k1 * sc, k2 * sc, k3 * sc));
            st4(&Bs[warp][c4], make_float4(v0, v1, v2, v3));
        }
        __syncthreads();
        // rank-8 outer product accumulation
#pragma unroll
        for (int kk = 0; kk < 8; kk++) {
            float4 a0 = ld4(&As[kk][cb]);
            float4 a1 = ld4(&As[kk][cb + 4]);
            float4 b0 = ld4(&Bs[kk][db]);
            float4 b1v = ld4(&Bs[kk][db + 4]);
            float av[8] = {a0.x,a0.y,a0.z,a0.w,a1.x,a1.y,a1.z,a1.w};
            float bv[8] = {b0.x,b0.y,b0.z,b0.w,b1v.x,b1v.y,b1v.z,b1v.w};
#pragma unroll
            for (int i = 0; i < 8; i++)
#pragma unroll
                for (int j = 0; j < 8; j++) acc[i][j] += av[i] * bv[j];
        }
    }
    float* op = &g_kvp[s][(size_t)p * CD * CD];
#pragma unroll
    for (int i = 0; i < 8; i++) {
        st4(&op[(cb + i) * CD + db],     make_float4(acc[i][0], acc[i][1], acc[i][2], acc[i][3]));
        st4(&op[(cb + i) * CD + db + 4], make_float4(acc[i][4], acc[i][5], acc[i][6], acc[i][7]));
    }
}

// ---------------- K3b: reduce split partials into g_kvp[0] ------------------
__global__ void __launch_bounds__(256) k_red() {
    size_t i = ((size_t)blockIdx.x * 256 + threadIdx.x) * 4;
    float4 s = ld4(&g_kvp[0][i]);
#pragma unroll
    for (int t = 1; t < NSPLIT; t++) {
        float4 v = ld4(&g_kvp[t][i]);
        s.x += v.x; s.y += v.y; s.z += v.z; s.w += v.w;
    }
    st4(&g_kvp[0][i], s);
}

// ---------------- K4: agg = (1/N) sum_k Qn_gather @ kv[b,k] -----------------
__global__ void __launch_bounds__(256) k_agg(const void* __restrict__ idx) {
    __shared__ float As[16][68];
    __shared__ float Bs[16][CD];
    __shared__ int   jr[64];
    __shared__ float sc[64];
    const int b  = blockIdx.y;
    const int n0 = blockIdx.x * 64;
    const int tid = threadIdx.x;
    const int tx = tid & 15, ty = tid >> 4;
    const int d0 = tx * 8, r0 = ty * 4;
    float acc[4][8] = {};
    for (int k = 0; k < NBK; k++) {
        __syncthreads();
        if (tid < 64) {
            int j = ld_idx(idx, ((size_t)(b * NN + n0 + tid)) * NBK + k);
            jr[tid] = j;
            sc[tid] = g_invq[b * NN + j];
        }
        const float* kvb = &g_kvp[0][((size_t)(b * NBK + k)) * CD * CD];
        for (int cb = 0; cb < 8; cb++) {
            int c0 = cb * 16;
            __syncthreads();
            {
                int r = tid >> 2, cq = tid & 3;
                int j = jr[r];
                float s = sc[r];
                float4 q = ld4(&g_qkv[((size_t)b * NN + j) * (3 * CD) + c0 + cq * 4]);
                As[cq * 4 + 0][r] = q.x * s;
                As[cq * 4 + 1][r] = q.y * s;
                As[cq * 4 + 2][r] = q.z * s;
                As[cq * 4 + 3][r] = q.w * s;
            }
            {
                int d4 = (tid & 31) * 4, ccb = tid >> 5;
                st4(&Bs[ccb][d4],     ld4(&kvb[(c0 + ccb) * CD + d4]));
                st4(&Bs[ccb + 8][d4], ld4(&kvb[(c0 + ccb + 8) * CD + d4]));
            }
            __syncthreads();
#pragma unroll
            for (int kk = 0; kk < 16; kk++) {
                float4 a  = ld4(&As[kk][r0]);
                float4 b0 = ld4(&Bs[kk][d0]);
                float4 b1 = ld4(&Bs[kk][d0 + 4]);
                float av[4] = {a.x, a.y, a.z, a.w};
                float bv[8] = {b0.x,b0.y,b0.z,b0.w,b1.x,b1.y,b1.z,b1.w};
#pragma unroll
                for (int i = 0; i < 4; i++)
#pragma unroll
                    for (int j = 0; j < 8; j++) acc[i][j] += av[i] * bv[j];
            }
        }
    }
    const float inv = 1.0f / (float)NN;
#pragma unroll
    for (int i = 0; i < 4; i++) {
        size_t ob = ((size_t)b * NN + n0 + r0 + i) * CD + d0;
        st4(&g_agg[ob],     make_float4(acc[i][0]*inv, acc[i][1]*inv, acc[i][2]*inv, acc[i][3]*inv));
        st4(&g_agg[ob + 4], make_float4(acc[i][4]*inv, acc[i][5]*inv, acc[i][6]*inv, acc[i][7]*inv));
    }
}

// ---------------- K5a: h = relu(agg @ Wm1^T + bm1) --------------------------
__global__ void __launch_bounds__(256) k_mlp1(const float* __restrict__ Wm1,
                                              const float* __restrict__ bm1) {
    __shared__ float As[32][68];
    __shared__ float Bs[32][68];
    const int row0 = blockIdx.y * 64;
    const int o0   = blockIdx.x * 64;
    const int tid = threadIdx.x;
    const int tx = tid & 15, ty = tid >> 4;
    float acc[4][4] = {};
    for (int c0 = 0; c0 < CD; c0 += 32) {
#pragma unroll
        for (int p = 0; p < 2; p++) {
            int r = tid >> 2, cq = tid & 3;
            float4 a = ld4(&g_agg[(size_t)(row0 + r) * CD + c0 + p * 16 + cq * 4]);
            As[p*16 + cq*4 + 0][r] = a.x; As[p*16 + cq*4 + 1][r] = a.y;
            As[p*16 + cq*4 + 2][r] = a.z; As[p*16 + cq*4 + 3][r] = a.w;
        }
#pragma unroll
        for (int p = 0; p < 2; p++) {
            int j = (tid >> 3) + p * 32, cq = tid & 7;
            float4 w = ld4(&Wm1[(size_t)(o0 + j) * CD + c0 + cq * 4]);
            Bs[cq*4 + 0][j] = w.x; Bs[cq*4 + 1][j] = w.y;
            Bs[cq*4 + 2][j] = w.z; Bs[cq*4 + 3][j] = w.w;
        }
        __syncthreads();
#pragma unroll
        for (int kk = 0; kk < 32; kk++) {
            float4 a = ld4(&As[kk][ty * 4]);
            float4 w = ld4(&Bs[kk][tx * 4]);
            float av[4] = {a.x, a.y, a.z, a.w};
            float wv[4] = {w.x, w.y, w.z, w.w};
#pragma unroll
            for (int i = 0; i < 4; i++)
#pragma unroll
                for (int j = 0; j < 4; j++) acc[i][j] += av[i] * wv[j];
        }
        __syncthreads();
    }
    float4 bb = ld4(&bm1[o0 + tx * 4]);
#pragma unroll
    for (int i = 0; i < 4; i++) {
        size_t ob = (size_t)(row0 + ty * 4 + i) * (4 * CD) + o0 + tx * 4;
        st4(&g_hid[ob], make_float4(fmaxf(acc[i][0] + bb.x, 0.f), fmaxf(acc[i][1] + bb.y, 0.f),
                                    fmaxf(acc[i][2] + bb.z, 0.f), fmaxf(acc[i][3] + bb.w, 0.f)));
    }
}

// ---------------- K5b: out = h @ Wm2^T + bm2 + x^T, transposed store --------
__global__ void __launch_bounds__(256) k_mlp2(const float* __restrict__ Wm2,
                                              const float* __restrict__ bm2,
                                              const float* __restrict__ x,
                                              float* __restrict__ out) {
    __shared__ float As[16][68];
    __shared__ float Bs[16][132];
    __shared__ float Csm[64][129];
    const int b  = blockIdx.y;
    const int n0 = blockIdx.x * 64;
    const int row0 = b * NN + n0;
    const int tid = threadIdx.x;
    const int tx = tid & 15, ty = tid >> 4;
    const int d0 = tx * 8, r0 = ty * 4;
    float acc[4][8] = {};
    for (int step = 0; step < 32; step++) {
        int o0 = step * 16;
        __syncthreads();
        {
            int r = tid >> 2, oq = tid & 3;
            float4 h = ld4(&g_hid[(size_t)(row0 + r) * (4 * CD) + o0 + oq * 4]);
            As[oq*4 + 0][r] = h.x; As[oq*4 + 1][r] = h.y;
            As[oq*4 + 2][r] = h.z; As[oq*4 + 3][r] = h.w;
        }
#pragma unroll
        for (int p = 0; p < 2; p++) {
            int d = (tid >> 2) + p * 64, oq = tid & 3;
            float4 w = ld4(&Wm2[(size_t)d * (4 * CD) + o0 + oq * 4]);
            Bs[oq*4 + 0][d] = w.x; Bs[oq*4 + 1][d] = w.y;
            Bs[oq*4 + 2][d] = w.z; Bs[oq*4 + 3][d] = w.w;
        }
        __syncthreads();
#pragma unroll
        for (int kk = 0; kk < 16; kk++) {
            float4 a  = ld4(&As[kk][r0]);
            float4 b0 = ld4(&Bs[kk][d0]);
            float4 b1 = ld4(&Bs[kk][d0 + 4]);
            float av[4] = {a.x, a.y, a.z, a.w};
            float bv[8] = {b0.x,b0.y,b0.z,b0.w,b1.x,b1.y,b1.z,b1.w};
#pragma unroll
            for (int i = 0; i < 4; i++)
#pragma unroll
                for (int j = 0; j < 8; j++) acc[i][j] += av[i] * bv[j];
        }
    }
    float4 b2a = ld4(&bm2[d0]);
    float4 b2b = ld4(&bm2[d0 + 4]);
    float bvv[8] = {b2a.x,b2a.y,b2a.z,b2a.w,b2b.x,b2b.y,b2b.z,b2b.w};
    __syncthreads();
#pragma unroll
    for (int i = 0; i < 4; i++)
#pragma unroll
        for (int j = 0; j < 8; j++) Csm[r0 + i][d0 + j] = acc[i][j] + bvv[j];
    __syncthreads();
    for (int v = tid; v < 64 * CD; v += 256) {
        int dd = v >> 6, nn = v & 63;
        size_t oa = ((size_t)b * CD + dd) * NN + n0 + nn;
        out[oa] = Csm[nn][dd] + x[oa];
    }
}

// ---------------- launcher ---------------------------------------------------
extern "C" void kernel_launch(void* const* d_in, const int* in_sizes, int n_in,
                              void* d_out, int out_size) {
    (void)in_sizes; (void)n_in; (void)out_size;
    const float* pos  = (const float*)d_in[0];
    const float* x    = (const float*)d_in[1];
    const void*  idx  = d_in[2];
    const float* dist = (const float*)d_in[3];
    const float* Wqkv = (const float*)d_in[4];
    const float* W1   = (const float*)d_in[5];
    const float* b1   = (const float*)d_in[6];
    const float* W2   = (const float*)d_in[7];
    const float* b2   = (const float*)d_in[8];
    const float* Wm1  = (const float*)d_in[9];
    const float* bm1  = (const float*)d_in[10];
    const float* Wm2  = (const float*)d_in[11];
    const float* bm2  = (const float*)d_in[12];
    float* out = (float*)d_out;

    k_detect <<<1, 256>>>((const unsigned int*)idx);
    k_qkv    <<<dim3(6, NN / 64, BB), 256>>>(x, Wqkv);
    k_invq   <<<ROWS / 8, 256>>>();
    k_kvfused<<<dim3(NSPLIT, PAIRS), 256>>>(pos, idx, dist, W1, b1, W2, b2);
    k_red    <<<(PAIRS * CD * CD) / (256 * 4), 256>>>();
    k_agg    <<<dim3(NN / 64, BB), 256>>>(idx);
    k_mlp1   <<<dim3(8, ROWS / 64), 256>>>(Wm1, bm1);
    k_mlp2   <<<dim3(NN / 64, BB), 256>>>(Wm2, bm2, x, out);
}

// round 4
// speedup vs baseline: 1.0950x; 1.0950x over previous
#include <cuda_runtime.h>
#include <cstdint>

#define BB  4
#define NN  4096
#define NBK 16
#define CD  128
#define HID 64
#define ROWS (BB*NN)            // 16384
#define GROWS (BB*NN*NBK)       // 262144
#define PAIRS (BB*NBK)          // 64
#define NSPLIT 8

// ---------------- scratch (device globals; no allocation allowed) ----------
__device__ float g_qkv [ROWS*3*CD];          // 25 MB
__device__ float g_invq[ROWS];
__device__ float g_pe  [(size_t)GROWS*CD];   // pos_emb, 134 MB
__device__ float g_kvp [NSPLIT][PAIRS*CD*CD];// split partials 32 MB; [0]=reduced
__device__ float g_aggp[2][ROWS*CD];         // k-split agg partials, 16 MB
__device__ float g_hid [ROWS*4*CD];          // 33 MB
__device__ int   g_idx64;

typedef unsigned long long u64;
__device__ __forceinline__ float4 ld4(const float* p) { return *(const float4*)p; }
__device__ __forceinline__ void   st4(float* p, float4 v) { *(float4*)p = v; }
__device__ __forceinline__ u64 splat2(float a) {
    u64 r; asm("mov.b64 %0, {%1, %1};" : "=l"(r) : "f"(a)); return r;
}
__device__ __forceinline__ u64 pack2(float lo, float hi) {
    u64 r; asm("mov.b64 %0, {%1, %2};" : "=l"(r) : "f"(lo), "f"(hi)); return r;
}
__device__ __forceinline__ void fma2(u64& d, u64 a, u64 b) {
    asm("fma.rn.f32x2 %0, %1, %2, %0;" : "+l"(d) : "l"(a), "l"(b));
}
__device__ __forceinline__ void unp(u64 v, float& lo, float& hi) {
    asm("mov.b64 {%0, %1}, %2;" : "=f"(lo), "=f"(hi) : "l"(v));
}

__device__ __forceinline__ int ld_idx(const void* p, size_t pos) {
    if (g_idx64) return (int)((const long long*)p)[pos];
    return ((const int*)p)[pos];
}

// ---------------- idx dtype autodetect -------------------------------------
__global__ void k_detect(const unsigned int* __restrict__ w) {
    __shared__ int any;
    if (threadIdx.x == 0) any = 0;
    __syncthreads();
    unsigned int v = w[1 + 2 * threadIdx.x];
    if (v != 0u) any = 1;
    __syncthreads();
    if (threadIdx.x == 0) g_idx64 = (any ? 0 : 1);
}

// ---------------- K1: qkv = x^T @ Wqkv^T ------------------------------------
__global__ void __launch_bounds__(256) k_qkv(const float* __restrict__ x,
                                             const float* __restrict__ Wqkv) {
    __shared__ float As[32][64];
    __shared__ float Bs[32][68];
    const int b  = blockIdx.z;
    const int n0 = blockIdx.y * 64;
    const int o0 = blockIdx.x * 64;
    const int tid = threadIdx.x;
    const int tx = tid & 15, ty = tid >> 4;
    u64 acc[4][2] = {};
    for (int c0 = 0; c0 < CD; c0 += 32) {
#pragma unroll
        for (int p = 0; p < 8; p++) {
            int v = tid + p * 256;
            int cc = v >> 6, i = v & 63;
            As[cc][i] = x[((size_t)b * CD + c0 + cc) * NN + n0 + i];
        }
#pragma unroll
        for (int p = 0; p < 8; p++) {
            int v = tid + p * 256;
            int cc = v & 31, j = v >> 5;
            Bs[cc][j] = Wqkv[(size_t)(o0 + j) * CD + c0 + cc];
        }
        __syncthreads();
#pragma unroll
        for (int kk = 0; kk < 32; kk++) {
            float4 a = ld4(&As[kk][ty * 4]);
            const u64* wp = (const u64*)&Bs[kk][tx * 4];
            u64 w0 = wp[0], w1 = wp[1];
            u64 s;
            s = splat2(a.x); fma2(acc[0][0], s, w0); fma2(acc[0][1], s, w1);
            s = splat2(a.y); fma2(acc[1][0], s, w0); fma2(acc[1][1], s, w1);
            s = splat2(a.z); fma2(acc[2][0], s, w0); fma2(acc[2][1], s, w1);
            s = splat2(a.w); fma2(acc[3][0], s, w0); fma2(acc[3][1], s, w1);
        }
        __syncthreads();
    }
#pragma unroll
    for (int i = 0; i < 4; i++) {
        float4 o; unp(acc[i][0], o.x, o.y); unp(acc[i][1], o.z, o.w);
        size_t ob = ((size_t)b * NN + n0 + ty * 4 + i) * (3 * CD) + o0 + tx * 4;
        st4(&g_qkv[ob], o);
    }
}

// ---------------- K1b: 1/||Q_row|| ------------------------------------------
__global__ void __launch_bounds__(256) k_invq() {
    int row  = blockIdx.x * 8 + (threadIdx.x >> 5);
    int lane = threadIdx.x & 31;
    float4 q = ld4(&g_qkv[(size_t)row * (3 * CD) + lane * 4]);
    float s = q.x * q.x + q.y * q.y + q.z * q.z + q.w * q.w;
#pragma unroll
    for (int o = 16; o; o >>= 1) s += __shfl_xor_sync(0xffffffffu, s, o);
    if (lane == 0) g_invq[row] = 1.0f / fmaxf(sqrtf(s), 1e-12f);
}

// ---------------- K2: pos-MLP -> g_pe [GROWS][CD] ---------------------------
// 32 rows/block; feats -> MLP1(10->64) -> tiled MLP2 (64->128), 4x4/thread
__global__ void __launch_bounds__(256) k_pe(
    const float* __restrict__ pos, const void* __restrict__ idx,
    const float* __restrict__ dist,
    const float* __restrict__ W1, const float* __restrict__ b1,
    const float* __restrict__ W2, const float* __restrict__ b2) {
    __shared__ float W2s[HID][CD];      // 32 KB, [j][c]
    __shared__ float hsT[HID][36];      // [j][row] padded
    __shared__ float W1s[HID * 10];
    __shared__ float b1s[HID];
    __shared__ float b2s[CD];
    __shared__ float feats[32][12];
    const int tid = threadIdx.x;
    const size_t g0 = (size_t)blockIdx.x * 32;

    for (int v = tid; v < HID * 10; v += 256) W1s[v] = W1[v];
    if (tid < HID) b1s[tid] = b1[tid];
    if (tid < CD)  b2s[tid] = b2[tid];
    for (int v = tid; v < CD * HID; v += 256) {
        int c = v / HID, j = v % HID;
        W2s[j][c] = W2[v];
    }
    if (tid < 32) {
        size_t g = g0 + tid;
        int b = (int)(g >> 16);
        int n = (int)((g >> 4) & (NN - 1));
        int j = ld_idx(idx, g);
        const float* pc = &pos[((size_t)b * NN + n) * 3];
        const float* pn = &pos[((size_t)b * NN + j) * 3];
        float a0 = pc[0], a1 = pc[1], a2 = pc[2];
        float q0 = pn[0], q1 = pn[1], q2 = pn[2];
        feats[tid][0] = a0;  feats[tid][1] = a1;  feats[tid][2] = a2;
        feats[tid][3] = q0;  feats[tid][4] = q1;  feats[tid][5] = q2;
        feats[tid][6] = a0 - q0; feats[tid][7] = a1 - q1; feats[tid][8] = a2 - q2;
        feats[tid][9] = dist[g];
    }
    __syncthreads();
    // MLP1: 32 rows x 64 hid; 8 outputs/thread, transposed store
#pragma unroll
    for (int p = 0; p < 8; p++) {
        int v = tid + p * 256;
        int r = v >> 6, j = v & 63;
        float s = b1s[j];
#pragma unroll
        for (int i = 0; i < 10; i++) s += feats[r][i] * W1s[j * 10 + i];
        hsT[j][r] = fmaxf(s, 0.0f);
    }
    __syncthreads();
    // MLP2: 4 rows x 4 cols per thread, f32x2
    const int tx = tid & 31, ty = tid >> 5;
    const int c0 = tx * 4, r0 = ty * 4;
    u64 acc[4][2];
    u64 bini0 = pack2(b2s[c0], b2s[c0 + 1]);
    u64 bini1 = pack2(b2s[c0 + 2], b2s[c0 + 3]);
#pragma unroll
    for (int i = 0; i < 4; i++) { acc[i][0] = bini0; acc[i][1] = bini1; }
#pragma unroll 8
    for (int j = 0; j < HID; j++) {
        float4 a = ld4(&hsT[j][r0]);
        const u64* wp = (const u64*)&W2s[j][c0];
        u64 w0 = wp[0], w1 = wp[1];
        u64 s;
        s = splat2(a.x); fma2(acc[0][0], s, w0); fma2(acc[0][1], s, w1);
        s = splat2(a.y); fma2(acc[1][0], s, w0); fma2(acc[1][1], s, w1);
        s = splat2(a.z); fma2(acc[2][0], s, w0); fma2(acc[2][1], s, w1);
        s = splat2(a.w); fma2(acc[3][0], s, w0); fma2(acc[3][1], s, w1);
    }
#pragma unroll
    for (int i = 0; i < 4; i++) {
        float4 o; unp(acc[i][0], o.x, o.y); unp(acc[i][1], o.z, o.w);
        st4(&g_pe[(g0 + r0 + i) * CD + c0], o);
    }
}

// ---------------- K3: kv outer product (gather + norm fused) ----------------
// grid (NSPLIT, PAIRS); 16 rows/step; 8x8 per thread, f32x2
__global__ void __launch_bounds__(256) k_kv(const void* __restrict__ idx) {
    __shared__ float As[16][CD];
    __shared__ float Bs[16][CD];
    const int p = blockIdx.y;
    const int s = blockIdx.x;
    const int b = p >> 4, kslot = p & 15;
    const int tid = threadIdx.x;
    const int tx = tid & 15, ty = tid >> 4;
    const int cb = ty * 8, db = tx * 8;
    const int lane = tid & 31, warp = tid >> 5;
    const int c4 = lane * 4;

    u64 acc[8][4] = {};
    const int n0 = s * (NN / NSPLIT);
    const int NSTEP = (NN / NSPLIT) / 16;
    for (int step = 0; step < NSTEP; step++) {
        const int nbase = n0 + step * 16;
        __syncthreads();   // prior compute done before overwrite
#pragma unroll
        for (int rr = 0; rr < 2; rr++) {
            int row = warp * 2 + rr;
            int n = nbase + row;
            size_t g = ((size_t)(b * NN + n)) * NBK + kslot;
            int j = ld_idx(idx, g);
            float4 pe = ld4(&g_pe[g * CD + c4]);
            const float* qrow = &g_qkv[((size_t)b * NN + j) * (3 * CD)];
            float4 kg = ld4(&qrow[CD + c4]);
            float4 vg = ld4(&qrow[2 * CD + c4]);
            float k0 = kg.x + pe.x, k1 = kg.y + pe.y, k2 = kg.z + pe.z, k3 = kg.w + pe.w;
            float v0 = fmaxf(vg.x + pe.x, 0.f), v1 = fmaxf(vg.y + pe.y, 0.f);
            float v2 = fmaxf(vg.z + pe.z, 0.f), v3 = fmaxf(vg.w + pe.w, 0.f);
            float ss = k0 * k0 + k1 * k1 + k2 * k2 + k3 * k3;
#pragma unroll
            for (int o = 16; o; o >>= 1) ss += __shfl_xor_sync(0xffffffffu, ss, o);
            float sc = 1.0f / fmaxf(sqrtf(ss), 1e-12f);
            st4(&As[row][c4], make_float4(k0 * sc, k1 * sc, k2 * sc, k3 * sc));
            st4(&Bs[row][c4], make_float4(v0, v1, v2, v3));
        }
        __syncthreads();
#pragma unroll
        for (int kk = 0; kk < 16; kk++) {
            float4 a0 = ld4(&As[kk][cb]);
            float4 a1 = ld4(&As[kk][cb + 4]);
            const u64* bp = (const u64*)&Bs[kk][db];
            u64 b0 = bp[0], b1 = bp[1], b2 = bp[2], b3 = bp[3];
            float av[8] = {a0.x,a0.y,a0.z,a0.w,a1.x,a1.y,a1.z,a1.w};
#pragma unroll
            for (int i = 0; i < 8; i++) {
                u64 sa = splat2(av[i]);
                fma2(acc[i][0], sa, b0); fma2(acc[i][1], sa, b1);
                fma2(acc[i][2], sa, b2); fma2(acc[i][3], sa, b3);
            }
        }
    }
    float* op = &g_kvp[s][(size_t)p * CD * CD];
#pragma unroll
    for (int i = 0; i < 8; i++) {
        float o[8];
        unp(acc[i][0], o[0], o[1]); unp(acc[i][1], o[2], o[3]);
        unp(acc[i][2], o[4], o[5]); unp(acc[i][3], o[6], o[7]);
        st4(&op[(cb + i) * CD + db],     make_float4(o[0], o[1], o[2], o[3]));
        st4(&op[(cb + i) * CD + db + 4], make_float4(o[4], o[5], o[6], o[7]));
    }
}

// ---------------- K3b: reduce split partials into g_kvp[0] ------------------
__global__ void __launch_bounds__(256) k_red() {
    size_t i = ((size_t)blockIdx.x * 256 + threadIdx.x) * 4;
    float4 s = ld4(&g_kvp[0][i]);
#pragma unroll
    for (int t = 1; t < NSPLIT; t++) {
        float4 v = ld4(&g_kvp[t][i]);
        s.x += v.x; s.y += v.y; s.z += v.z; s.w += v.w;
    }
    st4(&g_kvp[0][i], s);
}

// ---------------- K4: agg partials; 128x128 tile, 8x8/thread, k-split 2 -----
__global__ void __launch_bounds__(256) k_agg(const void* __restrict__ idx) {
    __shared__ float As[8][132];
    __shared__ float Bs[8][CD];
    __shared__ int   jr[128];
    __shared__ float sc[128];
    const int kh = blockIdx.x;          // 0/1
    const int rt = blockIdx.y;          // 0..127
    const int row0 = rt * 128;          // flattened b*NN+n
    const int b = row0 >> 12;
    const int tid = threadIdx.x;
    const int tx = tid & 15, ty = tid >> 4;
    const int d0 = tx * 8, r0 = ty * 8;
    u64 acc[8][4] = {};
    for (int ks = 0; ks < 8; ks++) {
        const int k = kh * 8 + ks;
        __syncthreads();
        if (tid < 128) {
            int j = ld_idx(idx, ((size_t)(row0 + tid)) * NBK + k);
            jr[tid] = j;
            sc[tid] = g_invq[b * NN + j];
        }
        __syncthreads();
        const float* kvb = &g_kvp[0][((size_t)(b * NBK + k)) * CD * CD];
        for (int cbk = 0; cbk < 16; cbk++) {
            const int c0 = cbk * 8;
            __syncthreads();
            {
                int r = tid >> 1, half = tid & 1;
                float s = sc[r]; int j = jr[r];
                float4 q = ld4(&g_qkv[((size_t)b * NN + j) * (3 * CD) + c0 + half * 4]);
                As[half * 4 + 0][r] = q.x * s;
                As[half * 4 + 1][r] = q.y * s;
                As[half * 4 + 2][r] = q.z * s;
                As[half * 4 + 3][r] = q.w * s;
            }
            {
                int cc = tid >> 5, d4 = (tid & 31) * 4;
                st4(&Bs[cc][d4], ld4(&kvb[(size_t)(c0 + cc) * CD + d4]));
            }
            __syncthreads();
#pragma unroll
            for (int kk = 0; kk < 8; kk++) {
                float4 a0 = ld4(&As[kk][r0]);
                float4 a1 = ld4(&As[kk][r0 + 4]);
                const u64* bp = (const u64*)&Bs[kk][d0];
                u64 b0 = bp[0], b1 = bp[1], b2 = bp[2], b3 = bp[3];
                float av[8] = {a0.x,a0.y,a0.z,a0.w,a1.x,a1.y,a1.z,a1.w};
#pragma unroll
                for (int i = 0; i < 8; i++) {
                    u64 sa = splat2(av[i]);
                    fma2(acc[i][0], sa, b0); fma2(acc[i][1], sa, b1);
                    fma2(acc[i][2], sa, b2); fma2(acc[i][3], sa, b3);
                }
            }
        }
    }
    const float inv = 1.0f / (float)NN;
#pragma unroll
    for (int i = 0; i < 8; i++) {
        float o[8];
        unp(acc[i][0], o[0], o[1]); unp(acc[i][1], o[2], o[3]);
        unp(acc[i][2], o[4], o[5]); unp(acc[i][3], o[6], o[7]);
        size_t ob = (size_t)(row0 + r0 + i) * CD + d0;
        st4(&g_aggp[kh][ob],     make_float4(o[0]*inv, o[1]*inv, o[2]*inv, o[3]*inv));
        st4(&g_aggp[kh][ob + 4], make_float4(o[4]*inv, o[5]*inv, o[6]*inv, o[7]*inv));
    }
}

// ---------------- K5a: h = relu((agg0+agg1) @ Wm1^T + bm1) ------------------
__global__ void __launch_bounds__(256) k_mlp1(const float* __restrict__ Wm1,
                                              const float* __restrict__ bm1) {
    __shared__ float As[32][68];
    __shared__ float Bs[32][68];
    const int row0 = blockIdx.y * 64;
    const int o0   = blockIdx.x * 64;
    const int tid = threadIdx.x;
    const int tx = tid & 15, ty = tid >> 4;
    u64 acc[4][2] = {};
    for (int c0 = 0; c0 < CD; c0 += 32) {
#pragma unroll
        for (int p = 0; p < 2; p++) {
            int r = tid >> 2, cq = tid & 3;
            size_t off = (size_t)(row0 + r) * CD + c0 + p * 16 + cq * 4;
            float4 a = ld4(&g_aggp[0][off]);
            float4 a2 = ld4(&g_aggp[1][off]);
            a.x += a2.x; a.y += a2.y; a.z += a2.z; a.w += a2.w;
            As[p*16 + cq*4 + 0][r] = a.x; As[p*16 + cq*4 + 1][r] = a.y;
            As[p*16 + cq*4 + 2][r] = a.z; As[p*16 + cq*4 + 3][r] = a.w;
        }
#pragma unroll
        for (int p = 0; p < 2; p++) {
            int j = (tid >> 3) + p * 32, cq = tid & 7;
            float4 w = ld4(&Wm1[(size_t)(o0 + j) * CD + c0 + cq * 4]);
            Bs[cq*4 + 0][j] = w.x; Bs[cq*4 + 1][j] = w.y;
            Bs[cq*4 + 2][j] = w.z; Bs[cq*4 + 3][j] = w.w;
        }
        __syncthreads();
#pragma unroll
        for (int kk = 0; kk < 32; kk++) {
            float4 a = ld4(&As[kk][ty * 4]);
            const u64* wp = (const u64*)&Bs[kk][tx * 4];
            u64 w0 = wp[0], w1 = wp[1];
            u64 s;
            s = splat2(a.x); fma2(acc[0][0], s, w0); fma2(acc[0][1], s, w1);
            s = splat2(a.y); fma2(acc[1][0], s, w0); fma2(acc[1][1], s, w1);
            s = splat2(a.z); fma2(acc[2][0], s, w0); fma2(acc[2][1], s, w1);
            s = splat2(a.w); fma2(acc[3][0], s, w0); fma2(acc[3][1], s, w1);
        }
        __syncthreads();
    }
    float4 bb = ld4(&bm1[o0 + tx * 4]);
#pragma unroll
    for (int i = 0; i < 4; i++) {
        float4 o; unp(acc[i][0], o.x, o.y); unp(acc[i][1], o.z, o.w);
        size_t ob = (size_t)(row0 + ty * 4 + i) * (4 * CD) + o0 + tx * 4;
        st4(&g_hid[ob], make_float4(fmaxf(o.x + bb.x, 0.f), fmaxf(o.y + bb.y, 0.f),
                                    fmaxf(o.z + bb.z, 0.f), fmaxf(o.w + bb.w, 0.f)));
    }
}

// ---------------- K5b: out = h @ Wm2^T + bm2 + x^T, transposed store --------
__global__ void __launch_bounds__(256) k_mlp2(const float* __restrict__ Wm2,
                                              const float* __restrict__ bm2,
                                              const float* __restrict__ x,
                                              float* __restrict__ out) {
    __shared__ float As[16][68];
    __shared__ float Bs[16][132];
    __shared__ float Csm[64][129];
    const int b  = blockIdx.y;
    const int n0 = blockIdx.x * 64;
    const int row0 = b * NN + n0;
    const int tid = threadIdx.x;
    const int tx = tid & 15, ty = tid >> 4;
    const int d0 = tx * 8, r0 = ty * 4;
    u64 acc[4][4] = {};
    for (int step = 0; step < 32; step++) {
        int o0 = step * 16;
        __syncthreads();
        {
            int r = tid >> 2, oq = tid & 3;
            float4 h = ld4(&g_hid[(size_t)(row0 + r) * (4 * CD) + o0 + oq * 4]);
            As[oq*4 + 0][r] = h.x; As[oq*4 + 1][r] = h.y;
            As[oq*4 + 2][r] = h.z; As[oq*4 + 3][r] = h.w;
        }
#pragma unroll
        for (int p = 0; p < 2; p++) {
            int d = (tid >> 2) + p * 64, oq = tid & 3;
            float4 w = ld4(&Wm2[(size_t)d * (4 * CD) + o0 + oq * 4]);
            Bs[oq*4 + 0][d] = w.x; Bs[oq*4 + 1][d] = w.y;
            Bs[oq*4 + 2][d] = w.z; Bs[oq*4 + 3][d] = w.w;
        }
        __syncthreads();
#pragma unroll
        for (int kk = 0; kk < 16; kk++) {
            float4 a = ld4(&As[kk][r0]);
            const u64* bp = (const u64*)&Bs[kk][d0];
            u64 b0 = bp[0], b1 = bp[1], b2 = bp[2], b3 = bp[3];
            u64 s;
            s = splat2(a.x); fma2(acc[0][0],s,b0); fma2(acc[0][1],s,b1); fma2(acc[0][2],s,b2); fma2(acc[0][3],s,b3);
            s = splat2(a.y); fma2(acc[1][0],s,b0); fma2(acc[1][1],s,b1); fma2(acc[1][2],s,b2); fma2(acc[1][3],s,b3);
            s = splat2(a.z); fma2(acc[2][0],s,b0); fma2(acc[2][1],s,b1); fma2(acc[2][2],s,b2); fma2(acc[2][3],s,b3);
            s = splat2(a.w); fma2(acc[3][0],s,b0); fma2(acc[3][1],s,b1); fma2(acc[3][2],s,b2); fma2(acc[3][3],s,b3);
        }
    }
    float4 b2a = ld4(&bm2[d0]);
    float4 b2b = ld4(&bm2[d0 + 4]);
    float bvv[8] = {b2a.x,b2a.y,b2a.z,b2a.w,b2b.x,b2b.y,b2b.z,b2b.w};
    __syncthreads();
#pragma unroll
    for (int i = 0; i < 4; i++) {
        float o[8];
        unp(acc[i][0], o[0], o[1]); unp(acc[i][1], o[2], o[3]);
        unp(acc[i][2], o[4], o[5]); unp(acc[i][3], o[6], o[7]);
#pragma unroll
        for (int j = 0; j < 8; j++) Csm[r0 + i][d0 + j] = o[j] + bvv[j];
    }
    __syncthreads();
    for (int v = tid; v < 64 * CD; v += 256) {
        int dd = v >> 6, nn = v & 63;
        size_t oa = ((size_t)b * CD + dd) * NN + n0 + nn;
        out[oa] = Csm[nn][dd] + x[oa];
    }
}

// ---------------- launcher ---------------------------------------------------
extern "C" void kernel_launch(void* const* d_in, const int* in_sizes, int n_in,
                              void* d_out, int out_size) {
    (void)in_sizes; (void)n_in; (void)out_size;
    const float* pos  = (const float*)d_in[0];
    const float* x    = (const float*)d_in[1];
    const void*  idx  = d_in[2];
    const float* dist = (const float*)d_in[3];
    const float* Wqkv = (const float*)d_in[4];
    const float* W1   = (const float*)d_in[5];
    const float* b1   = (const float*)d_in[6];
    const float* W2   = (const float*)d_in[7];
    const float* b2   = (const float*)d_in[8];
    const float* Wm1  = (const float*)d_in[9];
    const float* bm1  = (const float*)d_in[10];
    const float* Wm2  = (const float*)d_in[11];
    const float* bm2  = (const float*)d_in[12];
    float* out = (float*)d_out;

    k_detect<<<1, 256>>>((const unsigned int*)idx);
    k_qkv   <<<dim3(6, NN / 64, BB), 256>>>(x, Wqkv);
    k_invq  <<<ROWS / 8, 256>>>();
    k_pe    <<<GROWS / 32, 256>>>(pos, idx, dist, W1, b1, W2, b2);
    k_kv    <<<dim3(NSPLIT, PAIRS), 256>>>(idx);
    k_red   <<<(PAIRS * CD * CD) / (256 * 4), 256>>>();
    k_agg   <<<dim3(2, ROWS / 128), 256>>>(idx);
    k_mlp1  <<<dim3(8, ROWS / 64), 256>>>(Wm1, bm1);
    k_mlp2  <<<dim3(NN / 64, BB), 256>>>(Wm2, bm2, x, out);
}

// round 6
// speedup vs baseline: 1.2466x; 1.1384x over previous
#include <cuda_runtime.h>
#include <cstdint>

#define BB  4
#define NN  4096
#define NBK 16
#define CD  128
#define HID 64
#define ROWS (BB*NN)            // 16384
#define GROWS (BB*NN*NBK)       // 262144
#define PAIRS (BB*NBK)          // 64
#define NSPLIT 8

// ---------------- scratch (device globals; no allocation allowed) ----------
__device__ float g_qkv [ROWS*3*CD];          // 25 MB
__device__ float g_invq[ROWS];
__device__ float g_pe  [(size_t)GROWS*CD];   // pos_emb, 134 MB
__device__ float g_kvp [NSPLIT][PAIRS*CD*CD];// split partials 32 MB; [0]=reduced
__device__ float g_aggp[2][ROWS*CD];         // k-split agg partials, 16 MB
__device__ float g_hid [ROWS*4*CD];          // 33 MB
__device__ int   g_idx64;

typedef unsigned long long u64;
__device__ __forceinline__ float4 ld4(const float* p) { return *(const float4*)p; }
__device__ __forceinline__ void   st4(float* p, float4 v) { *(float4*)p = v; }
__device__ __forceinline__ u64 splat2(float a) {
    u64 r; asm("mov.b64 %0, {%1, %1};" : "=l"(r) : "f"(a)); return r;
}
__device__ __forceinline__ u64 pack2(float lo, float hi) {
    u64 r; asm("mov.b64 %0, {%1, %2};" : "=l"(r) : "f"(lo), "f"(hi)); return r;
}
__device__ __forceinline__ void fma2(u64& d, u64 a, u64 b) {
    asm("fma.rn.f32x2 %0, %1, %2, %0;" : "+l"(d) : "l"(a), "l"(b));
}
__device__ __forceinline__ void unp(u64 v, float& lo, float& hi) {
    asm("mov.b64 {%0, %1}, %2;" : "=f"(lo), "=f"(hi) : "l"(v));
}

__device__ __forceinline__ int ld_idx(const void* p, size_t pos) {
    if (g_idx64) return (int)((const long long*)p)[pos];
    return ((const int*)p)[pos];
}

// ---------------- idx dtype autodetect -------------------------------------
__global__ void k_detect(const unsigned int* __restrict__ w) {
    __shared__ int any;
    if (threadIdx.x == 0) any = 0;
    __syncthreads();
    unsigned int v = w[1 + 2 * threadIdx.x];
    if (v != 0u) any = 1;
    __syncthreads();
    if (threadIdx.x == 0) g_idx64 = (any ? 0 : 1);
}

// ---------------- K1: qkv = x^T @ Wqkv^T ------------------------------------
__global__ void __launch_bounds__(256) k_qkv(const float* __restrict__ x,
                                             const float* __restrict__ Wqkv) {
    __shared__ float As[32][64];
    __shared__ float Bs[32][68];
    const int b  = blockIdx.z;
    const int n0 = blockIdx.y * 64;
    const int o0 = blockIdx.x * 64;
    const int tid = threadIdx.x;
    const int tx = tid & 15, ty = tid >> 4;
    u64 acc[4][2] = {};
    for (int c0 = 0; c0 < CD; c0 += 32) {
#pragma unroll
        for (int p = 0; p < 8; p++) {
            int v = tid + p * 256;
            int cc = v >> 6, i = v & 63;
            As[cc][i] = x[((size_t)b * CD + c0 + cc) * NN + n0 + i];
        }
#pragma unroll
        for (int p = 0; p < 8; p++) {
            int v = tid + p * 256;
            int cc = v & 31, j = v >> 5;
            Bs[cc][j] = Wqkv[(size_t)(o0 + j) * CD + c0 + cc];
        }
        __syncthreads();
#pragma unroll
        for (int kk = 0; kk < 32; kk++) {
            float4 a = ld4(&As[kk][ty * 4]);
            const u64* wp = (const u64*)&Bs[kk][tx * 4];
            u64 w0 = wp[0], w1 = wp[1];
            u64 s;
            s = splat2(a.x); fma2(acc[0][0], s, w0); fma2(acc[0][1], s, w1);
            s = splat2(a.y); fma2(acc[1][0], s, w0); fma2(acc[1][1], s, w1);
            s = splat2(a.z); fma2(acc[2][0], s, w0); fma2(acc[2][1], s, w1);
            s = splat2(a.w); fma2(acc[3][0], s, w0); fma2(acc[3][1], s, w1);
        }
        __syncthreads();
    }
#pragma unroll
    for (int i = 0; i < 4; i++) {
        float4 o; unp(acc[i][0], o.x, o.y); unp(acc[i][1], o.z, o.w);
        size_t ob = ((size_t)b * NN + n0 + ty * 4 + i) * (3 * CD) + o0 + tx * 4;
        st4(&g_qkv[ob], o);
    }
}

// ---------------- K1b: 1/||Q_row|| ------------------------------------------
__global__ void __launch_bounds__(256) k_invq() {
    int row  = blockIdx.x * 8 + (threadIdx.x >> 5);
    int lane = threadIdx.x & 31;
    float4 q = ld4(&g_qkv[(size_t)row * (3 * CD) + lane * 4]);
    float s = q.x * q.x + q.y * q.y + q.z * q.z + q.w * q.w;
#pragma unroll
    for (int o = 16; o; o >>= 1) s += __shfl_xor_sync(0xffffffffu, s, o);
    if (lane == 0) g_invq[row] = 1.0f / fmaxf(sqrtf(s), 1e-12f);
}

// ---------------- K2: pos-MLP -> g_pe [GROWS][CD] ---------------------------
// 128 rows/block, 8x8 micro-tile f32x2 GEMM, hidden dim in 2 chunks of 32
__global__ void __launch_bounds__(256) k_pe(
    const float* __restrict__ pos, const void* __restrict__ idx,
    const float* __restrict__ dist,
    const float* __restrict__ W1, const float* __restrict__ b1,
    const float* __restrict__ W2, const float* __restrict__ b2) {
    __shared__ float W2s[32][CD];       // 16 KB, chunk of W2, [jj][c]
    __shared__ float hsT[32][132];      // 16.5 KB, [jj][row], stride 132 (16B-aligned)
    __shared__ float W1s[HID * 10];
    __shared__ float b1s[HID];
    __shared__ float b2s[CD];
    __shared__ float feats[128][12];
    const int tid = threadIdx.x;
    const size_t g0 = (size_t)blockIdx.x * 128;
    const int tx = tid & 15, ty = tid >> 4;
    const int c0 = tx * 8, r0 = ty * 8;

    for (int v = tid; v < HID * 10; v += 256) W1s[v] = W1[v];
    if (tid < HID) b1s[tid] = b1[tid];
    if (tid < CD)  b2s[tid] = b2[tid];
    if (tid < 128) {
        size_t g = g0 + tid;
        int b = (int)(g >> 16);
        int n = (int)((g >> 4) & (NN - 1));
        int j = ld_idx(idx, g);
        const float* pc = &pos[((size_t)b * NN + n) * 3];
        const float* pn = &pos[((size_t)b * NN + j) * 3];
        float a0 = pc[0], a1 = pc[1], a2 = pc[2];
        float q0 = pn[0], q1 = pn[1], q2 = pn[2];
        feats[tid][0] = a0;  feats[tid][1] = a1;  feats[tid][2] = a2;
        feats[tid][3] = q0;  feats[tid][4] = q1;  feats[tid][5] = q2;
        feats[tid][6] = a0 - q0; feats[tid][7] = a1 - q1; feats[tid][8] = a2 - q2;
        feats[tid][9] = dist[g];
    }
    __syncthreads();

    u64 acc[8][4];
    {
        u64 bi[4];
#pragma unroll
        for (int q = 0; q < 4; q++) bi[q] = pack2(b2s[c0 + 2*q], b2s[c0 + 2*q + 1]);
#pragma unroll
        for (int i = 0; i < 8; i++)
#pragma unroll
            for (int q = 0; q < 4; q++) acc[i][q] = bi[q];
    }

    for (int jc = 0; jc < 2; jc++) {
        const int j0 = jc * 32;
        if (jc) __syncthreads();   // protect previous chunk's W2s/hsT reads
        // load W2 chunk: W2 is [CD][HID] row-major; W2s[jj][c] = W2[c*HID + j0+jj]
#pragma unroll
        for (int p = 0; p < 16; p++) {
            int v = tid + p * 256;          // v in [0, 4096)
            int c = v >> 5, jj = v & 31;
            W2s[jj][c] = W2[(size_t)c * HID + j0 + jj];
        }
        // MLP1 chunk: hsT[jj][r] for jj in [0,32), r in [0,128)
#pragma unroll
        for (int p = 0; p < 16; p++) {
            int v = tid + p * 256;
            int jj = v & 31, r = v >> 5;
            int j = j0 + jj;
            float s = b1s[j];
#pragma unroll
            for (int i = 0; i < 10; i++) s += feats[r][i] * W1s[j * 10 + i];
            hsT[jj][r] = fmaxf(s, 0.0f);
        }
        __syncthreads();
        // GEMM chunk: 32 kk steps, 8x8 per thread
#pragma unroll 4
        for (int kk = 0; kk < 32; kk++) {
            float4 a0 = ld4(&hsT[kk][r0]);
            float4 a1 = ld4(&hsT[kk][r0 + 4]);
            const u64* bp = (const u64*)&W2s[kk][c0];
            u64 b0 = bp[0], b1v = bp[1], b2v = bp[2], b3 = bp[3];
            float av[8] = {a0.x,a0.y,a0.z,a0.w,a1.x,a1.y,a1.z,a1.w};
#pragma unroll
            for (int i = 0; i < 8; i++) {
                u64 s = splat2(av[i]);
                fma2(acc[i][0], s, b0); fma2(acc[i][1], s, b1v);
                fma2(acc[i][2], s, b2v); fma2(acc[i][3], s, b3);
            }
        }
    }
#pragma unroll
    for (int i = 0; i < 8; i++) {
        float o[8];
        unp(acc[i][0], o[0], o[1]); unp(acc[i][1], o[2], o[3]);
        unp(acc[i][2], o[4], o[5]); unp(acc[i][3], o[6], o[7]);
        size_t ob = (g0 + r0 + i) * CD + c0;
        st4(&g_pe[ob],     make_float4(o[0], o[1], o[2], o[3]));
        st4(&g_pe[ob + 4], make_float4(o[4], o[5], o[6], o[7]));
    }
}

// ---------------- K3: kv outer product (gather + norm fused) ----------------
__global__ void __launch_bounds__(256) k_kv(const void* __restrict__ idx) {
    __shared__ float As[16][CD];
    __shared__ float Bs[16][CD];
    const int p = blockIdx.y;
    const int s = blockIdx.x;
    const int b = p >> 4, kslot = p & 15;
    const int tid = threadIdx.x;
    const int tx = tid & 15, ty = tid >> 4;
    const int cb = ty * 8, db = tx * 8;
    const int lane = tid & 31, warp = tid >> 5;
    const int c4 = lane * 4;

    u64 acc[8][4] = {};
    const int n0 = s * (NN / NSPLIT);
    const int NSTEP = (NN / NSPLIT) / 16;
    for (int step = 0; step < NSTEP; step++) {
        const int nbase = n0 + step * 16;
        __syncthreads();
#pragma unroll
        for (int rr = 0; rr < 2; rr++) {
            int row = warp * 2 + rr;
            int n = nbase + row;
            size_t g = ((size_t)(b * NN + n)) * NBK + kslot;
            int j = ld_idx(idx, g);
            float4 pe = ld4(&g_pe[g * CD + c4]);
            const float* qrow = &g_qkv[((size_t)b * NN + j) * (3 * CD)];
            float4 kg = ld4(&qrow[CD + c4]);
            float4 vg = ld4(&qrow[2 * CD + c4]);
            float k0 = kg.x + pe.x, k1 = kg.y + pe.y, k2 = kg.z + pe.z, k3 = kg.w + pe.w;
            float v0 = fmaxf(vg.x + pe.x, 0.f), v1 = fmaxf(vg.y + pe.y, 0.f);
            float v2 = fmaxf(vg.z + pe.z, 0.f), v3 = fmaxf(vg.w + pe.w, 0.f);
            float ss = k0 * k0 + k1 * k1 + k2 * k2 + k3 * k3;
#pragma unroll
            for (int o = 16; o; o >>= 1) ss += __shfl_xor_sync(0xffffffffu, ss, o);
            float sc = 1.0f / fmaxf(sqrtf(ss), 1e-12f);
            st4(&As[row][c4], make_float4(k0 * sc, k1 * sc, k2 * sc, k3 * sc));
            st4(&Bs[row][c4], make_float4(v0, v1, v2, v3));
        }
        __syncthreads();
#pragma unroll
        for (int kk = 0; kk < 16; kk++) {
            float4 a0 = ld4(&As[kk][cb]);
            float4 a1 = ld4(&As[kk][cb + 4]);
            const u64* bp = (const u64*)&Bs[kk][db];
            u64 b0 = bp[0], b1 = bp[1], b2 = bp[2], b3 = bp[3];
            float av[8] = {a0.x,a0.y,a0.z,a0.w,a1.x,a1.y,a1.z,a1.w};
#pragma unroll
            for (int i = 0; i < 8; i++) {
                u64 sa = splat2(av[i]);
                fma2(acc[i][0], sa, b0); fma2(acc[i][1], sa, b1);
                fma2(acc[i][2], sa, b2); fma2(acc[i][3], sa, b3);
            }
        }
    }
    float* op = &g_kvp[s][(size_t)p * CD * CD];
#pragma unroll
    for (int i = 0; i < 8; i++) {
        float o[8];
        unp(acc[i][0], o[0], o[1]); unp(acc[i][1], o[2], o[3]);
        unp(acc[i][2], o[4], o[5]); unp(acc[i][3], o[6], o[7]);
        st4(&op[(cb + i) * CD + db],     make_float4(o[0], o[1], o[2], o[3]));
        st4(&op[(cb + i) * CD + db + 4], make_float4(o[4], o[5], o[6], o[7]));
    }
}

// ---------------- K3b: reduce split partials into g_kvp[0] ------------------
__global__ void __launch_bounds__(256) k_red() {
    size_t i = ((size_t)blockIdx.x * 256 + threadIdx.x) * 4;
    float4 s = ld4(&g_kvp[0][i]);
#pragma unroll
    for (int t = 1; t < NSPLIT; t++) {
        float4 v = ld4(&g_kvp[t][i]);
        s.x += v.x; s.y += v.y; s.z += v.z; s.w += v.w;
    }
    st4(&g_kvp[0][i], s);
}

// ---------------- K4: agg partials; 128x128 tile, 8x8/thread, k-split 2 -----
__global__ void __launch_bounds__(256) k_agg(const void* __restrict__ idx) {
    __shared__ float As[8][132];
    __shared__ float Bs[8][CD];
    __shared__ int   jr[128];
    __shared__ float sc[128];
    const int kh = blockIdx.x;
    const int rt = blockIdx.y;
    const int row0 = rt * 128;
    const int b = row0 >> 12;
    const int tid = threadIdx.x;
    const int tx = tid & 15, ty = tid >> 4;
    const int d0 = tx * 8, r0 = ty * 8;
    u64 acc[8][4] = {};
    for (int ks = 0; ks < 8; ks++) {
        const int k = kh * 8 + ks;
        __syncthreads();
        if (tid < 128) {
            int j = ld_idx(idx, ((size_t)(row0 + tid)) * NBK + k);
            jr[tid] = j;
            sc[tid] = g_invq[b * NN + j];
        }
        __syncthreads();
        const float* kvb = &g_kvp[0][((size_t)(b * NBK + k)) * CD * CD];
        for (int cbk = 0; cbk < 16; cbk++) {
            const int c0 = cbk * 8;
            __syncthreads();
            {
                int r = tid >> 1, half = tid & 1;
                float s = sc[r]; int j = jr[r];
                float4 q = ld4(&g_qkv[((size_t)b * NN + j) * (3 * CD) + c0 + half * 4]);
                As[half * 4 + 0][r] = q.x * s;
                As[half * 4 + 1][r] = q.y * s;
                As[half * 4 + 2][r] = q.z * s;
                As[half * 4 + 3][r] = q.w * s;
            }
            {
                int cc = tid >> 5, d4 = (tid & 31) * 4;
                st4(&Bs[cc][d4], ld4(&kvb[(size_t)(c0 + cc) * CD + d4]));
            }
            __syncthreads();
#pragma unroll
            for (int kk = 0; kk < 8; kk++) {
                float4 a0 = ld4(&As[kk][r0]);
                float4 a1 = ld4(&As[kk][r0 + 4]);
                const u64* bp = (const u64*)&Bs[kk][d0];
                u64 b0 = bp[0], b1 = bp[1], b2 = bp[2], b3 = bp[3];
                float av[8] = {a0.x,a0.y,a0.z,a0.w,a1.x,a1.y,a1.z,a1.w};
#pragma unroll
                for (int i = 0; i < 8; i++) {
                    u64 sa = splat2(av[i]);
                    fma2(acc[i][0], sa, b0); fma2(acc[i][1], sa, b1);
                    fma2(acc[i][2], sa, b2); fma2(acc[i][3], sa, b3);
                }
            }
        }
    }
    const float inv = 1.0f / (float)NN;
#pragma unroll
    for (int i = 0; i < 8; i++) {
        float o[8];
        unp(acc[i][0], o[0], o[1]); unp(acc[i][1], o[2], o[3]);
        unp(acc[i][2], o[4], o[5]); unp(acc[i][3], o[6], o[7]);
        size_t ob = (size_t)(row0 + r0 + i) * CD + d0;
        st4(&g_aggp[kh][ob],     make_float4(o[0]*inv, o[1]*inv, o[2]*inv, o[3]*inv));
        st4(&g_aggp[kh][ob + 4], make_float4(o[4]*inv, o[5]*inv, o[6]*inv, o[7]*inv));
    }
}

// ---------------- K5a: h = relu((agg0+agg1) @ Wm1^T + bm1) ------------------
__global__ void __launch_bounds__(256) k_mlp1(const float* __restrict__ Wm1,
                                              const float* __restrict__ bm1) {
    __shared__ float As[32][68];
    __shared__ float Bs[32][68];
    const int row0 = blockIdx.y * 64;
    const int o0   = blockIdx.x * 64;
    const int tid = threadIdx.x;
    const int tx = tid & 15, ty = tid >> 4;
    u64 acc[4][2] = {};
    for (int c0 = 0; c0 < CD; c0 += 32) {
#pragma unroll
        for (int p = 0; p < 2; p++) {
            int r = tid >> 2, cq = tid & 3;
            size_t off = (size_t)(row0 + r) * CD + c0 + p * 16 + cq * 4;
            float4 a = ld4(&g_aggp[0][off]);
            float4 a2 = ld4(&g_aggp[1][off]);
            a.x += a2.x; a.y += a2.y; a.z += a2.z; a.w += a2.w;
            As[p*16 + cq*4 + 0][r] = a.x; As[p*16 + cq*4 + 1][r] = a.y;
            As[p*16 + cq*4 + 2][r] = a.z; As[p*16 + cq*4 + 3][r] = a.w;
        }
#pragma unroll
        for (int p = 0; p < 2; p++) {
            int j = (tid >> 3) + p * 32, cq = tid & 7;
            float4 w = ld4(&Wm1[(size_t)(o0 + j) * CD + c0 + cq * 4]);
            Bs[cq*4 + 0][j] = w.x; Bs[cq*4 + 1][j] = w.y;
            Bs[cq*4 + 2][j] = w.z; Bs[cq*4 + 3][j] = w.w;
        }
        __syncthreads();
#pragma unroll
        for (int kk = 0; kk < 32; kk++) {
            float4 a = ld4(&As[kk][ty * 4]);
            const u64* wp = (const u64*)&Bs[kk][tx * 4];
            u64 w0 = wp[0], w1 = wp[1];
            u64 s;
            s = splat2(a.x); fma2(acc[0][0], s, w0); fma2(acc[0][1], s, w1);
            s = splat2(a.y); fma2(acc[1][0], s, w0); fma2(acc[1][1], s, w1);
            s = splat2(a.z); fma2(acc[2][0], s, w0); fma2(acc[2][1], s, w1);
            s = splat2(a.w); fma2(acc[3][0], s, w0); fma2(acc[3][1], s, w1);
        }
        __syncthreads();
    }
    float4 bb = ld4(&bm1[o0 + tx * 4]);
#pragma unroll
    for (int i = 0; i < 4; i++) {
        float4 o; unp(acc[i][0], o.x, o.y); unp(acc[i][1], o.z, o.w);
        size_t ob = (size_t)(row0 + ty * 4 + i) * (4 * CD) + o0 + tx * 4;
        st4(&g_hid[ob], make_float4(fmaxf(o.x + bb.x, 0.f), fmaxf(o.y + bb.y, 0.f),
                                    fmaxf(o.z + bb.z, 0.f), fmaxf(o.w + bb.w, 0.f)));
    }
}

// ---------------- K5b: out = h @ Wm2^T + bm2 + x^T, transposed store --------
__global__ void __launch_bounds__(256) k_mlp2(const float* __restrict__ Wm2,
                                              const float* __restrict__ bm2,
                                              const float* __restrict__ x,
                                              float* __restrict__ out) {
    __shared__ float As[16][68];
    __shared__ float Bs[16][132];
    __shared__ float Csm[64][129];
    const int b  = blockIdx.y;
    const int n0 = blockIdx.x * 64;
    const int row0 = b * NN + n0;
    const int tid = threadIdx.x;
    const int tx = tid & 15, ty = tid >> 4;
    const int d0 = tx * 8, r0 = ty * 4;
    u64 acc[4][4] = {};
    for (int step = 0; step < 32; step++) {
        int o0 = step * 16;
        __syncthreads();
        {
            int r = tid >> 2, oq = tid & 3;
            float4 h = ld4(&g_hid[(size_t)(row0 + r) * (4 * CD) + o0 + oq * 4]);
            As[oq*4 + 0][r] = h.x; As[oq*4 + 1][r] = h.y;
            As[oq*4 + 2][r] = h.z; As[oq*4 + 3][r] = h.w;
        }
#pragma unroll
        for (int p = 0; p < 2; p++) {
            int d = (tid >> 2) + p * 64, oq = tid & 3;
            float4 w = ld4(&Wm2[(size_t)d * (4 * CD) + o0 + oq * 4]);
            Bs[oq*4 + 0][d] = w.x; Bs[oq*4 + 1][d] = w.y;
            Bs[oq*4 + 2][d] = w.z; Bs[oq*4 + 3][d] = w.w;
        }
        __syncthreads();
#pragma unroll
        for (int kk = 0; kk < 16; kk++) {
            float4 a = ld4(&As[kk][r0]);
            const u64* bp = (const u64*)&Bs[kk][d0];
            u64 b0 = bp[0], b1 = bp[1], b2 = bp[2], b3 = bp[3];
            u64 s;
            s = splat2(a.x); fma2(acc[0][0],s,b0); fma2(acc[0][1],s,b1); fma2(acc[0][2],s,b2); fma2(acc[0][3],s,b3);
            s = splat2(a.y); fma2(acc[1][0],s,b0); fma2(acc[1][1],s,b1); fma2(acc[1][2],s,b2); fma2(acc[1][3],s,b3);
            s = splat2(a.z); fma2(acc[2][0],s,b0); fma2(acc[2][1],s,b1); fma2(acc[2][2],s,b2); fma2(acc[2][3],s,b3);
            s = splat2(a.w); fma2(acc[3][0],s,b0); fma2(acc[3][1],s,b1); fma2(acc[3][2],s,b2); fma2(acc[3][3],s,b3);
        }
    }
    float4 b2a = ld4(&bm2[d0]);
    float4 b2b = ld4(&bm2[d0 + 4]);
    float bvv[8] = {b2a.x,b2a.y,b2a.z,b2a.w,b2b.x,b2b.y,b2b.z,b2b.w};
    __syncthreads();
#pragma unroll
    for (int i = 0; i < 4; i++) {
        float o[8];
        unp(acc[i][0], o[0], o[1]); unp(acc[i][1], o[2], o[3]);
        unp(acc[i][2], o[4], o[5]); unp(acc[i][3], o[6], o[7]);
#pragma unroll
        for (int j = 0; j < 8; j++) Csm[r0 + i][d0 + j] = o[j] + bvv[j];
    }
    __syncthreads();
    for (int v = tid; v < 64 * CD; v += 256) {
        int dd = v >> 6, nn = v & 63;
        size_t oa = ((size_t)b * CD + dd) * NN + n0 + nn;
        out[oa] = Csm[nn][dd] + x[oa];
    }
}

// ---------------- launcher ---------------------------------------------------
extern "C" void kernel_launch(void* const* d_in, const int* in_sizes, int n_in,
                              void* d_out, int out_size) {
    (void)in_sizes; (void)n_in; (void)out_size;
    const float* pos  = (const float*)d_in[0];
    const float* x    = (const float*)d_in[1];
    const void*  idx  = d_in[2];
    const float* dist = (const float*)d_in[3];
    const float* Wqkv = (const float*)d_in[4];
    const float* W1   = (const float*)d_in[5];
    const float* b1   = (const float*)d_in[6];
    const float* W2   = (const float*)d_in[7];
    const float* b2   = (const float*)d_in[8];
    const float* Wm1  = (const float*)d_in[9];
    const float* bm1  = (const float*)d_in[10];
    const float* Wm2  = (const float*)d_in[11];
    const float* bm2  = (const float*)d_in[12];
    float* out = (float*)d_out;

    k_detect<<<1, 256>>>((const unsigned int*)idx);
    k_qkv   <<<dim3(6, NN / 64, BB), 256>>>(x, Wqkv);
    k_invq  <<<ROWS / 8, 256>>>();
    k_pe    <<<GROWS / 128, 256>>>(pos, idx, dist, W1, b1, W2, b2);
    k_kv    <<<dim3(NSPLIT, PAIRS), 256>>>(idx);
    k_red   <<<(PAIRS * CD * CD) / (256 * 4), 256>>>();
    k_agg   <<<dim3(2, ROWS / 128), 256>>>(idx);
    k_mlp1  <<<dim3(8, ROWS / 64), 256>>>(Wm1, bm1);
    k_mlp2  <<<dim3(NN / 64, BB), 256>>>(Wm2, bm2, x, out);
}

// round 7
// speedup vs baseline: 1.2921x; 1.0365x over previous
#include <cuda_runtime.h>
#include <cstdint>

#define BB  4
#define NN  4096
#define NBK 16
#define CD  128
#define HID 64
#define ROWS (BB*NN)            // 16384
#define GROWS (BB*NN*NBK)       // 262144
#define PAIRS (BB*NBK)          // 64
#define NSPLIT 8

// ---------------- scratch (device globals; no allocation allowed) ----------
__device__ float g_qkv [ROWS*3*CD];          // 25 MB
__device__ float g_invq[ROWS];
__device__ float g_pe  [(size_t)GROWS*CD];   // pos_emb, 134 MB
__device__ float g_kvp [NSPLIT][PAIRS*CD*CD];// split partials 32 MB; [0]=reduced
__device__ float g_aggp[2][ROWS*CD];         // k-split agg partials, 16 MB
__device__ float g_hid [ROWS*4*CD];          // 33 MB
__device__ int   g_idx64;

typedef unsigned long long u64;
__device__ __forceinline__ float4 ld4(const float* p) { return *(const float4*)p; }
__device__ __forceinline__ void   st4(float* p, float4 v) { *(float4*)p = v; }
__device__ __forceinline__ u64 splat2(float a) {
    u64 r; asm("mov.b64 %0, {%1, %1};" : "=l"(r) : "f"(a)); return r;
}
__device__ __forceinline__ u64 pack2(float lo, float hi) {
    u64 r; asm("mov.b64 %0, {%1, %2};" : "=l"(r) : "f"(lo), "f"(hi)); return r;
}
__device__ __forceinline__ void fma2(u64& d, u64 a, u64 b) {
    asm("fma.rn.f32x2 %0, %1, %2, %0;" : "+l"(d) : "l"(a), "l"(b));
}
__device__ __forceinline__ void unp(u64 v, float& lo, float& hi) {
    asm("mov.b64 {%0, %1}, %2;" : "=f"(lo), "=f"(hi) : "l"(v));
}

__device__ __forceinline__ int ld_idx(const void* p, size_t pos) {
    if (g_idx64) return (int)((const long long*)p)[pos];
    return ((const int*)p)[pos];
}

// ---------------- idx dtype autodetect -------------------------------------
__global__ void k_detect(const unsigned int* __restrict__ w) {
    __shared__ int any;
    if (threadIdx.x == 0) any = 0;
    __syncthreads();
    unsigned int v = w[1 + 2 * threadIdx.x];
    if (v != 0u) any = 1;
    __syncthreads();
    if (threadIdx.x == 0) g_idx64 = (any ? 0 : 1);
}

// ---------------- K1: qkv = x^T @ Wqkv^T ------------------------------------
__global__ void __launch_bounds__(256) k_qkv(const float* __restrict__ x,
                                             const float* __restrict__ Wqkv) {
    __shared__ float As[32][64];
    __shared__ float Bs[32][68];
    const int b  = blockIdx.z;
    const int n0 = blockIdx.y * 64;
    const int o0 = blockIdx.x * 64;
    const int tid = threadIdx.x;
    const int tx = tid & 15, ty = tid >> 4;
    u64 acc[4][2] = {};
    for (int c0 = 0; c0 < CD; c0 += 32) {
#pragma unroll
        for (int p = 0; p < 8; p++) {
            int v = tid + p * 256;
            int cc = v >> 6, i = v & 63;
            As[cc][i] = x[((size_t)b * CD + c0 + cc) * NN + n0 + i];
        }
#pragma unroll
        for (int p = 0; p < 8; p++) {
            int v = tid + p * 256;
            int cc = v & 31, j = v >> 5;
            Bs[cc][j] = Wqkv[(size_t)(o0 + j) * CD + c0 + cc];
        }
        __syncthreads();
#pragma unroll
        for (int kk = 0; kk < 32; kk++) {
            float4 a = ld4(&As[kk][ty * 4]);
            const u64* wp = (const u64*)&Bs[kk][tx * 4];
            u64 w0 = wp[0], w1 = wp[1];
            u64 s;
            s = splat2(a.x); fma2(acc[0][0], s, w0); fma2(acc[0][1], s, w1);
            s = splat2(a.y); fma2(acc[1][0], s, w0); fma2(acc[1][1], s, w1);
            s = splat2(a.z); fma2(acc[2][0], s, w0); fma2(acc[2][1], s, w1);
            s = splat2(a.w); fma2(acc[3][0], s, w0); fma2(acc[3][1], s, w1);
        }
        __syncthreads();
    }
#pragma unroll
    for (int i = 0; i < 4; i++) {
        float4 o; unp(acc[i][0], o.x, o.y); unp(acc[i][1], o.z, o.w);
        size_t ob = ((size_t)b * NN + n0 + ty * 4 + i) * (3 * CD) + o0 + tx * 4;
        st4(&g_qkv[ob], o);
    }
}

// ---------------- K1b: 1/||Q_row|| ------------------------------------------
__global__ void __launch_bounds__(256) k_invq() {
    int row  = blockIdx.x * 8 + (threadIdx.x >> 5);
    int lane = threadIdx.x & 31;
    float4 q = ld4(&g_qkv[(size_t)row * (3 * CD) + lane * 4]);
    float s = q.x * q.x + q.y * q.y + q.z * q.z + q.w * q.w;
#pragma unroll
    for (int o = 16; o; o >>= 1) s += __shfl_xor_sync(0xffffffffu, s, o);
    if (lane == 0) g_invq[row] = 1.0f / fmaxf(sqrtf(s), 1e-12f);
}

// ---------------- K2: pos-MLP -> g_pe [GROWS][CD] ---------------------------
// 128 rows/block, 8x8 micro-tile f32x2 GEMM; occupancy-forced 2 blocks/SM
__global__ void __launch_bounds__(256, 2) k_pe(
    const float* __restrict__ pos, const void* __restrict__ idx,
    const float* __restrict__ dist,
    const float* __restrict__ W1, const float* __restrict__ b1,
    const float* __restrict__ W2, const float* __restrict__ b2) {
    __shared__ float W2s[32][CD];       // 16 KB, chunk of W2, [jj][c]
    __shared__ float hsT[32][132];      // 16.5 KB, [jj][row], stride 132 (16B-aligned)
    __shared__ float W1s[HID * 10];
    __shared__ float b1s[HID];
    __shared__ float b2s[CD];
    __shared__ float feats[128][12];
    const int tid = threadIdx.x;
    const size_t g0 = (size_t)blockIdx.x * 128;
    const int tx = tid & 15, ty = tid >> 4;
    const int c0 = tx * 8, r0 = ty * 8;

    for (int v = tid; v < HID * 10; v += 256) W1s[v] = W1[v];
    if (tid < HID) b1s[tid] = b1[tid];
    if (tid < CD)  b2s[tid] = b2[tid];
    if (tid < 128) {
        size_t g = g0 + tid;
        int b = (int)(g >> 16);
        int n = (int)((g >> 4) & (NN - 1));
        int j = ld_idx(idx, g);
        const float* pc = &pos[((size_t)b * NN + n) * 3];
        const float* pn = &pos[((size_t)b * NN + j) * 3];
        float a0 = pc[0], a1 = pc[1], a2 = pc[2];
        float q0 = pn[0], q1 = pn[1], q2 = pn[2];
        feats[tid][0] = a0;  feats[tid][1] = a1;  feats[tid][2] = a2;
        feats[tid][3] = q0;  feats[tid][4] = q1;  feats[tid][5] = q2;
        feats[tid][6] = a0 - q0; feats[tid][7] = a1 - q1; feats[tid][8] = a2 - q2;
        feats[tid][9] = dist[g];
    }
    __syncthreads();

    u64 acc[8][4];
    {
        u64 bi[4];
#pragma unroll
        for (int q = 0; q < 4; q++) bi[q] = pack2(b2s[c0 + 2*q], b2s[c0 + 2*q + 1]);
#pragma unroll
        for (int i = 0; i < 8; i++)
#pragma unroll
            for (int q = 0; q < 4; q++) acc[i][q] = bi[q];
    }

    for (int jc = 0; jc < 2; jc++) {
        const int j0 = jc * 32;
        if (jc) __syncthreads();   // protect previous chunk's W2s/hsT reads
        // load W2 chunk: W2 is [CD][HID] row-major; W2s[jj][c] = W2[c*HID + j0+jj]
#pragma unroll
        for (int p = 0; p < 16; p++) {
            int v = tid + p * 256;          // v in [0, 4096)
            int c = v >> 5, jj = v & 31;
            W2s[jj][c] = W2[(size_t)c * HID + j0 + jj];
        }
        // MLP1 chunk: hsT[jj][r] for jj in [0,32), r in [0,128)
#pragma unroll
        for (int p = 0; p < 16; p++) {
            int v = tid + p * 256;
            int jj = v & 31, r = v >> 5;
            int j = j0 + jj;
            float s = b1s[j];
#pragma unroll
            for (int i = 0; i < 10; i++) s += feats[r][i] * W1s[j * 10 + i];
            hsT[jj][r] = fmaxf(s, 0.0f);
        }
        __syncthreads();
        // GEMM chunk: 32 kk steps, 8x8 per thread
#pragma unroll 4
        for (int kk = 0; kk < 32; kk++) {
            float4 a0 = ld4(&hsT[kk][r0]);
            float4 a1 = ld4(&hsT[kk][r0 + 4]);
            const u64* bp = (const u64*)&W2s[kk][c0];
            u64 b0 = bp[0], b1v = bp[1], b2v = bp[2], b3 = bp[3];
            float av[8] = {a0.x,a0.y,a0.z,a0.w,a1.x,a1.y,a1.z,a1.w};
#pragma unroll
            for (int i = 0; i < 8; i++) {
                u64 s = splat2(av[i]);
                fma2(acc[i][0], s, b0); fma2(acc[i][1], s, b1v);
                fma2(acc[i][2], s, b2v); fma2(acc[i][3], s, b3);
            }
        }
    }
#pragma unroll
    for (int i = 0; i < 8; i++) {
        float o[8];
        unp(acc[i][0], o[0], o[1]); unp(acc[i][1], o[2], o[3]);
        unp(acc[i][2], o[4], o[5]); unp(acc[i][3], o[6], o[7]);
        size_t ob = (g0 + r0 + i) * CD + c0;
        st4(&g_pe[ob],     make_float4(o[0], o[1], o[2], o[3]));
        st4(&g_pe[ob + 4], make_float4(o[4], o[5], o[6], o[7]));
    }
}

// ---------------- K3: kv outer product (gather + norm fused) ----------------
__global__ void __launch_bounds__(256, 2) k_kv(const void* __restrict__ idx) {
    __shared__ float As[16][CD];
    __shared__ float Bs[16][CD];
    const int p = blockIdx.y;
    const int s = blockIdx.x;
    const int b = p >> 4, kslot = p & 15;
    const int tid = threadIdx.x;
    const int tx = tid & 15, ty = tid >> 4;
    const int cb = ty * 8, db = tx * 8;
    const int lane = tid & 31, warp = tid >> 5;
    const int c4 = lane * 4;

    u64 acc[8][4] = {};
    const int n0 = s * (NN / NSPLIT);
    const int NSTEP = (NN / NSPLIT) / 16;
    for (int step = 0; step < NSTEP; step++) {
        const int nbase = n0 + step * 16;
        __syncthreads();
#pragma unroll
        for (int rr = 0; rr < 2; rr++) {
            int row = warp * 2 + rr;
            int n = nbase + row;
            size_t g = ((size_t)(b * NN + n)) * NBK + kslot;
            int j = ld_idx(idx, g);
            float4 pe = ld4(&g_pe[g * CD + c4]);
            const float* qrow = &g_qkv[((size_t)b * NN + j) * (3 * CD)];
            float4 kg = ld4(&qrow[CD + c4]);
            float4 vg = ld4(&qrow[2 * CD + c4]);
            float k0 = kg.x + pe.x, k1 = kg.y + pe.y, k2 = kg.z + pe.z, k3 = kg.w + pe.w;
            float v0 = fmaxf(vg.x + pe.x, 0.f), v1 = fmaxf(vg.y + pe.y, 0.f);
            float v2 = fmaxf(vg.z + pe.z, 0.f), v3 = fmaxf(vg.w + pe.w, 0.f);
            float ss = k0 * k0 + k1 * k1 + k2 * k2 + k3 * k3;
#pragma unroll
            for (int o = 16; o; o >>= 1) ss += __shfl_xor_sync(0xffffffffu, ss, o);
            float sc = 1.0f / fmaxf(sqrtf(ss), 1e-12f);
            st4(&As[row][c4], make_float4(k0 * sc, k1 * sc, k2 * sc, k3 * sc));
            st4(&Bs[row][c4], make_float4(v0, v1, v2, v3));
        }
        __syncthreads();
#pragma unroll
        for (int kk = 0; kk < 16; kk++) {
            float4 a0 = ld4(&As[kk][cb]);
            float4 a1 = ld4(&As[kk][cb + 4]);
            const u64* bp = (const u64*)&Bs[kk][db];
            u64 b0 = bp[0], b1 = bp[1], b2 = bp[2], b3 = bp[3];
            float av[8] = {a0.x,a0.y,a0.z,a0.w,a1.x,a1.y,a1.z,a1.w};
#pragma unroll
            for (int i = 0; i < 8; i++) {
                u64 sa = splat2(av[i]);
                fma2(acc[i][0], sa, b0); fma2(acc[i][1], sa, b1);
                fma2(acc[i][2], sa, b2); fma2(acc[i][3], sa, b3);
            }
        }
    }
    float* op = &g_kvp[s][(size_t)p * CD * CD];
#pragma unroll
    for (int i = 0; i < 8; i++) {
        float o[8];
        unp(acc[i][0], o[0], o[1]); unp(acc[i][1], o[2], o[3]);
        unp(acc[i][2], o[4], o[5]); unp(acc[i][3], o[6], o[7]);
        st4(&op[(cb + i) * CD + db],     make_float4(o[0], o[1], o[2], o[3]));
        st4(&op[(cb + i) * CD + db + 4], make_float4(o[4], o[5], o[6], o[7]));
    }
}

// ---------------- K3b: reduce split partials into g_kvp[0] ------------------
__global__ void __launch_bounds__(256) k_red() {
    size_t i = ((size_t)blockIdx.x * 256 + threadIdx.x) * 4;
    float4 s = ld4(&g_kvp[0][i]);
#pragma unroll
    for (int t = 1; t < NSPLIT; t++) {
        float4 v = ld4(&g_kvp[t][i]);
        s.x += v.x; s.y += v.y; s.z += v.z; s.w += v.w;
    }
    st4(&g_kvp[0][i], s);
}

// ---------------- K4: agg partials; 128x128 tile, 8x8/thread, k-split 2 -----
// c processed in chunks of 16 (halved barrier count vs chunks of 8)
__global__ void __launch_bounds__(256, 2) k_agg(const void* __restrict__ idx) {
    __shared__ float As[16][132];
    __shared__ float Bs[16][CD];
    __shared__ int   jr[128];
    __shared__ float sc[128];
    const int kh = blockIdx.x;
    const int rt = blockIdx.y;
    const int row0 = rt * 128;
    const int b = row0 >> 12;
    const int tid = threadIdx.x;
    const int tx = tid & 15, ty = tid >> 4;
    const int d0 = tx * 8, r0 = ty * 8;
    u64 acc[8][4] = {};
    for (int ks = 0; ks < 8; ks++) {
        const int k = kh * 8 + ks;
        __syncthreads();
        if (tid < 128) {
            int j = ld_idx(idx, ((size_t)(row0 + tid)) * NBK + k);
            jr[tid] = j;
            sc[tid] = g_invq[b * NN + j];
        }
        __syncthreads();
        const float* kvb = &g_kvp[0][((size_t)(b * NBK + k)) * CD * CD];
        for (int cbk = 0; cbk < 8; cbk++) {
            const int c0 = cbk * 16;
            __syncthreads();
            {
                // As[cc][r]: 16 c x 128 rows; each thread fills 8 values (2 gathers)
                int r = tid >> 1, half = tid & 1;
                float s = sc[r]; int j = jr[r];
                const float* qrow = &g_qkv[((size_t)b * NN + j) * (3 * CD) + c0];
                float4 q0 = ld4(&qrow[half * 4]);
                float4 q1 = ld4(&qrow[8 + half * 4]);
                As[half * 4 + 0][r] = q0.x * s;
                As[half * 4 + 1][r] = q0.y * s;
                As[half * 4 + 2][r] = q0.z * s;
                As[half * 4 + 3][r] = q0.w * s;
                As[8 + half * 4 + 0][r] = q1.x * s;
                As[8 + half * 4 + 1][r] = q1.y * s;
                As[8 + half * 4 + 2][r] = q1.z * s;
                As[8 + half * 4 + 3][r] = q1.w * s;
            }
            {
                int cc = tid >> 5, d4 = (tid & 31) * 4;
                st4(&Bs[cc][d4],     ld4(&kvb[(size_t)(c0 + cc) * CD + d4]));
                st4(&Bs[cc + 8][d4], ld4(&kvb[(size_t)(c0 + cc + 8) * CD + d4]));
            }
            __syncthreads();
#pragma unroll
            for (int kk = 0; kk < 16; kk++) {
                float4 a0 = ld4(&As[kk][r0]);
                float4 a1 = ld4(&As[kk][r0 + 4]);
                const u64* bp = (const u64*)&Bs[kk][d0];
                u64 b0 = bp[0], b1 = bp[1], b2 = bp[2], b3 = bp[3];
                float av[8] = {a0.x,a0.y,a0.z,a0.w,a1.x,a1.y,a1.z,a1.w};
#pragma unroll
                for (int i = 0; i < 8; i++) {
                    u64 sa = splat2(av[i]);
                    fma2(acc[i][0], sa, b0); fma2(acc[i][1], sa, b1);
                    fma2(acc[i][2], sa, b2); fma2(acc[i][3], sa, b3);
                }
            }
        }
    }
    const float inv = 1.0f / (float)NN;
#pragma unroll
    for (int i = 0; i < 8; i++) {
        float o[8];
        unp(acc[i][0], o[0], o[1]); unp(acc[i][1], o[2], o[3]);
        unp(acc[i][2], o[4], o[5]); unp(acc[i][3], o[6], o[7]);
        size_t ob = (size_t)(row0 + r0 + i) * CD + d0;
        st4(&g_aggp[kh][ob],     make_float4(o[0]*inv, o[1]*inv, o[2]*inv, o[3]*inv));
        st4(&g_aggp[kh][ob + 4], make_float4(o[4]*inv, o[5]*inv, o[6]*inv, o[7]*inv));
    }
}

// ---------------- K5a: h = relu((agg0+agg1) @ Wm1^T + bm1) ------------------
__global__ void __launch_bounds__(256) k_mlp1(const float* __restrict__ Wm1,
                                              const float* __restrict__ bm1) {
    __shared__ float As[32][68];
    __shared__ float Bs[32][68];
    const int row0 = blockIdx.y * 64;
    const int o0   = blockIdx.x * 64;
    const int tid = threadIdx.x;
    const int tx = tid & 15, ty = tid >> 4;
    u64 acc[4][2] = {};
    for (int c0 = 0; c0 < CD; c0 += 32) {
#pragma unroll
        for (int p = 0; p < 2; p++) {
            int r = tid >> 2, cq = tid & 3;
            size_t off = (size_t)(row0 + r) * CD + c0 + p * 16 + cq * 4;
            float4 a = ld4(&g_aggp[0][off]);
            float4 a2 = ld4(&g_aggp[1][off]);
            a.x += a2.x; a.y += a2.y; a.z += a2.z; a.w += a2.w;
            As[p*16 + cq*4 + 0][r] = a.x; As[p*16 + cq*4 + 1][r] = a.y;
            As[p*16 + cq*4 + 2][r] = a.z; As[p*16 + cq*4 + 3][r] = a.w;
        }
#pragma unroll
        for (int p = 0; p < 2; p++) {
            int j = (tid >> 3) + p * 32, cq = tid & 7;
            float4 w = ld4(&Wm1[(size_t)(o0 + j) * CD + c0 + cq * 4]);
            Bs[cq*4 + 0][j] = w.x; Bs[cq*4 + 1][j] = w.y;
            Bs[cq*4 + 2][j] = w.z; Bs[cq*4 + 3][j] = w.w;
        }
        __syncthreads();
#pragma unroll
        for (int kk = 0; kk < 32; kk++) {
            float4 a = ld4(&As[kk][ty * 4]);
            const u64* wp = (const u64*)&Bs[kk][tx * 4];
            u64 w0 = wp[0], w1 = wp[1];
            u64 s;
            s = splat2(a.x); fma2(acc[0][0], s, w0); fma2(acc[0][1], s, w1);
            s = splat2(a.y); fma2(acc[1][0], s, w0); fma2(acc[1][1], s, w1);
            s = splat2(a.z); fma2(acc[2][0], s, w0); fma2(acc[2][1], s, w1);
            s = splat2(a.w); fma2(acc[3][0], s, w0); fma2(acc[3][1], s, w1);
        }
        __syncthreads();
    }
    float4 bb = ld4(&bm1[o0 + tx * 4]);
#pragma unroll
    for (int i = 0; i < 4; i++) {
        float4 o; unp(acc[i][0], o.x, o.y); unp(acc[i][1], o.z, o.w);
        size_t ob = (size_t)(row0 + ty * 4 + i) * (4 * CD) + o0 + tx * 4;
        st4(&g_hid[ob], make_float4(fmaxf(o.x + bb.x, 0.f), fmaxf(o.y + bb.y, 0.f),
                                    fmaxf(o.z + bb.z, 0.f), fmaxf(o.w + bb.w, 0.f)));
    }
}

// ---------------- K5b: out = h @ Wm2^T + bm2 + x^T, transposed store --------
__global__ void __launch_bounds__(256) k_mlp2(const float* __restrict__ Wm2,
                                              const float* __restrict__ bm2,
                                              const float* __restrict__ x,
                                              float* __restrict__ out) {
    __shared__ float As[16][68];
    __shared__ float Bs[16][132];
    __shared__ float Csm[64][129];
    const int b  = blockIdx.y;
    const int n0 = blockIdx.x * 64;
    const int row0 = b * NN + n0;
    const int tid = threadIdx.x;
    const int tx = tid & 15, ty = tid >> 4;
    const int d0 = tx * 8, r0 = ty * 4;
    u64 acc[4][4] = {};
    for (int step = 0; step < 32; step++) {
        int o0 = step * 16;
        __syncthreads();
        {
            int r = tid >> 2, oq = tid & 3;
            float4 h = ld4(&g_hid[(size_t)(row0 + r) * (4 * CD) + o0 + oq * 4]);
            As[oq*4 + 0][r] = h.x; As[oq*4 + 1][r] = h.y;
            As[oq*4 + 2][r] = h.z; As[oq*4 + 3][r] = h.w;
        }
#pragma unroll
        for (int p = 0; p < 2; p++) {
            int d = (tid >> 2) + p * 64, oq = tid & 3;
            float4 w = ld4(&Wm2[(size_t)d * (4 * CD) + o0 + oq * 4]);
            Bs[oq*4 + 0][d] = w.x; Bs[oq*4 + 1][d] = w.y;
            Bs[oq*4 + 2][d] = w.z; Bs[oq*4 + 3][d] = w.w;
        }
        __syncthreads();
#pragma unroll
        for (int kk = 0; kk < 16; kk++) {
            float4 a = ld4(&As[kk][r0]);
            const u64* bp = (const u64*)&Bs[kk][d0];
            u64 b0 = bp[0], b1 = bp[1], b2 = bp[2], b3 = bp[3];
            u64 s;
            s = splat2(a.x); fma2(acc[0][0],s,b0); fma2(acc[0][1],s,b1); fma2(acc[0][2],s,b2); fma2(acc[0][3],s,b3);
            s = splat2(a.y); fma2(acc[1][0],s,b0); fma2(acc[1][1],s,b1); fma2(acc[1][2],s,b2); fma2(acc[1][3],s,b3);
            s = splat2(a.z); fma2(acc[2][0],s,b0); fma2(acc[2][1],s,b1); fma2(acc[2][2],s,b2); fma2(acc[2][3],s,b3);
            s = splat2(a.w); fma2(acc[3][0],s,b0); fma2(acc[3][1],s,b1); fma2(acc[3][2],s,b2); fma2(acc[3][3],s,b3);
        }
    }
    float4 b2a = ld4(&bm2[d0]);
    float4 b2b = ld4(&bm2[d0 + 4]);
    float bvv[8] = {b2a.x,b2a.y,b2a.z,b2a.w,b2b.x,b2b.y,b2b.z,b2b.w};
    __syncthreads();
#pragma unroll
    for (int i = 0; i < 4; i++) {
        float o[8];
        unp(acc[i][0], o[0], o[1]); unp(acc[i][1], o[2], o[3]);
        unp(acc[i][2], o[4], o[5]); unp(acc[i][3], o[6], o[7]);
#pragma unroll
        for (int j = 0; j < 8; j++) Csm[r0 + i][d0 + j] = o[j] + bvv[j];
    }
    __syncthreads();
    for (int v = tid; v < 64 * CD; v += 256) {
        int dd = v >> 6, nn = v & 63;
        size_t oa = ((size_t)b * CD + dd) * NN + n0 + nn;
        out[oa] = Csm[nn][dd] + x[oa];
    }
}

// ---------------- launcher ---------------------------------------------------
extern "C" void kernel_launch(void* const* d_in, const int* in_sizes, int n_in,
                              void* d_out, int out_size) {
    (void)in_sizes; (void)n_in; (void)out_size;
    const float* pos  = (const float*)d_in[0];
    const float* x    = (const float*)d_in[1];
    const void*  idx  = d_in[2];
    const float* dist = (const float*)d_in[3];
    const float* Wqkv = (const float*)d_in[4];
    const float* W1   = (const float*)d_in[5];
    const float* b1   = (const float*)d_in[6];
    const float* W2   = (const float*)d_in[7];
    const float* b2   = (const float*)d_in[8];
    const float* Wm1  = (const float*)d_in[9];
    const float* bm1  = (const float*)d_in[10];
    const float* Wm2  = (const float*)d_in[11];
    const float* bm2  = (const float*)d_in[12];
    float* out = (float*)d_out;

    k_detect<<<1, 256>>>((const unsigned int*)idx);
    k_qkv   <<<dim3(6, NN / 64, BB), 256>>>(x, Wqkv);
    k_invq  <<<ROWS / 8, 256>>>();
    k_pe    <<<GROWS / 128, 256>>>(pos, idx, dist, W1, b1, W2, b2);
    k_kv    <<<dim3(NSPLIT, PAIRS), 256>>>(idx);
    k_red   <<<(PAIRS * CD * CD) / (256 * 4), 256>>>();
    k_agg   <<<dim3(2, ROWS / 128), 256>>>(idx);
    k_mlp1  <<<dim3(8, ROWS / 64), 256>>>(Wm1, bm1);
    k_mlp2  <<<dim3(NN / 64, BB), 256>>>(Wm2, bm2, x, out);
}

// round 9
// speedup vs baseline: 1.3808x; 1.0686x over previous
#include <cuda_runtime.h>
#include <cuda_bf16.h>
#include <cstdint>

#define BB  4
#define NN  4096
#define NBK 16
#define CD  128
#define HID 64
#define ROWS (BB*NN)            // 16384
#define GROWS (BB*NN*NBK)       // 262144
#define PAIRS (BB*NBK)          // 64
#define NSPLIT 8
#define BPITCH 136              // bf16 tile pitch (272 B rows: 16B-aligned, ldmatrix conflict-free)

// ---------------- scratch (device globals; no allocation allowed) ----------
__device__ float g_qkv [ROWS*3*CD];                 // 25 MB
__device__ float g_invq[ROWS];
__device__ float g_pe  [(size_t)GROWS*CD];          // pos_emb, 134 MB
__device__ float g_kvp [NSPLIT][PAIRS*CD*CD];       // split partials 32 MB; [0]=reduced
__device__ unsigned short g_kvb[PAIRS][2][128*BPITCH]; // bf16 hi/lo kv images, 4.5 MB
__device__ float g_agg [ROWS*CD];                   // 8 MB
__device__ float g_hid [ROWS*4*CD];                 // 33 MB
__device__ int   g_idx64;

typedef unsigned long long u64;
__device__ __forceinline__ float4 ld4(const float* p) { return *(const float4*)p; }
__device__ __forceinline__ void   st4(float* p, float4 v) { *(float4*)p = v; }
__device__ __forceinline__ u64 splat2(float a) {
    u64 r; asm("mov.b64 %0, {%1, %1};" : "=l"(r) : "f"(a)); return r;
}
__device__ __forceinline__ u64 pack2(float lo, float hi) {
    u64 r; asm("mov.b64 %0, {%1, %2};" : "=l"(r) : "f"(lo), "f"(hi)); return r;
}
__device__ __forceinline__ void fma2(u64& d, u64 a, u64 b) {
    asm("fma.rn.f32x2 %0, %1, %2, %0;" : "+l"(d) : "l"(a), "l"(b));
}
__device__ __forceinline__ void unp(u64 v, float& lo, float& hi) {
    asm("mov.b64 {%0, %1}, %2;" : "=f"(lo), "=f"(hi) : "l"(v));
}
__device__ __forceinline__ int ld_idx(const void* p, size_t pos) {
    if (g_idx64) return (int)((const long long*)p)[pos];
    return ((const int*)p)[pos];
}
__device__ __forceinline__ uint32_t smem_u32(const void* p) {
    uint32_t a;
    asm("{ .reg .u64 t; cvta.to.shared.u64 t, %1; cvt.u32.u64 %0, t; }" : "=r"(a) : "l"(p));
    return a;
}
__device__ __forceinline__ void bf_split(float x, unsigned short& h, unsigned short& l) {
    __nv_bfloat16 bh = __float2bfloat16(x);
    h = __bfloat16_as_ushort(bh);
    l = __bfloat16_as_ushort(__float2bfloat16(x - __bfloat162float(bh)));
}

#define LDSM_X4(r0,r1,r2,r3, a) \
    asm volatile("ldmatrix.sync.aligned.m8n8.x4.shared.b16 {%0,%1,%2,%3}, [%4];" \
        : "=r"(r0),"=r"(r1),"=r"(r2),"=r"(r3) : "r"(a))
#define LDSM_X4T(r0,r1,r2,r3, a) \
    asm volatile("ldmatrix.sync.aligned.m8n8.x4.trans.shared.b16 {%0,%1,%2,%3}, [%4];" \
        : "=r"(r0),"=r"(r1),"=r"(r2),"=r"(r3) : "r"(a))
#define MMA_BF16(d, a0,a1,a2,a3, b0,b1) \
    asm volatile("mma.sync.aligned.m16n8k16.row.col.f32.bf16.bf16.f32 " \
        "{%0,%1,%2,%3}, {%4,%5,%6,%7}, {%8,%9}, {%0,%1,%2,%3};" \
        : "+f"((d)[0]),"+f"((d)[1]),"+f"((d)[2]),"+f"((d)[3]) \
        : "r"(a0),"r"(a1),"r"(a2),"r"(a3), "r"(b0),"r"(b1))

// ---------------- idx dtype autodetect -------------------------------------
__global__ void k_detect(const unsigned int* __restrict__ w) {
    __shared__ int any;
    if (threadIdx.x == 0) any = 0;
    __syncthreads();
    unsigned int v = w[1 + 2 * threadIdx.x];
    if (v != 0u) any = 1;
    __syncthreads();
    if (threadIdx.x == 0) g_idx64 = (any ? 0 : 1);
}

// ---------------- K1: qkv = x^T @ Wqkv^T ------------------------------------
__global__ void __launch_bounds__(256) k_qkv(const float* __restrict__ x,
                                             const float* __restrict__ Wqkv) {
    __shared__ float As[32][64];
    __shared__ float Bs[32][68];
    const int b  = blockIdx.z;
    const int n0 = blockIdx.y * 64;
    const int o0 = blockIdx.x * 64;
    const int tid = threadIdx.x;
    const int tx = tid & 15, ty = tid >> 4;
    u64 acc[4][2] = {};
    for (int c0 = 0; c0 < CD; c0 += 32) {
#pragma unroll
        for (int p = 0; p < 8; p++) {
            int v = tid + p * 256;
            int cc = v >> 6, i = v & 63;
            As[cc][i] = x[((size_t)b * CD + c0 + cc) * NN + n0 + i];
        }
#pragma unroll
        for (int p = 0; p < 8; p++) {
            int v = tid + p * 256;
            int cc = v & 31, j = v >> 5;
            Bs[cc][j] = Wqkv[(size_t)(o0 + j) * CD + c0 + cc];
        }
        __syncthreads();
#pragma unroll
        for (int kk = 0; kk < 32; kk++) {
            float4 a = ld4(&As[kk][ty * 4]);
            const u64* wp = (const u64*)&Bs[kk][tx * 4];
            u64 w0 = wp[0], w1 = wp[1];
            u64 s;
            s = splat2(a.x); fma2(acc[0][0], s, w0); fma2(acc[0][1], s, w1);
            s = splat2(a.y); fma2(acc[1][0], s, w0); fma2(acc[1][1], s, w1);
            s = splat2(a.z); fma2(acc[2][0], s, w0); fma2(acc[2][1], s, w1);
            s = splat2(a.w); fma2(acc[3][0], s, w0); fma2(acc[3][1], s, w1);
        }
        __syncthreads();
    }
#pragma unroll
    for (int i = 0; i < 4; i++) {
        float4 o; unp(acc[i][0], o.x, o.y); unp(acc[i][1], o.z, o.w);
        size_t ob = ((size_t)b * NN + n0 + ty * 4 + i) * (3 * CD) + o0 + tx * 4;
        st4(&g_qkv[ob], o);
    }
}

// ---------------- K1b: 1/||Q_row|| ------------------------------------------
__global__ void __launch_bounds__(256) k_invq() {
    int row  = blockIdx.x * 8 + (threadIdx.x >> 5);
    int lane = threadIdx.x & 31;
    float4 q = ld4(&g_qkv[(size_t)row * (3 * CD) + lane * 4]);
    float s = q.x * q.x + q.y * q.y + q.z * q.z + q.w * q.w;
#pragma unroll
    for (int o = 16; o; o >>= 1) s += __shfl_xor_sync(0xffffffffu, s, o);
    if (lane == 0) g_invq[row] = 1.0f / fmaxf(sqrtf(s), 1e-12f);
}

// ---------------- K2: pos-MLP -> g_pe [GROWS][CD] ---------------------------
__global__ void __launch_bounds__(256, 2) k_pe(
    const float* __restrict__ pos, const void* __restrict__ idx,
    const float* __restrict__ dist,
    const float* __restrict__ W1, const float* __restrict__ b1,
    const float* __restrict__ W2, const float* __restrict__ b2) {
    __shared__ float W2s[32][CD];
    __shared__ float hsT[32][132];
    __shared__ float W1s[HID * 10];
    __shared__ float b1s[HID];
    __shared__ float b2s[CD];
    __shared__ float feats[128][12];
    const int tid = threadIdx.x;
    const size_t g0 = (size_t)blockIdx.x * 128;
    const int tx = tid & 15, ty = tid >> 4;
    const int c0 = tx * 8, r0 = ty * 8;

    for (int v = tid; v < HID * 10; v += 256) W1s[v] = W1[v];
    if (tid < HID) b1s[tid] = b1[tid];
    if (tid < CD)  b2s[tid] = b2[tid];
    if (tid < 128) {
        size_t g = g0 + tid;
        int b = (int)(g >> 16);
        int n = (int)((g >> 4) & (NN - 1));
        int j = ld_idx(idx, g);
        const float* pc = &pos[((size_t)b * NN + n) * 3];
        const float* pn = &pos[((size_t)b * NN + j) * 3];
        float a0 = pc[0], a1 = pc[1], a2 = pc[2];
        float q0 = pn[0], q1 = pn[1], q2 = pn[2];
        feats[tid][0] = a0;  feats[tid][1] = a1;  feats[tid][2] = a2;
        feats[tid][3] = q0;  feats[tid][4] = q1;  feats[tid][5] = q2;
        feats[tid][6] = a0 - q0; feats[tid][7] = a1 - q1; feats[tid][8] = a2 - q2;
        feats[tid][9] = dist[g];
    }
    __syncthreads();

    u64 acc[8][4];
    {
        u64 bi[4];
#pragma unroll
        for (int q = 0; q < 4; q++) bi[q] = pack2(b2s[c0 + 2*q], b2s[c0 + 2*q + 1]);
#pragma unroll
        for (int i = 0; i < 8; i++)
#pragma unroll
            for (int q = 0; q < 4; q++) acc[i][q] = bi[q];
    }

    for (int jc = 0; jc < 2; jc++) {
        const int j0 = jc * 32;
        if (jc) __syncthreads();
#pragma unroll
        for (int p = 0; p < 16; p++) {
            int v = tid + p * 256;
            int c = v >> 5, jj = v & 31;
            W2s[jj][c] = W2[(size_t)c * HID + j0 + jj];
        }
#pragma unroll
        for (int p = 0; p < 16; p++) {
            int v = tid + p * 256;
            int jj = v & 31, r = v >> 5;
            int j = j0 + jj;
            float s = b1s[j];
#pragma unroll
            for (int i = 0; i < 10; i++) s += feats[r][i] * W1s[j * 10 + i];
            hsT[jj][r] = fmaxf(s, 0.0f);
        }
        __syncthreads();
#pragma unroll 4
        for (int kk = 0; kk < 32; kk++) {
            float4 a0 = ld4(&hsT[kk][r0]);
            float4 a1 = ld4(&hsT[kk][r0 + 4]);
            const u64* bp = (const u64*)&W2s[kk][c0];
            u64 b0 = bp[0], b1v = bp[1], b2v = bp[2], b3 = bp[3];
            float av[8] = {a0.x,a0.y,a0.z,a0.w,a1.x,a1.y,a1.z,a1.w};
#pragma unroll
            for (int i = 0; i < 8; i++) {
                u64 s = splat2(av[i]);
                fma2(acc[i][0], s, b0); fma2(acc[i][1], s, b1v);
                fma2(acc[i][2], s, b2v); fma2(acc[i][3], s, b3);
            }
        }
    }
#pragma unroll
    for (int i = 0; i < 8; i++) {
        float o[8];
        unp(acc[i][0], o[0], o[1]); unp(acc[i][1], o[2], o[3]);
        unp(acc[i][2], o[4], o[5]); unp(acc[i][3], o[6], o[7]);
        size_t ob = (g0 + r0 + i) * CD + c0;
        st4(&g_pe[ob],     make_float4(o[0], o[1], o[2], o[3]));
        st4(&g_pe[ob + 4], make_float4(o[4], o[5], o[6], o[7]));
    }
}

// ---------------- K3: kv outer product (gather + norm fused) ----------------
__global__ void __launch_bounds__(256, 2) k_kv(const void* __restrict__ idx) {
    __shared__ float As[16][CD];
    __shared__ float Bs[16][CD];
    const int p = blockIdx.y;
    const int s = blockIdx.x;
    const int b = p >> 4, kslot = p & 15;
    const int tid = threadIdx.x;
    const int tx = tid & 15, ty = tid >> 4;
    const int cb = ty * 8, db = tx * 8;
    const int lane = tid & 31, warp = tid >> 5;
    const int c4 = lane * 4;

    u64 acc[8][4] = {};
    const int n0 = s * (NN / NSPLIT);
    const int NSTEP = (NN / NSPLIT) / 16;
    for (int step = 0; step < NSTEP; step++) {
        const int nbase = n0 + step * 16;
        __syncthreads();
#pragma unroll
        for (int rr = 0; rr < 2; rr++) {
            int row = warp * 2 + rr;
            int n = nbase + row;
            size_t g = ((size_t)(b * NN + n)) * NBK + kslot;
            int j = ld_idx(idx, g);
            float4 pe = ld4(&g_pe[g * CD + c4]);
            const float* qrow = &g_qkv[((size_t)b * NN + j) * (3 * CD)];
            float4 kg = ld4(&qrow[CD + c4]);
            float4 vg = ld4(&qrow[2 * CD + c4]);
            float k0 = kg.x + pe.x, k1 = kg.y + pe.y, k2 = kg.z + pe.z, k3 = kg.w + pe.w;
            float v0 = fmaxf(vg.x + pe.x, 0.f), v1 = fmaxf(vg.y + pe.y, 0.f);
            float v2 = fmaxf(vg.z + pe.z, 0.f), v3 = fmaxf(vg.w + pe.w, 0.f);
            float ss = k0 * k0 + k1 * k1 + k2 * k2 + k3 * k3;
#pragma unroll
            for (int o = 16; o; o >>= 1) ss += __shfl_xor_sync(0xffffffffu, ss, o);
            float sc = 1.0f / fmaxf(sqrtf(ss), 1e-12f);
            st4(&As[row][c4], make_float4(k0 * sc, k1 * sc, k2 * sc, k3 * sc));
            st4(&Bs[row][c4], make_float4(v0, v1, v2, v3));
        }
        __syncthreads();
#pragma unroll
        for (int kk = 0; kk < 16; kk++) {
            float4 a0 = ld4(&As[kk][cb]);
            float4 a1 = ld4(&As[kk][cb + 4]);
            const u64* bp = (const u64*)&Bs[kk][db];
            u64 b0 = bp[0], b1 = bp[1], b2 = bp[2], b3 = bp[3];
            float av[8] = {a0.x,a0.y,a0.z,a0.w,a1.x,a1.y,a1.z,a1.w};
#pragma unroll
            for (int i = 0; i < 8; i++) {
                u64 sa = splat2(av[i]);
                fma2(acc[i][0], sa, b0); fma2(acc[i][1], sa, b1);
                fma2(acc[i][2], sa, b2); fma2(acc[i][3], sa, b3);
            }
        }
    }
    float* op = &g_kvp[s][(size_t)p * CD * CD];
#pragma unroll
    for (int i = 0; i < 8; i++) {
        float o[8];
        unp(acc[i][0], o[0], o[1]); unp(acc[i][1], o[2], o[3]);
        unp(acc[i][2], o[4], o[5]); unp(acc[i][3], o[6], o[7]);
        st4(&op[(cb + i) * CD + db],     make_float4(o[0], o[1], o[2], o[3]));
        st4(&op[(cb + i) * CD + db + 4], make_float4(o[4], o[5], o[6], o[7]));
    }
}

// ---------------- K3b: reduce split partials into g_kvp[0] ------------------
__global__ void __launch_bounds__(256) k_red() {
    size_t i = ((size_t)blockIdx.x * 256 + threadIdx.x) * 4;
    float4 s = ld4(&g_kvp[0][i]);
#pragma unroll
    for (int t = 1; t < NSPLIT; t++) {
        float4 v = ld4(&g_kvp[t][i]);
        s.x += v.x; s.y += v.y; s.z += v.z; s.w += v.w;
    }
    st4(&g_kvp[0][i], s);
}

// ---------------- K3c: kv -> bf16 hi/lo images [c][d], pitch BPITCH ---------
__global__ void __launch_bounds__(256) k_kvsplit() {
    const int v = blockIdx.x;          // 0=hi, 1=lo
    const int p = blockIdx.y;
    const int tid = threadIdx.x;
    const float* src = &g_kvp[0][(size_t)p * CD * CD];
    unsigned short* dst = &g_kvb[p][v][0];
    for (int e = tid; e < CD * CD; e += 256) {
        int c = e >> 7, d = e & 127;
        float x = src[e];
        __nv_bfloat16 bh = __float2bfloat16(x);
        unsigned short bits;
        if (v == 0) bits = __bfloat16_as_ushort(bh);
        else bits = __bfloat16_as_ushort(__float2bfloat16(x - __bfloat162float(bh)));
        dst[c * BPITCH + d] = bits;
    }
}

// ---------------- K4: agg via mma.sync bf16 hi/lo ---------------------------
// grid 128 CTAs x 256 thr; warp owns 16 rows x 128 d; reg accumulators
#define AGG_A0 0
#define AGG_A1 34816
#define AGG_B0 69632
#define AGG_B1 104448
#define AGG_SMEM 139264

__global__ void __launch_bounds__(256, 1) k_agg_mma(const void* __restrict__ idx) {
    extern __shared__ __align__(16) unsigned char dsm[];
    __shared__ int   jr[128];
    __shared__ float sc[128];
    const uint32_t sb = smem_u32(dsm);
    const int tid = threadIdx.x;
    const int wid = tid >> 5, lane = tid & 31;
    const int row0 = blockIdx.x * 128;
    const int b = row0 >> 12;
    const int m0 = wid * 16;

    const int rowSel = lane & 15;
    const int colSel = (lane >> 4) << 3;
    // A ldmatrix addr term (per cc add cc*16): bytes
    const uint32_t aTerm = (uint32_t)(((m0 + rowSel) * BPITCH + colSel) * 2);
    // B ldmatrix addr term (per cc add cc*16*BPITCH, per dblk add dblk*16)
    const uint32_t bTerm = (uint32_t)((rowSel * BPITCH + colSel) * 2);

    float facc[16][4] = {};

    const int arow = tid >> 1, ahalf = tid & 1;   // A staging: 2 threads/row

    for (int k = 0; k < NBK; k++) {
        __syncthreads();   // prior compute done before restage
        if (tid < 128) {
            int j = ld_idx(idx, ((size_t)(row0 + tid)) * NBK + k);
            jr[tid] = j;
            sc[tid] = g_invq[b * NN + j];
        }
        __syncthreads();
        // ---- stage A hi/lo (gathered, scaled Q rows), pitch BPITCH ----
        {
            int j = jr[arow];
            float s = sc[arow];
            const float* qrow = &g_qkv[((size_t)b * NN + j) * (3 * CD) + ahalf * 64];
            unsigned char* Ah = dsm + AGG_A0;
            unsigned char* Al = dsm + AGG_A1;
#pragma unroll
            for (int gg = 0; gg < 8; gg++) {
                float4 qa = ld4(qrow + gg * 8);
                float4 qb = ld4(qrow + gg * 8 + 4);
                float xs[8] = {qa.x*s, qa.y*s, qa.z*s, qa.w*s, qb.x*s, qb.y*s, qb.z*s, qb.w*s};
                unsigned short h[8], l[8];
#pragma unroll
                for (int q = 0; q < 8; q++) bf_split(xs[q], h[q], l[q]);
                uint4 vh, vl;
                vh.x = (uint32_t)h[0] | ((uint32_t)h[1] << 16);
                vh.y = (uint32_t)h[2] | ((uint32_t)h[3] << 16);
                vh.z = (uint32_t)h[4] | ((uint32_t)h[5] << 16);
                vh.w = (uint32_t)h[6] | ((uint32_t)h[7] << 16);
                vl.x = (uint32_t)l[0] | ((uint32_t)l[1] << 16);
                vl.y = (uint32_t)l[2] | ((uint32_t)l[3] << 16);
                vl.z = (uint32_t)l[4] | ((uint32_t)l[5] << 16);
                vl.w = (uint32_t)l[6] | ((uint32_t)l[7] << 16);
                uint32_t off = (uint32_t)((arow * BPITCH + ahalf * 64 + gg * 8) * 2);
                *(uint4*)(Ah + off) = vh;
                *(uint4*)(Al + off) = vl;
            }
        }
        // ---- copy pre-converted B hi/lo images ----
        {
            const int p = b * NBK + k;
            uint4* Bh = (uint4*)(dsm + AGG_B0);
            uint4* Bl = (uint4*)(dsm + AGG_B1);
            const uint4* sh = (const uint4*)&g_kvb[p][0][0];
            const uint4* sl = (const uint4*)&g_kvb[p][1][0];
            for (int e = tid; e < (128 * BPITCH * 2) / 16; e += 256) {
                Bh[e] = sh[e];
                Bl[e] = sl[e];
            }
        }
        __syncthreads();
        // ---- compute: 8 c-chunks, 16 d-tiles, 3 products ----
#pragma unroll 1
        for (int cc = 0; cc < 8; cc++) {
            uint32_t ah0, ah1, ah2, ah3, al0, al1, al2, al3;
            uint32_t aAddr = sb + AGG_A0 + aTerm + (uint32_t)(cc * 16 * 2);
            LDSM_X4(ah0, ah1, ah2, ah3, aAddr);
            LDSM_X4(al0, al1, al2, al3, aAddr + (AGG_A1 - AGG_A0));
            uint32_t bBase = sb + AGG_B0 + bTerm + (uint32_t)(cc * 16 * BPITCH * 2);
#pragma unroll
            for (int dblk = 0; dblk < 8; dblk++) {
                uint32_t bh0, bh1, bh2, bh3, bl0, bl1, bl2, bl3;
                uint32_t bAddr = bBase + (uint32_t)(dblk * 16 * 2);
                LDSM_X4T(bh0, bh1, bh2, bh3, bAddr);
                LDSM_X4T(bl0, bl1, bl2, bl3, bAddr + (AGG_B1 - AGG_B0));
                float* d0 = facc[dblk * 2];
                float* d1 = facc[dblk * 2 + 1];
                MMA_BF16(d0, ah0, ah1, ah2, ah3, bh0, bh1);
                MMA_BF16(d1, ah0, ah1, ah2, ah3, bh2, bh3);
                MMA_BF16(d0, al0, al1, al2, al3, bh0, bh1);
                MMA_BF16(d1, al0, al1, al2, al3, bh2, bh3);
                MMA_BF16(d0, ah0, ah1, ah2, ah3, bl0, bl1);
                MMA_BF16(d1, ah0, ah1, ah2, ah3, bl2, bl3);
            }
        }
    }
    // ---- epilogue: scale 1/N, store ----
    const float inv = 1.0f / (float)NN;
    const int g = lane >> 2, t = lane & 3;
    size_t r0b = (size_t)(row0 + m0 + g) * CD;
#pragma unroll
    for (int dt = 0; dt < 16; dt++) {
        int col = dt * 8 + t * 2;
        *(float2*)&g_agg[r0b + col] = make_float2(facc[dt][0] * inv, facc[dt][1] * inv);
        *(float2*)&g_agg[r0b + 8 * CD + col] = make_float2(facc[dt][2] * inv, facc[dt][3] * inv);
    }
}

// ---------------- K5a: h = relu(agg @ Wm1^T + bm1) --------------------------
__global__ void __launch_bounds__(256) k_mlp1(const float* __restrict__ Wm1,
                                              const float* __restrict__ bm1) {
    __shared__ float As[32][68];
    __shared__ float Bs[32][68];
    const int row0 = blockIdx.y * 64;
    const int o0   = blockIdx.x * 64;
    const int tid = threadIdx.x;
    const int tx = tid & 15, ty = tid >> 4;
    u64 acc[4][2] = {};
    for (int c0 = 0; c0 < CD; c0 += 32) {
#pragma unroll
        for (int p = 0; p < 2; p++) {
            int r = tid >> 2, cq = tid & 3;
            size_t off = (size_t)(row0 + r) * CD + c0 + p * 16 + cq * 4;
            float4 a = ld4(&g_agg[off]);
            As[p*16 + cq*4 + 0][r] = a.x; As[p*16 + cq*4 + 1][r] = a.y;
            As[p*16 + cq*4 + 2][r] = a.z; As[p*16 + cq*4 + 3][r] = a.w;
        }
#pragma unroll
        for (int p = 0; p < 2; p++) {
            int j = (tid >> 3) + p * 32, cq = tid & 7;
            float4 w = ld4(&Wm1[(size_t)(o0 + j) * CD + c0 + cq * 4]);
            Bs[cq*4 + 0][j] = w.x; Bs[cq*4 + 1][j] = w.y;
            Bs[cq*4 + 2][j] = w.z; Bs[cq*4 + 3][j] = w.w;
        }
        __syncthreads();
#pragma unroll
        for (int kk = 0; kk < 32; kk++) {
            float4 a = ld4(&As[kk][ty * 4]);
            const u64* wp = (const u64*)&Bs[kk][tx * 4];
            u64 w0 = wp[0], w1 = wp[1];
            u64 s;
            s = splat2(a.x); fma2(acc[0][0], s, w0); fma2(acc[0][1], s, w1);
            s = splat2(a.y); fma2(acc[1][0], s, w0); fma2(acc[1][1], s, w1);
            s = splat2(a.z); fma2(acc[2][0], s, w0); fma2(acc[2][1], s, w1);
            s = splat2(a.w); fma2(acc[3][0], s, w0); fma2(acc[3][1], s, w1);
        }
        __syncthreads();
    }
    float4 bb = ld4(&bm1[o0 + tx * 4]);
#pragma unroll
    for (int i = 0; i < 4; i++) {
        float4 o; unp(acc[i][0], o.x, o.y); unp(acc[i][1], o.z, o.w);
        size_t ob = (size_t)(row0 + ty * 4 + i) * (4 * CD) + o0 + tx * 4;
        st4(&g_hid[ob], make_float4(fmaxf(o.x + bb.x, 0.f), fmaxf(o.y + bb.y, 0.f),
                                    fmaxf(o.z + bb.z, 0.f), fmaxf(o.w + bb.w, 0.f)));
    }
}

// ---------------- K5b: out = h @ Wm2^T + bm2 + x^T, transposed store --------
__global__ void __launch_bounds__(256) k_mlp2(const float* __restrict__ Wm2,
                                              const float* __restrict__ bm2,
                                              const float* __restrict__ x,
                                              float* __restrict__ out) {
    __shared__ float As[16][68];
    __shared__ float Bs[16][132];
    __shared__ float Csm[64][129];
    const int b  = blockIdx.y;
    const int n0 = blockIdx.x * 64;
    const int row0 = b * NN + n0;
    const int tid = threadIdx.x;
    const int tx = tid & 15, ty = tid >> 4;
    const int d0 = tx * 8, r0 = ty * 4;
    u64 acc[4][4] = {};
    for (int step = 0; step < 32; step++) {
        int o0 = step * 16;
        __syncthreads();
        {
            int r = tid >> 2, oq = tid & 3;
            float4 h = ld4(&g_hid[(size_t)(row0 + r) * (4 * CD) + o0 + oq * 4]);
            As[oq*4 + 0][r] = h.x; As[oq*4 + 1][r] = h.y;
            As[oq*4 + 2][r] = h.z; As[oq*4 + 3][r] = h.w;
        }
#pragma unroll
        for (int p = 0; p < 2; p++) {
            int d = (tid >> 2) + p * 64, oq = tid & 3;
            float4 w = ld4(&Wm2[(size_t)d * (4 * CD) + o0 + oq * 4]);
            Bs[oq*4 + 0][d] = w.x; Bs[oq*4 + 1][d] = w.y;
            Bs[oq*4 + 2][d] = w.z; Bs[oq*4 + 3][d] = w.w;
        }
        __syncthreads();
#pragma unroll
        for (int kk = 0; kk < 16; kk++) {
            float4 a = ld4(&As[kk][r0]);
            const u64* bp = (const u64*)&Bs[kk][d0];
            u64 b0 = bp[0], b1 = bp[1], b2 = bp[2], b3 = bp[3];
            u64 s;
            s = splat2(a.x); fma2(acc[0][0],s,b0); fma2(acc[0][1],s,b1); fma2(acc[0][2],s,b2); fma2(acc[0][3],s,b3);
            s = splat2(a.y); fma2(acc[1][0],s,b0); fma2(acc[1][1],s,b1); fma2(acc[1][2],s,b2); fma2(acc[1][3],s,b3);
            s = splat2(a.z); fma2(acc[2][0],s,b0); fma2(acc[2][1],s,b1); fma2(acc[2][2],s,b2); fma2(acc[2][3],s,b3);
            s = splat2(a.w); fma2(acc[3][0],s,b0); fma2(acc[3][1],s,b1); fma2(acc[3][2],s,b2); fma2(acc[3][3],s,b3);
        }
    }
    float4 b2a = ld4(&bm2[d0]);
    float4 b2b = ld4(&bm2[d0 + 4]);
    float bvv[8] = {b2a.x,b2a.y,b2a.z,b2a.w,b2b.x,b2b.y,b2b.z,b2b.w};
    __syncthreads();
#pragma unroll
    for (int i = 0; i < 4; i++) {
        float o[8];
        unp(acc[i][0], o[0], o[1]); unp(acc[i][1], o[2], o[3]);
        unp(acc[i][2], o[4], o[5]); unp(acc[i][3], o[6], o[7]);
#pragma unroll
        for (int j = 0; j < 8; j++) Csm[r0 + i][d0 + j] = o[j] + bvv[j];
    }
    __syncthreads();
    for (int v = tid; v < 64 * CD; v += 256) {
        int dd = v >> 6, nn = v & 63;
        size_t oa = ((size_t)b * CD + dd) * NN + n0 + nn;
        out[oa] = Csm[nn][dd] + x[oa];
    }
}

// ---------------- launcher ---------------------------------------------------
extern "C" void kernel_launch(void* const* d_in, const int* in_sizes, int n_in,
                              void* d_out, int out_size) {
    (void)in_sizes; (void)n_in; (void)out_size;
    const float* pos  = (const float*)d_in[0];
    const float* x    = (const float*)d_in[1];
    const void*  idx  = d_in[2];
    const float* dist = (const float*)d_in[3];
    const float* Wqkv = (const float*)d_in[4];
    const float* W1   = (const float*)d_in[5];
    const float* b1   = (const float*)d_in[6];
    const float* W2   = (const float*)d_in[7];
    const float* b2   = (const float*)d_in[8];
    const float* Wm1  = (const float*)d_in[9];
    const float* bm1  = (const float*)d_in[10];
    const float* Wm2  = (const float*)d_in[11];
    const float* bm2  = (const float*)d_in[12];
    float* out = (float*)d_out;

    cudaFuncSetAttribute(k_agg_mma, cudaFuncAttributeMaxDynamicSharedMemorySize, AGG_SMEM);

    k_detect <<<1, 256>>>((const unsigned int*)idx);
    k_qkv    <<<dim3(6, NN / 64, BB), 256>>>(x, Wqkv);
    k_invq   <<<ROWS / 8, 256>>>();
    k_pe     <<<GROWS / 128, 256>>>(pos, idx, dist, W1, b1, W2, b2);
    k_kv     <<<dim3(NSPLIT, PAIRS), 256>>>(idx);
    k_red    <<<(PAIRS * CD * CD) / (256 * 4), 256>>>();
    k_kvsplit<<<dim3(2, PAIRS), 256>>>();
    k_agg_mma<<<ROWS / 128, 256, AGG_SMEM>>>(idx);
    k_mlp1   <<<dim3(8, ROWS / 64), 256>>>(Wm1, bm1);
    k_mlp2   <<<dim3(NN / 64, BB), 256>>>(Wm2, bm2, x, out);
}

// round 10
// speedup vs baseline: 1.5681x; 1.1357x over previous
#include <cuda_runtime.h>
#include <cuda_bf16.h>
#include <cstdint>

#define BB  4
#define NN  4096
#define NBK 16
#define CD  128
#define HID 64
#define ROWS (BB*NN)            // 16384
#define GROWS (BB*NN*NBK)       // 262144
#define PAIRS (BB*NBK)          // 64
#define NSPLIT 8
#define BPITCH 136              // bf16 tile pitch (272 B rows: 16B-aligned, ldmatrix conflict-free)

// ---------------- scratch (device globals; no allocation allowed) ----------
__device__ float g_qkv [ROWS*3*CD];                 // 25 MB
__device__ float g_invq[ROWS];
__device__ float g_pe  [(size_t)GROWS*CD];          // pos_emb, 134 MB
__device__ float g_kvp [NSPLIT][PAIRS*CD*CD];       // split partials 32 MB; [0]=reduced
__device__ unsigned short g_kvb[PAIRS][2][128*BPITCH]; // bf16 hi/lo kv images, 4.5 MB
__device__ float g_agg [ROWS*CD];                   // 8 MB
__device__ float g_hid [ROWS*4*CD];                 // 33 MB
__device__ int   g_idx64;

typedef unsigned long long u64;
__device__ __forceinline__ float4 ld4(const float* p) { return *(const float4*)p; }
__device__ __forceinline__ void   st4(float* p, float4 v) { *(float4*)p = v; }
__device__ __forceinline__ u64 splat2(float a) {
    u64 r; asm("mov.b64 %0, {%1, %1};" : "=l"(r) : "f"(a)); return r;
}
__device__ __forceinline__ u64 pack2(float lo, float hi) {
    u64 r; asm("mov.b64 %0, {%1, %2};" : "=l"(r) : "f"(lo), "f"(hi)); return r;
}
__device__ __forceinline__ void fma2(u64& d, u64 a, u64 b) {
    asm("fma.rn.f32x2 %0, %1, %2, %0;" : "+l"(d) : "l"(a), "l"(b));
}
__device__ __forceinline__ void unp(u64 v, float& lo, float& hi) {
    asm("mov.b64 {%0, %1}, %2;" : "=f"(lo), "=f"(hi) : "l"(v));
}
__device__ __forceinline__ int ld_idx(const void* p, size_t pos) {
    if (g_idx64) return (int)((const long long*)p)[pos];
    return ((const int*)p)[pos];
}
__device__ __forceinline__ uint32_t smem_u32(const void* p) {
    uint32_t a;
    asm("{ .reg .u64 t; cvta.to.shared.u64 t, %1; cvt.u32.u64 %0, t; }" : "=r"(a) : "l"(p));
    return a;
}
__device__ __forceinline__ void bf_split(float x, unsigned short& h, unsigned short& l) {
    __nv_bfloat16 bh = __float2bfloat16(x);
    h = __bfloat16_as_ushort(bh);
    l = __bfloat16_as_ushort(__float2bfloat16(x - __bfloat162float(bh)));
}

#define LDSM_X4(r0,r1,r2,r3, a) \
    asm volatile("ldmatrix.sync.aligned.m8n8.x4.shared.b16 {%0,%1,%2,%3}, [%4];" \
        : "=r"(r0),"=r"(r1),"=r"(r2),"=r"(r3) : "r"(a))
#define LDSM_X4T(r0,r1,r2,r3, a) \
    asm volatile("ldmatrix.sync.aligned.m8n8.x4.trans.shared.b16 {%0,%1,%2,%3}, [%4];" \
        : "=r"(r0),"=r"(r1),"=r"(r2),"=r"(r3) : "r"(a))
#define MMA_BF16(d, a0,a1,a2,a3, b0,b1) \
    asm volatile("mma.sync.aligned.m16n8k16.row.col.f32.bf16.bf16.f32 " \
        "{%0,%1,%2,%3}, {%4,%5,%6,%7}, {%8,%9}, {%0,%1,%2,%3};" \
        : "+f"((d)[0]),"+f"((d)[1]),"+f"((d)[2]),"+f"((d)[3]) \
        : "r"(a0),"r"(a1),"r"(a2),"r"(a3), "r"(b0),"r"(b1))

// ---------------- idx dtype autodetect -------------------------------------
__global__ void k_detect(const unsigned int* __restrict__ w) {
    __shared__ int any;
    if (threadIdx.x == 0) any = 0;
    __syncthreads();
    unsigned int v = w[1 + 2 * threadIdx.x];
    if (v != 0u) any = 1;
    __syncthreads();
    if (threadIdx.x == 0) g_idx64 = (any ? 0 : 1);
}

// ---------------- K1: qkv = x^T @ Wqkv^T ------------------------------------
__global__ void __launch_bounds__(256) k_qkv(const float* __restrict__ x,
                                             const float* __restrict__ Wqkv) {
    __shared__ float As[32][64];
    __shared__ float Bs[32][68];
    const int b  = blockIdx.z;
    const int n0 = blockIdx.y * 64;
    const int o0 = blockIdx.x * 64;
    const int tid = threadIdx.x;
    const int tx = tid & 15, ty = tid >> 4;
    u64 acc[4][2] = {};
    for (int c0 = 0; c0 < CD; c0 += 32) {
#pragma unroll
        for (int p = 0; p < 8; p++) {
            int v = tid + p * 256;
            int cc = v >> 6, i = v & 63;
            As[cc][i] = x[((size_t)b * CD + c0 + cc) * NN + n0 + i];
        }
#pragma unroll
        for (int p = 0; p < 8; p++) {
            int v = tid + p * 256;
            int cc = v & 31, j = v >> 5;
            Bs[cc][j] = Wqkv[(size_t)(o0 + j) * CD + c0 + cc];
        }
        __syncthreads();
#pragma unroll
        for (int kk = 0; kk < 32; kk++) {
            float4 a = ld4(&As[kk][ty * 4]);
            const u64* wp = (const u64*)&Bs[kk][tx * 4];
            u64 w0 = wp[0], w1 = wp[1];
            u64 s;
            s = splat2(a.x); fma2(acc[0][0], s, w0); fma2(acc[0][1], s, w1);
            s = splat2(a.y); fma2(acc[1][0], s, w0); fma2(acc[1][1], s, w1);
            s = splat2(a.z); fma2(acc[2][0], s, w0); fma2(acc[2][1], s, w1);
            s = splat2(a.w); fma2(acc[3][0], s, w0); fma2(acc[3][1], s, w1);
        }
        __syncthreads();
    }
#pragma unroll
    for (int i = 0; i < 4; i++) {
        float4 o; unp(acc[i][0], o.x, o.y); unp(acc[i][1], o.z, o.w);
        size_t ob = ((size_t)b * NN + n0 + ty * 4 + i) * (3 * CD) + o0 + tx * 4;
        st4(&g_qkv[ob], o);
    }
}

// ---------------- K1b: 1/||Q_row|| ------------------------------------------
__global__ void __launch_bounds__(256) k_invq() {
    int row  = blockIdx.x * 8 + (threadIdx.x >> 5);
    int lane = threadIdx.x & 31;
    float4 q = ld4(&g_qkv[(size_t)row * (3 * CD) + lane * 4]);
    float s = q.x * q.x + q.y * q.y + q.z * q.z + q.w * q.w;
#pragma unroll
    for (int o = 16; o; o >>= 1) s += __shfl_xor_sync(0xffffffffu, s, o);
    if (lane == 0) g_invq[row] = 1.0f / fmaxf(sqrtf(s), 1e-12f);
}

// ---------------- K2: pos-MLP -> g_pe [GROWS][CD] ---------------------------
__global__ void __launch_bounds__(256, 2) k_pe(
    const float* __restrict__ pos, const void* __restrict__ idx,
    const float* __restrict__ dist,
    const float* __restrict__ W1, const float* __restrict__ b1,
    const float* __restrict__ W2, const float* __restrict__ b2) {
    __shared__ float W2s[32][CD];
    __shared__ float hsT[32][132];
    __shared__ float W1s[HID * 10];
    __shared__ float b1s[HID];
    __shared__ float b2s[CD];
    __shared__ float feats[128][12];
    const int tid = threadIdx.x;
    const size_t g0 = (size_t)blockIdx.x * 128;
    const int tx = tid & 15, ty = tid >> 4;
    const int c0 = tx * 8, r0 = ty * 8;

    for (int v = tid; v < HID * 10; v += 256) W1s[v] = W1[v];
    if (tid < HID) b1s[tid] = b1[tid];
    if (tid < CD)  b2s[tid] = b2[tid];
    if (tid < 128) {
        size_t g = g0 + tid;
        int b = (int)(g >> 16);
        int n = (int)((g >> 4) & (NN - 1));
        int j = ld_idx(idx, g);
        const float* pc = &pos[((size_t)b * NN + n) * 3];
        const float* pn = &pos[((size_t)b * NN + j) * 3];
        float a0 = pc[0], a1 = pc[1], a2 = pc[2];
        float q0 = pn[0], q1 = pn[1], q2 = pn[2];
        feats[tid][0] = a0;  feats[tid][1] = a1;  feats[tid][2] = a2;
        feats[tid][3] = q0;  feats[tid][4] = q1;  feats[tid][5] = q2;
        feats[tid][6] = a0 - q0; feats[tid][7] = a1 - q1; feats[tid][8] = a2 - q2;
        feats[tid][9] = dist[g];
    }
    __syncthreads();

    u64 acc[8][4];
    {
        u64 bi[4];
#pragma unroll
        for (int q = 0; q < 4; q++) bi[q] = pack2(b2s[c0 + 2*q], b2s[c0 + 2*q + 1]);
#pragma unroll
        for (int i = 0; i < 8; i++)
#pragma unroll
            for (int q = 0; q < 4; q++) acc[i][q] = bi[q];
    }

    for (int jc = 0; jc < 2; jc++) {
        const int j0 = jc * 32;
        if (jc) __syncthreads();
#pragma unroll
        for (int p = 0; p < 16; p++) {
            int v = tid + p * 256;
            int c = v >> 5, jj = v & 31;
            W2s[jj][c] = W2[(size_t)c * HID + j0 + jj];
        }
#pragma unroll
        for (int p = 0; p < 16; p++) {
            int v = tid + p * 256;
            int jj = v & 31, r = v >> 5;
            int j = j0 + jj;
            float s = b1s[j];
#pragma unroll
            for (int i = 0; i < 10; i++) s += feats[r][i] * W1s[j * 10 + i];
            hsT[jj][r] = fmaxf(s, 0.0f);
        }
        __syncthreads();
#pragma unroll 4
        for (int kk = 0; kk < 32; kk++) {
            float4 a0 = ld4(&hsT[kk][r0]);
            float4 a1 = ld4(&hsT[kk][r0 + 4]);
            const u64* bp = (const u64*)&W2s[kk][c0];
            u64 b0 = bp[0], b1v = bp[1], b2v = bp[2], b3 = bp[3];
            float av[8] = {a0.x,a0.y,a0.z,a0.w,a1.x,a1.y,a1.z,a1.w};
#pragma unroll
            for (int i = 0; i < 8; i++) {
                u64 s = splat2(av[i]);
                fma2(acc[i][0], s, b0); fma2(acc[i][1], s, b1v);
                fma2(acc[i][2], s, b2v); fma2(acc[i][3], s, b3);
            }
        }
    }
#pragma unroll
    for (int i = 0; i < 8; i++) {
        float o[8];
        unp(acc[i][0], o[0], o[1]); unp(acc[i][1], o[2], o[3]);
        unp(acc[i][2], o[4], o[5]); unp(acc[i][3], o[6], o[7]);
        size_t ob = (g0 + r0 + i) * CD + c0;
        st4(&g_pe[ob],     make_float4(o[0], o[1], o[2], o[3]));
        st4(&g_pe[ob + 4], make_float4(o[4], o[5], o[6], o[7]));
    }
}

// ---------------- K3: kv outer product via mma.sync bf16 hi/lo --------------
// grid (NSPLIT, PAIRS); per 16-n step: stage Kn/Vr bf16 hi/lo [n][c/d] tiles;
// A frag = ldmatrix.trans of Kn (reorder r0,r2,r1,r3); B = trans of Vr.
__global__ void __launch_bounds__(256, 2) k_kv_mma(const void* __restrict__ idx) {
    __shared__ unsigned short KnH[16 * BPITCH];
    __shared__ unsigned short KnL[16 * BPITCH];
    __shared__ unsigned short VrH[16 * BPITCH];
    __shared__ unsigned short VrL[16 * BPITCH];
    const int p = blockIdx.y;
    const int s = blockIdx.x;
    const int b = p >> 4, kslot = p & 15;
    const int tid = threadIdx.x;
    const int lane = tid & 31, warp = tid >> 5;
    const int c4 = lane * 4;
    const int m0 = warp * 16;            // this warp's c-range

    const uint32_t knh = smem_u32(KnH), knl = smem_u32(KnL);
    const uint32_t vrh = smem_u32(VrH), vrl = smem_u32(VrL);
    const int rowSel = lane & 15;
    const int colSel = (lane >> 4) << 3;
    const uint32_t aTerm = (uint32_t)((rowSel * BPITCH + m0 + colSel) * 2);
    const uint32_t bTerm = (uint32_t)((rowSel * BPITCH + colSel) * 2);

    float facc[16][4] = {};

    const int n0 = s * (NN / NSPLIT);
    const int NSTEP = (NN / NSPLIT) / 16;
    for (int step = 0; step < NSTEP; step++) {
        const int nbase = n0 + step * 16;
        __syncthreads();
#pragma unroll
        for (int rr = 0; rr < 2; rr++) {
            int row = warp * 2 + rr;
            int n = nbase + row;
            size_t g = ((size_t)(b * NN + n)) * NBK + kslot;
            int j = ld_idx(idx, g);
            float4 pe = ld4(&g_pe[g * CD + c4]);
            const float* qrow = &g_qkv[((size_t)b * NN + j) * (3 * CD)];
            float4 kg = ld4(&qrow[CD + c4]);
            float4 vg = ld4(&qrow[2 * CD + c4]);
            float k0 = kg.x + pe.x, k1 = kg.y + pe.y, k2 = kg.z + pe.z, k3 = kg.w + pe.w;
            float v0 = fmaxf(vg.x + pe.x, 0.f), v1 = fmaxf(vg.y + pe.y, 0.f);
            float v2 = fmaxf(vg.z + pe.z, 0.f), v3 = fmaxf(vg.w + pe.w, 0.f);
            float ss = k0 * k0 + k1 * k1 + k2 * k2 + k3 * k3;
#pragma unroll
            for (int o = 16; o; o >>= 1) ss += __shfl_xor_sync(0xffffffffu, ss, o);
            float sc = 1.0f / fmaxf(sqrtf(ss), 1e-12f);
            k0 *= sc; k1 *= sc; k2 *= sc; k3 *= sc;
            unsigned short kh[4], kl[4], vh[4], vl[4];
            bf_split(k0, kh[0], kl[0]); bf_split(k1, kh[1], kl[1]);
            bf_split(k2, kh[2], kl[2]); bf_split(k3, kh[3], kl[3]);
            bf_split(v0, vh[0], vl[0]); bf_split(v1, vh[1], vl[1]);
            bf_split(v2, vh[2], vl[2]); bf_split(v3, vh[3], vl[3]);
            int off = row * BPITCH + c4;
            *(uint2*)&KnH[off] = make_uint2((uint32_t)kh[0] | ((uint32_t)kh[1] << 16),
                                            (uint32_t)kh[2] | ((uint32_t)kh[3] << 16));
            *(uint2*)&KnL[off] = make_uint2((uint32_t)kl[0] | ((uint32_t)kl[1] << 16),
                                            (uint32_t)kl[2] | ((uint32_t)kl[3] << 16));
            *(uint2*)&VrH[off] = make_uint2((uint32_t)vh[0] | ((uint32_t)vh[1] << 16),
                                            (uint32_t)vh[2] | ((uint32_t)vh[3] << 16));
            *(uint2*)&VrL[off] = make_uint2((uint32_t)vl[0] | ((uint32_t)vl[1] << 16),
                                            (uint32_t)vl[2] | ((uint32_t)vl[3] << 16));
        }
        __syncthreads();
        // A fragments (hi/lo) via trans ldmatrix on [n][c] tile; reorder (r0,r2,r1,r3)
        uint32_t t0, t1, t2, t3;
        uint32_t ah0, ah1, ah2, ah3, al0, al1, al2, al3;
        LDSM_X4T(t0, t1, t2, t3, knh + aTerm);
        ah0 = t0; ah1 = t2; ah2 = t1; ah3 = t3;
        LDSM_X4T(t0, t1, t2, t3, knl + aTerm);
        al0 = t0; al1 = t2; al2 = t1; al3 = t3;
#pragma unroll
        for (int dblk = 0; dblk < 8; dblk++) {
            uint32_t bh0, bh1, bh2, bh3, bl0, bl1, bl2, bl3;
            uint32_t bOff = bTerm + (uint32_t)(dblk * 16 * 2);
            LDSM_X4T(bh0, bh1, bh2, bh3, vrh + bOff);
            LDSM_X4T(bl0, bl1, bl2, bl3, vrl + bOff);
            float* d0 = facc[dblk * 2];
            float* d1 = facc[dblk * 2 + 1];
            MMA_BF16(d0, ah0, ah1, ah2, ah3, bh0, bh1);
            MMA_BF16(d1, ah0, ah1, ah2, ah3, bh2, bh3);
            MMA_BF16(d0, al0, al1, al2, al3, bh0, bh1);
            MMA_BF16(d1, al0, al1, al2, al3, bh2, bh3);
            MMA_BF16(d0, ah0, ah1, ah2, ah3, bl0, bl1);
            MMA_BF16(d1, ah0, ah1, ah2, ah3, bl2, bl3);
        }
    }
    // epilogue: write c16 x d128 partials
    float* op = &g_kvp[s][(size_t)p * CD * CD];
    const int g = lane >> 2, t = lane & 3;
#pragma unroll
    for (int dt = 0; dt < 16; dt++) {
        int col = dt * 8 + t * 2;
        *(float2*)&op[(size_t)(m0 + g) * CD + col]     = make_float2(facc[dt][0], facc[dt][1]);
        *(float2*)&op[(size_t)(m0 + 8 + g) * CD + col] = make_float2(facc[dt][2], facc[dt][3]);
    }
}

// ---------------- K3b: reduce split partials into g_kvp[0] ------------------
__global__ void __launch_bounds__(256) k_red() {
    size_t i = ((size_t)blockIdx.x * 256 + threadIdx.x) * 4;
    float4 s = ld4(&g_kvp[0][i]);
#pragma unroll
    for (int t = 1; t < NSPLIT; t++) {
        float4 v = ld4(&g_kvp[t][i]);
        s.x += v.x; s.y += v.y; s.z += v.z; s.w += v.w;
    }
    st4(&g_kvp[0][i], s);
}

// ---------------- K3c: kv -> bf16 hi/lo images [c][d], pitch BPITCH ---------
__global__ void __launch_bounds__(256) k_kvsplit() {
    const int v = blockIdx.x;          // 0=hi, 1=lo
    const int p = blockIdx.y;
    const int tid = threadIdx.x;
    const float* src = &g_kvp[0][(size_t)p * CD * CD];
    unsigned short* dst = &g_kvb[p][v][0];
    for (int e = tid; e < CD * CD; e += 256) {
        int c = e >> 7, d = e & 127;
        float x = src[e];
        __nv_bfloat16 bh = __float2bfloat16(x);
        unsigned short bits;
        if (v == 0) bits = __bfloat16_as_ushort(bh);
        else bits = __bfloat16_as_ushort(__float2bfloat16(x - __bfloat162float(bh)));
        dst[c * BPITCH + d] = bits;
    }
}

// ---------------- K4: agg via mma.sync bf16 hi/lo ---------------------------
#define AGG_A0 0
#define AGG_A1 34816
#define AGG_B0 69632
#define AGG_B1 104448
#define AGG_SMEM 139264

__global__ void __launch_bounds__(256, 1) k_agg_mma(const void* __restrict__ idx) {
    extern __shared__ __align__(16) unsigned char dsm[];
    __shared__ int   jr[128];
    __shared__ float sc[128];
    const uint32_t sb = smem_u32(dsm);
    const int tid = threadIdx.x;
    const int wid = tid >> 5, lane = tid & 31;
    const int row0 = blockIdx.x * 128;
    const int b = row0 >> 12;
    const int m0 = wid * 16;

    const int rowSel = lane & 15;
    const int colSel = (lane >> 4) << 3;
    const uint32_t aTerm = (uint32_t)(((m0 + rowSel) * BPITCH + colSel) * 2);
    const uint32_t bTerm = (uint32_t)((rowSel * BPITCH + colSel) * 2);

    float facc[16][4] = {};

    const int arow = tid >> 1, ahalf = tid & 1;

    for (int k = 0; k < NBK; k++) {
        __syncthreads();
        if (tid < 128) {
            int j = ld_idx(idx, ((size_t)(row0 + tid)) * NBK + k);
            jr[tid] = j;
            sc[tid] = g_invq[b * NN + j];
        }
        __syncthreads();
        {
            int j = jr[arow];
            float s = sc[arow];
            const float* qrow = &g_qkv[((size_t)b * NN + j) * (3 * CD) + ahalf * 64];
            unsigned char* Ah = dsm + AGG_A0;
            unsigned char* Al = dsm + AGG_A1;
#pragma unroll
            for (int gg = 0; gg < 8; gg++) {
                float4 qa = ld4(qrow + gg * 8);
                float4 qb = ld4(qrow + gg * 8 + 4);
                float xs[8] = {qa.x*s, qa.y*s, qa.z*s, qa.w*s, qb.x*s, qb.y*s, qb.z*s, qb.w*s};
                unsigned short h[8], l[8];
#pragma unroll
                for (int q = 0; q < 8; q++) bf_split(xs[q], h[q], l[q]);
                uint4 vh, vl;
                vh.x = (uint32_t)h[0] | ((uint32_t)h[1] << 16);
                vh.y = (uint32_t)h[2] | ((uint32_t)h[3] << 16);
                vh.z = (uint32_t)h[4] | ((uint32_t)h[5] << 16);
                vh.w = (uint32_t)h[6] | ((uint32_t)h[7] << 16);
                vl.x = (uint32_t)l[0] | ((uint32_t)l[1] << 16);
                vl.y = (uint32_t)l[2] | ((uint32_t)l[3] << 16);
                vl.z = (uint32_t)l[4] | ((uint32_t)l[5] << 16);
                vl.w = (uint32_t)l[6] | ((uint32_t)l[7] << 16);
                uint32_t off = (uint32_t)((arow * BPITCH + ahalf * 64 + gg * 8) * 2);
                *(uint4*)(Ah + off) = vh;
                *(uint4*)(Al + off) = vl;
            }
        }
        {
            const int p = b * NBK + k;
            uint4* Bh = (uint4*)(dsm + AGG_B0);
            uint4* Bl = (uint4*)(dsm + AGG_B1);
            const uint4* sh = (const uint4*)&g_kvb[p][0][0];
            const uint4* sl = (const uint4*)&g_kvb[p][1][0];
            for (int e = tid; e < (128 * BPITCH * 2) / 16; e += 256) {
                Bh[e] = sh[e];
                Bl[e] = sl[e];
            }
        }
        __syncthreads();
#pragma unroll 1
        for (int cc = 0; cc < 8; cc++) {
            uint32_t ah0, ah1, ah2, ah3, al0, al1, al2, al3;
            uint32_t aAddr = sb + AGG_A0 + aTerm + (uint32_t)(cc * 16 * 2);
            LDSM_X4(ah0, ah1, ah2, ah3, aAddr);
            LDSM_X4(al0, al1, al2, al3, aAddr + (AGG_A1 - AGG_A0));
            uint32_t bBase = sb + AGG_B0 + bTerm + (uint32_t)(cc * 16 * BPITCH * 2);
#pragma unroll
            for (int dblk = 0; dblk < 8; dblk++) {
                uint32_t bh0, bh1, bh2, bh3, bl0, bl1, bl2, bl3;
                uint32_t bAddr = bBase + (uint32_t)(dblk * 16 * 2);
                LDSM_X4T(bh0, bh1, bh2, bh3, bAddr);
                LDSM_X4T(bl0, bl1, bl2, bl3, bAddr + (AGG_B1 - AGG_B0));
                float* d0 = facc[dblk * 2];
                float* d1 = facc[dblk * 2 + 1];
                MMA_BF16(d0, ah0, ah1, ah2, ah3, bh0, bh1);
                MMA_BF16(d1, ah0, ah1, ah2, ah3, bh2, bh3);
                MMA_BF16(d0, al0, al1, al2, al3, bh0, bh1);
                MMA_BF16(d1, al0, al1, al2, al3, bh2, bh3);
                MMA_BF16(d0, ah0, ah1, ah2, ah3, bl0, bl1);
                MMA_BF16(d1, ah0, ah1, ah2, ah3, bl2, bl3);
            }
        }
    }
    const float inv = 1.0f / (float)NN;
    const int g = lane >> 2, t = lane & 3;
    size_t r0b = (size_t)(row0 + m0 + g) * CD;
#pragma unroll
    for (int dt = 0; dt < 16; dt++) {
        int col = dt * 8 + t * 2;
        *(float2*)&g_agg[r0b + col] = make_float2(facc[dt][0] * inv, facc[dt][1] * inv);
        *(float2*)&g_agg[r0b + 8 * CD + col] = make_float2(facc[dt][2] * inv, facc[dt][3] * inv);
    }
}

// ---------------- K5a: h = relu(agg @ Wm1^T + bm1) --------------------------
__global__ void __launch_bounds__(256) k_mlp1(const float* __restrict__ Wm1,
                                              const float* __restrict__ bm1) {
    __shared__ float As[32][68];
    __shared__ float Bs[32][68];
    const int row0 = blockIdx.y * 64;
    const int o0   = blockIdx.x * 64;
    const int tid = threadIdx.x;
    const int tx = tid & 15, ty = tid >> 4;
    u64 acc[4][2] = {};
    for (int c0 = 0; c0 < CD; c0 += 32) {
#pragma unroll
        for (int p = 0; p < 2; p++) {
            int r = tid >> 2, cq = tid & 3;
            size_t off = (size_t)(row0 + r) * CD + c0 + p * 16 + cq * 4;
            float4 a = ld4(&g_agg[off]);
            As[p*16 + cq*4 + 0][r] = a.x; As[p*16 + cq*4 + 1][r] = a.y;
            As[p*16 + cq*4 + 2][r] = a.z; As[p*16 + cq*4 + 3][r] = a.w;
        }
#pragma unroll
        for (int p = 0; p < 2; p++) {
            int j = (tid >> 3) + p * 32, cq = tid & 7;
            float4 w = ld4(&Wm1[(size_t)(o0 + j) * CD + c0 + cq * 4]);
            Bs[cq*4 + 0][j] = w.x; Bs[cq*4 + 1][j] = w.y;
            Bs[cq*4 + 2][j] = w.z; Bs[cq*4 + 3][j] = w.w;
        }
        __syncthreads();
#pragma unroll
        for (int kk = 0; kk < 32; kk++) {
            float4 a = ld4(&As[kk][ty * 4]);
            const u64* wp = (const u64*)&Bs[kk][tx * 4];
            u64 w0 = wp[0], w1 = wp[1];
            u64 s;
            s = splat2(a.x); fma2(acc[0][0], s, w0); fma2(acc[0][1], s, w1);
            s = splat2(a.y); fma2(acc[1][0], s, w0); fma2(acc[1][1], s, w1);
            s = splat2(a.z); fma2(acc[2][0], s, w0); fma2(acc[2][1], s, w1);
            s = splat2(a.w); fma2(acc[3][0], s, w0); fma2(acc[3][1], s, w1);
        }
        __syncthreads();
    }
    float4 bb = ld4(&bm1[o0 + tx * 4]);
#pragma unroll
    for (int i = 0; i < 4; i++) {
        float4 o; unp(acc[i][0], o.x, o.y); unp(acc[i][1], o.z, o.w);
        size_t ob = (size_t)(row0 + ty * 4 + i) * (4 * CD) + o0 + tx * 4;
        st4(&g_hid[ob], make_float4(fmaxf(o.x + bb.x, 0.f), fmaxf(o.y + bb.y, 0.f),
                                    fmaxf(o.z + bb.z, 0.f), fmaxf(o.w + bb.w, 0.f)));
    }
}

// ---------------- K5b: out = h @ Wm2^T + bm2 + x^T, transposed store --------
__global__ void __launch_bounds__(256) k_mlp2(const float* __restrict__ Wm2,
                                              const float* __restrict__ bm2,
                                              const float* __restrict__ x,
                                              float* __restrict__ out) {
    __shared__ float As[16][68];
    __shared__ float Bs[16][132];
    __shared__ float Csm[64][129];
    const int b  = blockIdx.y;
    const int n0 = blockIdx.x * 64;
    const int row0 = b * NN + n0;
    const int tid = threadIdx.x;
    const int tx = tid & 15, ty = tid >> 4;
    const int d0 = tx * 8, r0 = ty * 4;
    u64 acc[4][4] = {};
    for (int step = 0; step < 32; step++) {
        int o0 = step * 16;
        __syncthreads();
        {
            int r = tid >> 2, oq = tid & 3;
            float4 h = ld4(&g_hid[(size_t)(row0 + r) * (4 * CD) + o0 + oq * 4]);
            As[oq*4 + 0][r] = h.x; As[oq*4 + 1][r] = h.y;
            As[oq*4 + 2][r] = h.z; As[oq*4 + 3][r] = h.w;
        }
#pragma unroll
        for (int p = 0; p < 2; p++) {
            int d = (tid >> 2) + p * 64, oq = tid & 3;
            float4 w = ld4(&Wm2[(size_t)d * (4 * CD) + o0 + oq * 4]);
            Bs[oq*4 + 0][d] = w.x; Bs[oq*4 + 1][d] = w.y;
            Bs[oq*4 + 2][d] = w.z; Bs[oq*4 + 3][d] = w.w;
        }
        __syncthreads();
#pragma unroll
        for (int kk = 0; kk < 16; kk++) {
            float4 a = ld4(&As[kk][r0]);
            const u64* bp = (const u64*)&Bs[kk][d0];
            u64 b0 = bp[0], b1 = bp[1], b2 = bp[2], b3 = bp[3];
            u64 s;
            s = splat2(a.x); fma2(acc[0][0],s,b0); fma2(acc[0][1],s,b1); fma2(acc[0][2],s,b2); fma2(acc[0][3],s,b3);
            s = splat2(a.y); fma2(acc[1][0],s,b0); fma2(acc[1][1],s,b1); fma2(acc[1][2],s,b2); fma2(acc[1][3],s,b3);
            s = splat2(a.z); fma2(acc[2][0],s,b0); fma2(acc[2][1],s,b1); fma2(acc[2][2],s,b2); fma2(acc[2][3],s,b3);
            s = splat2(a.w); fma2(acc[3][0],s,b0); fma2(acc[3][1],s,b1); fma2(acc[3][2],s,b2); fma2(acc[3][3],s,b3);
        }
    }
    float4 b2a = ld4(&bm2[d0]);
    float4 b2b = ld4(&bm2[d0 + 4]);
    float bvv[8] = {b2a.x,b2a.y,b2a.z,b2a.w,b2b.x,b2b.y,b2b.z,b2b.w};
    __syncthreads();
#pragma unroll
    for (int i = 0; i < 4; i++) {
        float o[8];
        unp(acc[i][0], o[0], o[1]); unp(acc[i][1], o[2], o[3]);
        unp(acc[i][2], o[4], o[5]); unp(acc[i][3], o[6], o[7]);
#pragma unroll
        for (int j = 0; j < 8; j++) Csm[r0 + i][d0 + j] = o[j] + bvv[j];
    }
    __syncthreads();
    for (int v = tid; v < 64 * CD; v += 256) {
        int dd = v >> 6, nn = v & 63;
        size_t oa = ((size_t)b * CD + dd) * NN + n0 + nn;
        out[oa] = Csm[nn][dd] + x[oa];
    }
}

// ---------------- launcher ---------------------------------------------------
extern "C" void kernel_launch(void* const* d_in, const int* in_sizes, int n_in,
                              void* d_out, int out_size) {
    (void)in_sizes; (void)n_in; (void)out_size;
    const float* pos  = (const float*)d_in[0];
    const float* x    = (const float*)d_in[1];
    const void*  idx  = d_in[2];
    const float* dist = (const float*)d_in[3];
    const float* Wqkv = (const float*)d_in[4];
    const float* W1   = (const float*)d_in[5];
    const float* b1   = (const float*)d_in[6];
    const float* W2   = (const float*)d_in[7];
    const float* b2   = (const float*)d_in[8];
    const float* Wm1  = (const float*)d_in[9];
    const float* bm1  = (const float*)d_in[10];
    const float* Wm2  = (const float*)d_in[11];
    const float* bm2  = (const float*)d_in[12];
    float* out = (float*)d_out;

    cudaFuncSetAttribute(k_agg_mma, cudaFuncAttributeMaxDynamicSharedMemorySize, AGG_SMEM);

    k_detect <<<1, 256>>>((const unsigned int*)idx);
    k_qkv    <<<dim3(6, NN / 64, BB), 256>>>(x, Wqkv);
    k_invq   <<<ROWS / 8, 256>>>();
    k_pe     <<<GROWS / 128, 256>>>(pos, idx, dist, W1, b1, W2, b2);
    k_kv_mma <<<dim3(NSPLIT, PAIRS), 256>>>(idx);
    k_red    <<<(PAIRS * CD * CD) / (256 * 4), 256>>>();
    k_kvsplit<<<dim3(2, PAIRS), 256>>>();
    k_agg_mma<<<ROWS / 128, 256, AGG_SMEM>>>(idx);
    k_mlp1   <<<dim3(8, ROWS / 64), 256>>>(Wm1, bm1);
    k_mlp2   <<<dim3(NN / 64, BB), 256>>>(Wm2, bm2, x, out);
}

// round 11
// speedup vs baseline: 1.7904x; 1.1417x over previous
#include <cuda_runtime.h>
#include <cuda_bf16.h>
#include <cstdint>

#define BB  4
#define NN  4096
#define NBK 16
#define CD  128
#define HID 64
#define ROWS (BB*NN)            // 16384
#define GROWS (BB*NN*NBK)       // 262144
#define PAIRS (BB*NBK)          // 64
#define NSPLIT 8
#define BPITCH 136              // bf16 tile pitch (272 B rows)
#define APITCH 72               // hs tile pitch (144 B rows)

// ---------------- scratch (device globals; no allocation allowed) ----------
__device__ float g_qkv [ROWS*3*CD];                 // 25 MB
__device__ float g_invq[ROWS];
__device__ float g_pe  [(size_t)GROWS*CD];          // pos_emb, 134 MB
__device__ float g_kvp [NSPLIT][PAIRS*CD*CD];       // split partials 32 MB; [0]=reduced
__device__ unsigned short g_kvb[PAIRS][2][128*BPITCH]; // bf16 hi/lo kv images, 4.5 MB
__device__ unsigned short g_w2b[2][HID*BPITCH];     // bf16 hi/lo W2^T images, 35 KB
__device__ float g_agg [ROWS*CD];                   // 8 MB
__device__ float g_hid [ROWS*4*CD];                 // 33 MB
__device__ int   g_idx64;

typedef unsigned long long u64;
__device__ __forceinline__ float4 ld4(const float* p) { return *(const float4*)p; }
__device__ __forceinline__ void   st4(float* p, float4 v) { *(float4*)p = v; }
__device__ __forceinline__ u64 splat2(float a) {
    u64 r; asm("mov.b64 %0, {%1, %1};" : "=l"(r) : "f"(a)); return r;
}
__device__ __forceinline__ u64 pack2(float lo, float hi) {
    u64 r; asm("mov.b64 %0, {%1, %2};" : "=l"(r) : "f"(lo), "f"(hi)); return r;
}
__device__ __forceinline__ void fma2(u64& d, u64 a, u64 b) {
    asm("fma.rn.f32x2 %0, %1, %2, %0;" : "+l"(d) : "l"(a), "l"(b));
}
__device__ __forceinline__ void unp(u64 v, float& lo, float& hi) {
    asm("mov.b64 {%0, %1}, %2;" : "=f"(lo), "=f"(hi) : "l"(v));
}
__device__ __forceinline__ int ld_idx(const void* p, size_t pos) {
    if (g_idx64) return (int)((const long long*)p)[pos];
    return ((const int*)p)[pos];
}
__device__ __forceinline__ uint32_t smem_u32(const void* p) {
    uint32_t a;
    asm("{ .reg .u64 t; cvta.to.shared.u64 t, %1; cvt.u32.u64 %0, t; }" : "=r"(a) : "l"(p));
    return a;
}
__device__ __forceinline__ void bf_split(float x, unsigned short& h, unsigned short& l) {
    __nv_bfloat16 bh = __float2bfloat16(x);
    h = __bfloat16_as_ushort(bh);
    l = __bfloat16_as_ushort(__float2bfloat16(x - __bfloat162float(bh)));
}

#define LDSM_X4(r0,r1,r2,r3, a) \
    asm volatile("ldmatrix.sync.aligned.m8n8.x4.shared.b16 {%0,%1,%2,%3}, [%4];" \
        : "=r"(r0),"=r"(r1),"=r"(r2),"=r"(r3) : "r"(a))
#define LDSM_X4T(r0,r1,r2,r3, a) \
    asm volatile("ldmatrix.sync.aligned.m8n8.x4.trans.shared.b16 {%0,%1,%2,%3}, [%4];" \
        : "=r"(r0),"=r"(r1),"=r"(r2),"=r"(r3) : "r"(a))
#define MMA_BF16(d, a0,a1,a2,a3, b0,b1) \
    asm volatile("mma.sync.aligned.m16n8k16.row.col.f32.bf16.bf16.f32 " \
        "{%0,%1,%2,%3}, {%4,%5,%6,%7}, {%8,%9}, {%0,%1,%2,%3};" \
        : "+f"((d)[0]),"+f"((d)[1]),"+f"((d)[2]),"+f"((d)[3]) \
        : "r"(a0),"r"(a1),"r"(a2),"r"(a3), "r"(b0),"r"(b1))

// ---------------- idx dtype autodetect -------------------------------------
__global__ void k_detect(const unsigned int* __restrict__ w) {
    __shared__ int any;
    if (threadIdx.x == 0) any = 0;
    __syncthreads();
    unsigned int v = w[1 + 2 * threadIdx.x];
    if (v != 0u) any = 1;
    __syncthreads();
    if (threadIdx.x == 0) g_idx64 = (any ? 0 : 1);
}

// ---------------- K1: qkv = x^T @ Wqkv^T ------------------------------------
__global__ void __launch_bounds__(256) k_qkv(const float* __restrict__ x,
                                             const float* __restrict__ Wqkv) {
    __shared__ float As[32][64];
    __shared__ float Bs[32][68];
    const int b  = blockIdx.z;
    const int n0 = blockIdx.y * 64;
    const int o0 = blockIdx.x * 64;
    const int tid = threadIdx.x;
    const int tx = tid & 15, ty = tid >> 4;
    u64 acc[4][2] = {};
    for (int c0 = 0; c0 < CD; c0 += 32) {
#pragma unroll
        for (int p = 0; p < 8; p++) {
            int v = tid + p * 256;
            int cc = v >> 6, i = v & 63;
            As[cc][i] = x[((size_t)b * CD + c0 + cc) * NN + n0 + i];
        }
#pragma unroll
        for (int p = 0; p < 8; p++) {
            int v = tid + p * 256;
            int cc = v & 31, j = v >> 5;
            Bs[cc][j] = Wqkv[(size_t)(o0 + j) * CD + c0 + cc];
        }
        __syncthreads();
#pragma unroll
        for (int kk = 0; kk < 32; kk++) {
            float4 a = ld4(&As[kk][ty * 4]);
            const u64* wp = (const u64*)&Bs[kk][tx * 4];
            u64 w0 = wp[0], w1 = wp[1];
            u64 s;
            s = splat2(a.x); fma2(acc[0][0], s, w0); fma2(acc[0][1], s, w1);
            s = splat2(a.y); fma2(acc[1][0], s, w0); fma2(acc[1][1], s, w1);
            s = splat2(a.z); fma2(acc[2][0], s, w0); fma2(acc[2][1], s, w1);
            s = splat2(a.w); fma2(acc[3][0], s, w0); fma2(acc[3][1], s, w1);
        }
        __syncthreads();
    }
#pragma unroll
    for (int i = 0; i < 4; i++) {
        float4 o; unp(acc[i][0], o.x, o.y); unp(acc[i][1], o.z, o.w);
        size_t ob = ((size_t)b * NN + n0 + ty * 4 + i) * (3 * CD) + o0 + tx * 4;
        st4(&g_qkv[ob], o);
    }
}

// ---------------- K1b: 1/||Q_row|| ------------------------------------------
__global__ void __launch_bounds__(256) k_invq() {
    int row  = blockIdx.x * 8 + (threadIdx.x >> 5);
    int lane = threadIdx.x & 31;
    float4 q = ld4(&g_qkv[(size_t)row * (3 * CD) + lane * 4]);
    float s = q.x * q.x + q.y * q.y + q.z * q.z + q.w * q.w;
#pragma unroll
    for (int o = 16; o; o >>= 1) s += __shfl_xor_sync(0xffffffffu, s, o);
    if (lane == 0) g_invq[row] = 1.0f / fmaxf(sqrtf(s), 1e-12f);
}

// ---------------- K1c: W2 -> bf16 hi/lo images [j][c], pitch BPITCH ---------
__global__ void __launch_bounds__(256) k_w2split(const float* __restrict__ W2) {
    const int v = blockIdx.x;      // 0=hi, 1=lo
    const int tid = threadIdx.x;
    unsigned short* dst = &g_w2b[v][0];
    for (int e = tid; e < CD * HID; e += 256) {
        int j = e >> 7, c = e & 127;
        float x = W2[(size_t)c * HID + j];
        __nv_bfloat16 bh = __float2bfloat16(x);
        unsigned short bits;
        if (v == 0) bits = __bfloat16_as_ushort(bh);
        else bits = __bfloat16_as_ushort(__float2bfloat16(x - __bfloat162float(bh)));
        dst[j * BPITCH + c] = bits;
    }
}

// ---------------- K2: pos-MLP via mma.sync -> g_pe --------------------------
// 128 rows/block; MLP1 emits bf16 hi/lo A tiles; B = presplit W2^T images.
#define PE_A0 0
#define PE_A1 (128*APITCH*2)                  // 18432
#define PE_B0 (2*128*APITCH*2)                // 36864
#define PE_B1 (PE_B0 + HID*BPITCH*2)          // +17408
#define PE_SMEM (PE_B1 + HID*BPITCH*2)        // 71680

__global__ void __launch_bounds__(256, 2) k_pe_mma(
    const float* __restrict__ pos, const void* __restrict__ idx,
    const float* __restrict__ dist,
    const float* __restrict__ W1, const float* __restrict__ b1,
    const float* __restrict__ b2) {
    extern __shared__ __align__(16) unsigned char dsm[];
    __shared__ float W1s[HID * 10];
    __shared__ float b1s[HID];
    __shared__ float b2s[CD];
    __shared__ float feats[128][12];
    const uint32_t sb = smem_u32(dsm);
    const int tid = threadIdx.x;
    const int wid = tid >> 5, lane = tid & 31;
    const size_t g0 = (size_t)blockIdx.x * 128;
    const int m0 = wid * 16;

    for (int v = tid; v < HID * 10; v += 256) W1s[v] = W1[v];
    if (tid < HID) b1s[tid] = b1[tid];
    if (tid < CD)  b2s[tid] = b2[tid];
    if (tid < 128) {
        size_t g = g0 + tid;
        int b = (int)(g >> 16);
        int n = (int)((g >> 4) & (NN - 1));
        int j = ld_idx(idx, g);
        const float* pc = &pos[((size_t)b * NN + n) * 3];
        const float* pn = &pos[((size_t)b * NN + j) * 3];
        float a0 = pc[0], a1 = pc[1], a2 = pc[2];
        float q0 = pn[0], q1 = pn[1], q2 = pn[2];
        feats[tid][0] = a0;  feats[tid][1] = a1;  feats[tid][2] = a2;
        feats[tid][3] = q0;  feats[tid][4] = q1;  feats[tid][5] = q2;
        feats[tid][6] = a0 - q0; feats[tid][7] = a1 - q1; feats[tid][8] = a2 - q2;
        feats[tid][9] = dist[g];
    }
    // B: copy presplit W2^T hi/lo images
    {
        uint4* Bh = (uint4*)(dsm + PE_B0);
        uint4* Bl = (uint4*)(dsm + PE_B1);
        const uint4* sh = (const uint4*)&g_w2b[0][0];
        const uint4* sl = (const uint4*)&g_w2b[1][0];
        for (int e = tid; e < (HID * BPITCH * 2) / 16; e += 256) {
            Bh[e] = sh[e];
            Bl[e] = sl[e];
        }
    }
    __syncthreads();
    // MLP1 -> bf16 hi/lo A tiles [row][j], pitch APITCH
    {
        unsigned short* Ah = (unsigned short*)(dsm + PE_A0);
        unsigned short* Al = (unsigned short*)(dsm + PE_A1);
#pragma unroll
        for (int p = 0; p < 32; p++) {
            int v = tid + p * 256;
            int j = v & 63, r = v >> 6;
            float s = b1s[j];
#pragma unroll
            for (int i = 0; i < 10; i++) s += feats[r][i] * W1s[j * 10 + i];
            s = fmaxf(s, 0.0f);
            unsigned short h, l;
            bf_split(s, h, l);
            Ah[r * APITCH + j] = h;
            Al[r * APITCH + j] = l;
        }
    }
    __syncthreads();
    // GEMM: A[128x64] @ B^T -> [128x128]; warp = 16 rows
    const int rowSel = lane & 15;
    const int colSel = (lane >> 4) << 3;
    const uint32_t aTerm = (uint32_t)(((m0 + rowSel) * APITCH + colSel) * 2);
    const uint32_t bTerm = (uint32_t)((rowSel * BPITCH + colSel) * 2);
    float facc[16][4] = {};
#pragma unroll
    for (int cc = 0; cc < 4; cc++) {
        uint32_t ah0, ah1, ah2, ah3, al0, al1, al2, al3;
        uint32_t aAddr = sb + PE_A0 + aTerm + (uint32_t)(cc * 16 * 2);
        LDSM_X4(ah0, ah1, ah2, ah3, aAddr);
        LDSM_X4(al0, al1, al2, al3, aAddr + (PE_A1 - PE_A0));
        uint32_t bBase = sb + PE_B0 + bTerm + (uint32_t)(cc * 16 * BPITCH * 2);
#pragma unroll
        for (int dblk = 0; dblk < 8; dblk++) {
            uint32_t bh0, bh1, bh2, bh3, bl0, bl1, bl2, bl3;
            uint32_t bAddr = bBase + (uint32_t)(dblk * 16 * 2);
            LDSM_X4T(bh0, bh1, bh2, bh3, bAddr);
            LDSM_X4T(bl0, bl1, bl2, bl3, bAddr + (PE_B1 - PE_B0));
            float* d0 = facc[dblk * 2];
            float* d1 = facc[dblk * 2 + 1];
            MMA_BF16(d0, ah0, ah1, ah2, ah3, bh0, bh1);
            MMA_BF16(d1, ah0, ah1, ah2, ah3, bh2, bh3);
            MMA_BF16(d0, al0, al1, al2, al3, bh0, bh1);
            MMA_BF16(d1, al0, al1, al2, al3, bh2, bh3);
            MMA_BF16(d0, ah0, ah1, ah2, ah3, bl0, bl1);
            MMA_BF16(d1, ah0, ah1, ah2, ah3, bl2, bl3);
        }
    }
    // epilogue: + bias, store
    const int g = lane >> 2, t = lane & 3;
    size_t r0b = (g0 + m0 + g) * CD;
#pragma unroll
    for (int dt = 0; dt < 16; dt++) {
        int col = dt * 8 + t * 2;
        float bx = b2s[col], by = b2s[col + 1];
        *(float2*)&g_pe[r0b + col] = make_float2(facc[dt][0] + bx, facc[dt][1] + by);
        *(float2*)&g_pe[r0b + 8 * CD + col] = make_float2(facc[dt][2] + bx, facc[dt][3] + by);
    }
}

// ---------------- K3: kv outer product via mma.sync bf16 hi/lo --------------
__global__ void __launch_bounds__(256, 2) k_kv_mma(const void* __restrict__ idx) {
    __shared__ unsigned short KnH[16 * BPITCH];
    __shared__ unsigned short KnL[16 * BPITCH];
    __shared__ unsigned short VrH[16 * BPITCH];
    __shared__ unsigned short VrL[16 * BPITCH];
    const int p = blockIdx.y;
    const int s = blockIdx.x;
    const int b = p >> 4, kslot = p & 15;
    const int tid = threadIdx.x;
    const int lane = tid & 31, warp = tid >> 5;
    const int c4 = lane * 4;
    const int m0 = warp * 16;

    const uint32_t knh = smem_u32(KnH), knl = smem_u32(KnL);
    const uint32_t vrh = smem_u32(VrH), vrl = smem_u32(VrL);
    const int rowSel = lane & 15;
    const int colSel = (lane >> 4) << 3;
    const uint32_t aTerm = (uint32_t)((rowSel * BPITCH + m0 + colSel) * 2);
    const uint32_t bTerm = (uint32_t)((rowSel * BPITCH + colSel) * 2);

    float facc[16][4] = {};

    const int n0 = s * (NN / NSPLIT);
    const int NSTEP = (NN / NSPLIT) / 16;
    for (int step = 0; step < NSTEP; step++) {
        const int nbase = n0 + step * 16;
        __syncthreads();
#pragma unroll
        for (int rr = 0; rr < 2; rr++) {
            int row = warp * 2 + rr;
            int n = nbase + row;
            size_t g = ((size_t)(b * NN + n)) * NBK + kslot;
            int j = ld_idx(idx, g);
            float4 pe = ld4(&g_pe[g * CD + c4]);
            const float* qrow = &g_qkv[((size_t)b * NN + j) * (3 * CD)];
            float4 kg = ld4(&qrow[CD + c4]);
            float4 vg = ld4(&qrow[2 * CD + c4]);
            float k0 = kg.x + pe.x, k1 = kg.y + pe.y, k2 = kg.z + pe.z, k3 = kg.w + pe.w;
            float v0 = fmaxf(vg.x + pe.x, 0.f), v1 = fmaxf(vg.y + pe.y, 0.f);
            float v2 = fmaxf(vg.z + pe.z, 0.f), v3 = fmaxf(vg.w + pe.w, 0.f);
            float ss = k0 * k0 + k1 * k1 + k2 * k2 + k3 * k3;
#pragma unroll
            for (int o = 16; o; o >>= 1) ss += __shfl_xor_sync(0xffffffffu, ss, o);
            float sc = 1.0f / fmaxf(sqrtf(ss), 1e-12f);
            k0 *= sc; k1 *= sc; k2 *= sc; k3 *= sc;
            unsigned short kh[4], kl[4], vh[4], vl[4];
            bf_split(k0, kh[0], kl[0]); bf_split(k1, kh[1], kl[1]);
            bf_split(k2, kh[2], kl[2]); bf_split(k3, kh[3], kl[3]);
            bf_split(v0, vh[0], vl[0]); bf_split(v1, vh[1], vl[1]);
            bf_split(v2, vh[2], vl[2]); bf_split(v3, vh[3], vl[3]);
            int off = row * BPITCH + c4;
            *(uint2*)&KnH[off] = make_uint2((uint32_t)kh[0] | ((uint32_t)kh[1] << 16),
                                            (uint32_t)kh[2] | ((uint32_t)kh[3] << 16));
            *(uint2*)&KnL[off] = make_uint2((uint32_t)kl[0] | ((uint32_t)kl[1] << 16),
                                            (uint32_t)kl[2] | ((uint32_t)kl[3] << 16));
            *(uint2*)&VrH[off] = make_uint2((uint32_t)vh[0] | ((uint32_t)vh[1] << 16),
                                            (uint32_t)vh[2] | ((uint32_t)vh[3] << 16));
            *(uint2*)&VrL[off] = make_uint2((uint32_t)vl[0] | ((uint32_t)vl[1] << 16),
                                            (uint32_t)vl[2] | ((uint32_t)vl[3] << 16));
        }
        __syncthreads();
        uint32_t t0, t1, t2, t3;
        uint32_t ah0, ah1, ah2, ah3, al0, al1, al2, al3;
        LDSM_X4T(t0, t1, t2, t3, knh + aTerm);
        ah0 = t0; ah1 = t2; ah2 = t1; ah3 = t3;
        LDSM_X4T(t0, t1, t2, t3, knl + aTerm);
        al0 = t0; al1 = t2; al2 = t1; al3 = t3;
#pragma unroll
        for (int dblk = 0; dblk < 8; dblk++) {
            uint32_t bh0, bh1, bh2, bh3, bl0, bl1, bl2, bl3;
            uint32_t bOff = bTerm + (uint32_t)(dblk * 16 * 2);
            LDSM_X4T(bh0, bh1, bh2, bh3, vrh + bOff);
            LDSM_X4T(bl0, bl1, bl2, bl3, vrl + bOff);
            float* d0 = facc[dblk * 2];
            float* d1 = facc[dblk * 2 + 1];
            MMA_BF16(d0, ah0, ah1, ah2, ah3, bh0, bh1);
            MMA_BF16(d1, ah0, ah1, ah2, ah3, bh2, bh3);
            MMA_BF16(d0, al0, al1, al2, al3, bh0, bh1);
            MMA_BF16(d1, al0, al1, al2, al3, bh2, bh3);
            MMA_BF16(d0, ah0, ah1, ah2, ah3, bl0, bl1);
            MMA_BF16(d1, ah0, ah1, ah2, ah3, bl2, bl3);
        }
    }
    float* op = &g_kvp[s][(size_t)p * CD * CD];
    const int g = lane >> 2, t = lane & 3;
#pragma unroll
    for (int dt = 0; dt < 16; dt++) {
        int col = dt * 8 + t * 2;
        *(float2*)&op[(size_t)(m0 + g) * CD + col]     = make_float2(facc[dt][0], facc[dt][1]);
        *(float2*)&op[(size_t)(m0 + 8 + g) * CD + col] = make_float2(facc[dt][2], facc[dt][3]);
    }
}

// ---------------- K3b: reduce split partials into g_kvp[0] ------------------
__global__ void __launch_bounds__(256) k_red() {
    size_t i = ((size_t)blockIdx.x * 256 + threadIdx.x) * 4;
    float4 s = ld4(&g_kvp[0][i]);
#pragma unroll
    for (int t = 1; t < NSPLIT; t++) {
        float4 v = ld4(&g_kvp[t][i]);
        s.x += v.x; s.y += v.y; s.z += v.z; s.w += v.w;
    }
    st4(&g_kvp[0][i], s);
}

// ---------------- K3c: kv -> bf16 hi/lo images [c][d], pitch BPITCH ---------
__global__ void __launch_bounds__(256) k_kvsplit() {
    const int v = blockIdx.x;          // 0=hi, 1=lo
    const int p = blockIdx.y;
    const int tid = threadIdx.x;
    const float* src = &g_kvp[0][(size_t)p * CD * CD];
    unsigned short* dst = &g_kvb[p][v][0];
    for (int e = tid; e < CD * CD; e += 256) {
        int c = e >> 7, d = e & 127;
        float x = src[e];
        __nv_bfloat16 bh = __float2bfloat16(x);
        unsigned short bits;
        if (v == 0) bits = __bfloat16_as_ushort(bh);
        else bits = __bfloat16_as_ushort(__float2bfloat16(x - __bfloat162float(bh)));
        dst[c * BPITCH + d] = bits;
    }
}

// ---------------- K4: agg via mma.sync bf16 hi/lo ---------------------------
#define AGG_A0 0
#define AGG_A1 34816
#define AGG_B0 69632
#define AGG_B1 104448
#define AGG_SMEM 139264

__global__ void __launch_bounds__(256, 1) k_agg_mma(const void* __restrict__ idx) {
    extern __shared__ __align__(16) unsigned char dsm[];
    __shared__ int   jr[128];
    __shared__ float sc[128];
    const uint32_t sb = smem_u32(dsm);
    const int tid = threadIdx.x;
    const int wid = tid >> 5, lane = tid & 31;
    const int row0 = blockIdx.x * 128;
    const int b = row0 >> 12;
    const int m0 = wid * 16;

    const int rowSel = lane & 15;
    const int colSel = (lane >> 4) << 3;
    const uint32_t aTerm = (uint32_t)(((m0 + rowSel) * BPITCH + colSel) * 2);
    const uint32_t bTerm = (uint32_t)((rowSel * BPITCH + colSel) * 2);

    float facc[16][4] = {};

    const int arow = tid >> 1, ahalf = tid & 1;

    for (int k = 0; k < NBK; k++) {
        __syncthreads();
        if (tid < 128) {
            int j = ld_idx(idx, ((size_t)(row0 + tid)) * NBK + k);
            jr[tid] = j;
            sc[tid] = g_invq[b * NN + j];
        }
        __syncthreads();
        {
            int j = jr[arow];
            float s = sc[arow];
            const float* qrow = &g_qkv[((size_t)b * NN + j) * (3 * CD) + ahalf * 64];
            unsigned char* Ah = dsm + AGG_A0;
            unsigned char* Al = dsm + AGG_A1;
#pragma unroll
            for (int gg = 0; gg < 8; gg++) {
                float4 qa = ld4(qrow + gg * 8);
                float4 qb = ld4(qrow + gg * 8 + 4);
                float xs[8] = {qa.x*s, qa.y*s, qa.z*s, qa.w*s, qb.x*s, qb.y*s, qb.z*s, qb.w*s};
                unsigned short h[8], l[8];
#pragma unroll
                for (int q = 0; q < 8; q++) bf_split(xs[q], h[q], l[q]);
                uint4 vh, vl;
                vh.x = (uint32_t)h[0] | ((uint32_t)h[1] << 16);
                vh.y = (uint32_t)h[2] | ((uint32_t)h[3] << 16);
                vh.z = (uint32_t)h[4] | ((uint32_t)h[5] << 16);
                vh.w = (uint32_t)h[6] | ((uint32_t)h[7] << 16);
                vl.x = (uint32_t)l[0] | ((uint32_t)l[1] << 16);
                vl.y = (uint32_t)l[2] | ((uint32_t)l[3] << 16);
                vl.z = (uint32_t)l[4] | ((uint32_t)l[5] << 16);
                vl.w = (uint32_t)l[6] | ((uint32_t)l[7] << 16);
                uint32_t off = (uint32_t)((arow * BPITCH + ahalf * 64 + gg * 8) * 2);
                *(uint4*)(Ah + off) = vh;
                *(uint4*)(Al + off) = vl;
            }
        }
        {
            const int p = b * NBK + k;
            uint4* Bh = (uint4*)(dsm + AGG_B0);
            uint4* Bl = (uint4*)(dsm + AGG_B1);
            const uint4* sh = (const uint4*)&g_kvb[p][0][0];
            const uint4* sl = (const uint4*)&g_kvb[p][1][0];
            for (int e = tid; e < (128 * BPITCH * 2) / 16; e += 256) {
                Bh[e] = sh[e];
                Bl[e] = sl[e];
            }
        }
        __syncthreads();
#pragma unroll 1
        for (int cc = 0; cc < 8; cc++) {
            uint32_t ah0, ah1, ah2, ah3, al0, al1, al2, al3;
            uint32_t aAddr = sb + AGG_A0 + aTerm + (uint32_t)(cc * 16 * 2);
            LDSM_X4(ah0, ah1, ah2, ah3, aAddr);
            LDSM_X4(al0, al1, al2, al3, aAddr + (AGG_A1 - AGG_A0));
            uint32_t bBase = sb + AGG_B0 + bTerm + (uint32_t)(cc * 16 * BPITCH * 2);
#pragma unroll
            for (int dblk = 0; dblk < 8; dblk++) {
                uint32_t bh0, bh1, bh2, bh3, bl0, bl1, bl2, bl3;
                uint32_t bAddr = bBase + (uint32_t)(dblk * 16 * 2);
                LDSM_X4T(bh0, bh1, bh2, bh3, bAddr);
                LDSM_X4T(bl0, bl1, bl2, bl3, bAddr + (AGG_B1 - AGG_B0));
                float* d0 = facc[dblk * 2];
                float* d1 = facc[dblk * 2 + 1];
                MMA_BF16(d0, ah0, ah1, ah2, ah3, bh0, bh1);
                MMA_BF16(d1, ah0, ah1, ah2, ah3, bh2, bh3);
                MMA_BF16(d0, al0, al1, al2, al3, bh0, bh1);
                MMA_BF16(d1, al0, al1, al2, al3, bh2, bh3);
                MMA_BF16(d0, ah0, ah1, ah2, ah3, bl0, bl1);
                MMA_BF16(d1, ah0, ah1, ah2, ah3, bl2, bl3);
            }
        }
    }
    const float inv = 1.0f / (float)NN;
    const int g = lane >> 2, t = lane & 3;
    size_t r0b = (size_t)(row0 + m0 + g) * CD;
#pragma unroll
    for (int dt = 0; dt < 16; dt++) {
        int col = dt * 8 + t * 2;
        *(float2*)&g_agg[r0b + col] = make_float2(facc[dt][0] * inv, facc[dt][1] * inv);
        *(float2*)&g_agg[r0b + 8 * CD + col] = make_float2(facc[dt][2] * inv, facc[dt][3] * inv);
    }
}

// ---------------- K5a: h = relu(agg @ Wm1^T + bm1) --------------------------
__global__ void __launch_bounds__(256) k_mlp1(const float* __restrict__ Wm1,
                                              const float* __restrict__ bm1) {
    __shared__ float As[32][68];
    __shared__ float Bs[32][68];
    const int row0 = blockIdx.y * 64;
    const int o0   = blockIdx.x * 64;
    const int tid = threadIdx.x;
    const int tx = tid & 15, ty = tid >> 4;
    u64 acc[4][2] = {};
    for (int c0 = 0; c0 < CD; c0 += 32) {
#pragma unroll
        for (int p = 0; p < 2; p++) {
            int r = tid >> 2, cq = tid & 3;
            size_t off = (size_t)(row0 + r) * CD + c0 + p * 16 + cq * 4;
            float4 a = ld4(&g_agg[off]);
            As[p*16 + cq*4 + 0][r] = a.x; As[p*16 + cq*4 + 1][r] = a.y;
            As[p*16 + cq*4 + 2][r] = a.z; As[p*16 + cq*4 + 3][r] = a.w;
        }
#pragma unroll
        for (int p = 0; p < 2; p++) {
            int j = (tid >> 3) + p * 32, cq = tid & 7;
            float4 w = ld4(&Wm1[(size_t)(o0 + j) * CD + c0 + cq * 4]);
            Bs[cq*4 + 0][j] = w.x; Bs[cq*4 + 1][j] = w.y;
            Bs[cq*4 + 2][j] = w.z; Bs[cq*4 + 3][j] = w.w;
        }
        __syncthreads();
#pragma unroll
        for (int kk = 0; kk < 32; kk++) {
            float4 a = ld4(&As[kk][ty * 4]);
            const u64* wp = (const u64*)&Bs[kk][tx * 4];
            u64 w0 = wp[0], w1 = wp[1];
            u64 s;
            s = splat2(a.x); fma2(acc[0][0], s, w0); fma2(acc[0][1], s, w1);
            s = splat2(a.y); fma2(acc[1][0], s, w0); fma2(acc[1][1], s, w1);
            s = splat2(a.z); fma2(acc[2][0], s, w0); fma2(acc[2][1], s, w1);
            s = splat2(a.w); fma2(acc[3][0], s, w0); fma2(acc[3][1], s, w1);
        }
        __syncthreads();
    }
    float4 bb = ld4(&bm1[o0 + tx * 4]);
#pragma unroll
    for (int i = 0; i < 4; i++) {
        float4 o; unp(acc[i][0], o.x, o.y); unp(acc[i][1], o.z, o.w);
        size_t ob = (size_t)(row0 + ty * 4 + i) * (4 * CD) + o0 + tx * 4;
        st4(&g_hid[ob], make_float4(fmaxf(o.x + bb.x, 0.f), fmaxf(o.y + bb.y, 0.f),
                                    fmaxf(o.z + bb.z, 0.f), fmaxf(o.w + bb.w, 0.f)));
    }
}

// ---------------- K5b: out = h @ Wm2^T + bm2 + x^T, transposed store --------
__global__ void __launch_bounds__(256) k_mlp2(const float* __restrict__ Wm2,
                                              const float* __restrict__ bm2,
                                              const float* __restrict__ x,
                                              float* __restrict__ out) {
    __shared__ float As[16][68];
    __shared__ float Bs[16][132];
    __shared__ float Csm[64][129];
    const int b  = blockIdx.y;
    const int n0 = blockIdx.x * 64;
    const int row0 = b * NN + n0;
    const int tid = threadIdx.x;
    const int tx = tid & 15, ty = tid >> 4;
    const int d0 = tx * 8, r0 = ty * 4;
    u64 acc[4][4] = {};
    for (int step = 0; step < 32; step++) {
        int o0 = step * 16;
        __syncthreads();
        {
            int r = tid >> 2, oq = tid & 3;
            float4 h = ld4(&g_hid[(size_t)(row0 + r) * (4 * CD) + o0 + oq * 4]);
            As[oq*4 + 0][r] = h.x; As[oq*4 + 1][r] = h.y;
            As[oq*4 + 2][r] = h.z; As[oq*4 + 3][r] = h.w;
        }
#pragma unroll
        for (int p = 0; p < 2; p++) {
            int d = (tid >> 2) + p * 64, oq = tid & 3;
            float4 w = ld4(&Wm2[(size_t)d * (4 * CD) + o0 + oq * 4]);
            Bs[oq*4 + 0][d] = w.x; Bs[oq*4 + 1][d] = w.y;
            Bs[oq*4 + 2][d] = w.z; Bs[oq*4 + 3][d] = w.w;
        }
        __syncthreads();
#pragma unroll
        for (int kk = 0; kk < 16; kk++) {
            float4 a = ld4(&As[kk][r0]);
            const u64* bp = (const u64*)&Bs[kk][d0];
            u64 b0 = bp[0], b1 = bp[1], b2 = bp[2], b3 = bp[3];
            u64 s;
            s = splat2(a.x); fma2(acc[0][0],s,b0); fma2(acc[0][1],s,b1); fma2(acc[0][2],s,b2); fma2(acc[0][3],s,b3);
            s = splat2(a.y); fma2(acc[1][0],s,b0); fma2(acc[1][1],s,b1); fma2(acc[1][2],s,b2); fma2(acc[1][3],s,b3);
            s = splat2(a.z); fma2(acc[2][0],s,b0); fma2(acc[2][1],s,b1); fma2(acc[2][2],s,b2); fma2(acc[2][3],s,b3);
            s = splat2(a.w); fma2(acc[3][0],s,b0); fma2(acc[3][1],s,b1); fma2(acc[3][2],s,b2); fma2(acc[3][3],s,b3);
        }
    }
    float4 b2a = ld4(&bm2[d0]);
    float4 b2b = ld4(&bm2[d0 + 4]);
    float bvv[8] = {b2a.x,b2a.y,b2a.z,b2a.w,b2b.x,b2b.y,b2b.z,b2b.w};
    __syncthreads();
#pragma unroll
    for (int i = 0; i < 4; i++) {
        float o[8];
        unp(acc[i][0], o[0], o[1]); unp(acc[i][1], o[2], o[3]);
        unp(acc[i][2], o[4], o[5]); unp(acc[i][3], o[6], o[7]);
#pragma unroll
        for (int j = 0; j < 8; j++) Csm[r0 + i][d0 + j] = o[j] + bvv[j];
    }
    __syncthreads();
    for (int v = tid; v < 64 * CD; v += 256) {
        int dd = v >> 6, nn = v & 63;
        size_t oa = ((size_t)b * CD + dd) * NN + n0 + nn;
        out[oa] = Csm[nn][dd] + x[oa];
    }
}

// ---------------- launcher ---------------------------------------------------
extern "C" void kernel_launch(void* const* d_in, const int* in_sizes, int n_in,
                              void* d_out, int out_size) {
    (void)in_sizes; (void)n_in; (void)out_size;
    const float* pos  = (const float*)d_in[0];
    const float* x    = (const float*)d_in[1];
    const void*  idx  = d_in[2];
    const float* dist = (const float*)d_in[3];
    const float* Wqkv = (const float*)d_in[4];
    const float* W1   = (const float*)d_in[5];
    const float* b1   = (const float*)d_in[6];
    const float* W2   = (const float*)d_in[7];
    const float* b2   = (const float*)d_in[8];
    const float* Wm1  = (const float*)d_in[9];
    const float* bm1  = (const float*)d_in[10];
    const float* Wm2  = (const float*)d_in[11];
    const float* bm2  = (const float*)d_in[12];
    float* out = (float*)d_out;

    cudaFuncSetAttribute(k_agg_mma, cudaFuncAttributeMaxDynamicSharedMemorySize, AGG_SMEM);
    cudaFuncSetAttribute(k_pe_mma,  cudaFuncAttributeMaxDynamicSharedMemorySize, PE_SMEM);

    k_detect <<<1, 256>>>((const unsigned int*)idx);
    k_qkv    <<<dim3(6, NN / 64, BB), 256>>>(x, Wqkv);
    k_invq   <<<ROWS / 8, 256>>>();
    k_w2split<<<2, 256>>>(W2);
    k_pe_mma <<<GROWS / 128, 256, PE_SMEM>>>(pos, idx, dist, W1, b1, b2);
    k_kv_mma <<<dim3(NSPLIT, PAIRS), 256>>>(idx);
    k_red    <<<(PAIRS * CD * CD) / (256 * 4), 256>>>();
    k_kvsplit<<<dim3(2, PAIRS), 256>>>();
    k_agg_mma<<<ROWS / 128, 256, AGG_SMEM>>>(idx);
    k_mlp1   <<<dim3(8, ROWS / 64), 256>>>(Wm1, bm1);
    k_mlp2   <<<dim3(NN / 64, BB), 256>>>(Wm2, bm2, x, out);
}

// round 13
// speedup vs baseline: 2.0175x; 1.1268x over previous
#include <cuda_runtime.h>
#include <cuda_bf16.h>
#include <cstdint>

#define BB  4
#define NN  4096
#define NBK 16
#define CD  128
#define HID 64
#define ROWS (BB*NN)            // 16384
#define GROWS (BB*NN*NBK)       // 262144
#define PAIRS (BB*NBK)          // 64
#define NSPLIT 8
#define BPITCH 136              // bf16 tile pitch (272 B rows)
#define APITCH 72               // hs tile pitch (144 B rows)

// ---------------- scratch (device globals; no allocation allowed) ----------
__device__ float g_qkv [ROWS*3*CD];                 // 25 MB
__device__ float g_invq[ROWS];
__device__ float g_pe  [(size_t)GROWS*CD];          // pos_emb, 134 MB
__device__ float g_kvp [NSPLIT][PAIRS*CD*CD];       // split partials 32 MB
__device__ unsigned short g_kvb[PAIRS][2][128*BPITCH]; // bf16 hi/lo kv images
__device__ unsigned short g_w2b[2][HID*BPITCH];     // bf16 hi/lo W2^T images
__device__ unsigned short g_wm1b[4][2][128*BPITCH]; // Wm1^T chunk images [c][o]
__device__ unsigned short g_wm2b[4][2][128*BPITCH]; // Wm2^T chunk images [o][d]
__device__ float g_agg [ROWS*CD];                   // 8 MB
__device__ int   g_idx64;

typedef unsigned long long u64;
__device__ __forceinline__ float4 ld4(const float* p) { return *(const float4*)p; }
__device__ __forceinline__ void   st4(float* p, float4 v) { *(float4*)p = v; }
__device__ __forceinline__ u64 splat2(float a) {
    u64 r; asm("mov.b64 %0, {%1, %1};" : "=l"(r) : "f"(a)); return r;
}
__device__ __forceinline__ u64 pack2(float lo, float hi) {
    u64 r; asm("mov.b64 %0, {%1, %2};" : "=l"(r) : "f"(lo), "f"(hi)); return r;
}
__device__ __forceinline__ void fma2(u64& d, u64 a, u64 b) {
    asm("fma.rn.f32x2 %0, %1, %2, %0;" : "+l"(d) : "l"(a), "l"(b));
}
__device__ __forceinline__ void unp(u64 v, float& lo, float& hi) {
    asm("mov.b64 {%0, %1}, %2;" : "=f"(lo), "=f"(hi) : "l"(v));
}
__device__ __forceinline__ int ld_idx(const void* p, size_t pos) {
    if (g_idx64) return (int)((const long long*)p)[pos];
    return ((const int*)p)[pos];
}
__device__ __forceinline__ uint32_t smem_u32(const void* p) {
    uint32_t a;
    asm("{ .reg .u64 t; cvta.to.shared.u64 t, %1; cvt.u32.u64 %0, t; }" : "=r"(a) : "l"(p));
    return a;
}
__device__ __forceinline__ void bf_split(float x, unsigned short& h, unsigned short& l) {
    __nv_bfloat16 bh = __float2bfloat16(x);
    h = __bfloat16_as_ushort(bh);
    l = __bfloat16_as_ushort(__float2bfloat16(x - __bfloat162float(bh)));
}

#define LDSM_X4(r0,r1,r2,r3, a) \
    asm volatile("ldmatrix.sync.aligned.m8n8.x4.shared.b16 {%0,%1,%2,%3}, [%4];" \
        : "=r"(r0),"=r"(r1),"=r"(r2),"=r"(r3) : "r"(a))
#define LDSM_X4T(r0,r1,r2,r3, a) \
    asm volatile("ldmatrix.sync.aligned.m8n8.x4.trans.shared.b16 {%0,%1,%2,%3}, [%4];" \
        : "=r"(r0),"=r"(r1),"=r"(r2),"=r"(r3) : "r"(a))
#define MMA_BF16(d, a0,a1,a2,a3, b0,b1) \
    asm volatile("mma.sync.aligned.m16n8k16.row.col.f32.bf16.bf16.f32 " \
        "{%0,%1,%2,%3}, {%4,%5,%6,%7}, {%8,%9}, {%0,%1,%2,%3};" \
        : "+f"((d)[0]),"+f"((d)[1]),"+f"((d)[2]),"+f"((d)[3]) \
        : "r"(a0),"r"(a1),"r"(a2),"r"(a3), "r"(b0),"r"(b1))

// ---------------- idx dtype autodetect -------------------------------------
__global__ void k_detect(const unsigned int* __restrict__ w) {
    __shared__ int any;
    if (threadIdx.x == 0) any = 0;
    __syncthreads();
    unsigned int v = w[1 + 2 * threadIdx.x];
    if (v != 0u) any = 1;
    __syncthreads();
    if (threadIdx.x == 0) g_idx64 = (any ? 0 : 1);
}

// ---------------- K1: qkv = x^T @ Wqkv^T ------------------------------------
__global__ void __launch_bounds__(256) k_qkv(const float* __restrict__ x,
                                             const float* __restrict__ Wqkv) {
    __shared__ float As[32][64];
    __shared__ float Bs[32][68];
    const int b  = blockIdx.z;
    const int n0 = blockIdx.y * 64;
    const int o0 = blockIdx.x * 64;
    const int tid = threadIdx.x;
    const int tx = tid & 15, ty = tid >> 4;
    u64 acc[4][2] = {};
    for (int c0 = 0; c0 < CD; c0 += 32) {
#pragma unroll
        for (int p = 0; p < 8; p++) {
            int v = tid + p * 256;
            int cc = v >> 6, i = v & 63;
            As[cc][i] = x[((size_t)b * CD + c0 + cc) * NN + n0 + i];
        }
#pragma unroll
        for (int p = 0; p < 8; p++) {
            int v = tid + p * 256;
            int cc = v & 31, j = v >> 5;
            Bs[cc][j] = Wqkv[(size_t)(o0 + j) * CD + c0 + cc];
        }
        __syncthreads();
#pragma unroll
        for (int kk = 0; kk < 32; kk++) {
            float4 a = ld4(&As[kk][ty * 4]);
            const u64* wp = (const u64*)&Bs[kk][tx * 4];
            u64 w0 = wp[0], w1 = wp[1];
            u64 s;
            s = splat2(a.x); fma2(acc[0][0], s, w0); fma2(acc[0][1], s, w1);
            s = splat2(a.y); fma2(acc[1][0], s, w0); fma2(acc[1][1], s, w1);
            s = splat2(a.z); fma2(acc[2][0], s, w0); fma2(acc[2][1], s, w1);
            s = splat2(a.w); fma2(acc[3][0], s, w0); fma2(acc[3][1], s, w1);
        }
        __syncthreads();
    }
#pragma unroll
    for (int i = 0; i < 4; i++) {
        float4 o; unp(acc[i][0], o.x, o.y); unp(acc[i][1], o.z, o.w);
        size_t ob = ((size_t)b * NN + n0 + ty * 4 + i) * (3 * CD) + o0 + tx * 4;
        st4(&g_qkv[ob], o);
    }
}

// ---------------- K1b: 1/||Q_row|| ------------------------------------------
__global__ void __launch_bounds__(256) k_invq() {
    int row  = blockIdx.x * 8 + (threadIdx.x >> 5);
    int lane = threadIdx.x & 31;
    float4 q = ld4(&g_qkv[(size_t)row * (3 * CD) + lane * 4]);
    float s = q.x * q.x + q.y * q.y + q.z * q.z + q.w * q.w;
#pragma unroll
    for (int o = 16; o; o >>= 1) s += __shfl_xor_sync(0xffffffffu, s, o);
    if (lane == 0) g_invq[row] = 1.0f / fmaxf(sqrtf(s), 1e-12f);
}

// ---------------- K1c: all weight bf16 hi/lo pre-splits ---------------------
// grid (2 variants, 9 targets): 0=W2^T, 1..4=Wm1^T chunks, 5..8=Wm2^T chunks
__global__ void __launch_bounds__(256) k_wsplit(const float* __restrict__ W2,
                                                const float* __restrict__ Wm1,
                                                const float* __restrict__ Wm2) {
    const int v = blockIdx.x;
    const int w = blockIdx.y;
    const int tid = threadIdx.x;
    if (w == 0) {
        for (int e = tid; e < CD * HID; e += 256) {
            int j = e >> 7, c = e & 127;
            float x = W2[(size_t)c * HID + j];
            __nv_bfloat16 bh = __float2bfloat16(x);
            unsigned short bits = v == 0 ? __bfloat16_as_ushort(bh)
                : __bfloat16_as_ushort(__float2bfloat16(x - __bfloat162float(bh)));
            g_w2b[v][j * BPITCH + c] = bits;
        }
    } else if (w <= 4) {
        const int oc = w - 1;
        for (int e = tid; e < CD * CD; e += 256) {
            int c = e >> 7, o = e & 127;
            float x = Wm1[(size_t)(oc * 128 + o) * CD + c];
            __nv_bfloat16 bh = __float2bfloat16(x);
            unsigned short bits = v == 0 ? __bfloat16_as_ushort(bh)
                : __bfloat16_as_ushort(__float2bfloat16(x - __bfloat162float(bh)));
            g_wm1b[oc][v][c * BPITCH + o] = bits;
        }
    } else {
        const int oc = w - 5;
        for (int e = tid; e < CD * CD; e += 256) {
            int ol = e >> 7, d = e & 127;
            float x = Wm2[(size_t)d * (4 * CD) + oc * 128 + ol];
            __nv_bfloat16 bh = __float2bfloat16(x);
            unsigned short bits = v == 0 ? __bfloat16_as_ushort(bh)
                : __bfloat16_as_ushort(__float2bfloat16(x - __bfloat162float(bh)));
            g_wm2b[oc][v][ol * BPITCH + d] = bits;
        }
    }
}

// ---------------- K2: pos-MLP via mma.sync -> g_pe --------------------------
#define PE_A0 0
#define PE_A1 (128*APITCH*2)
#define PE_B0 (2*128*APITCH*2)
#define PE_B1 (PE_B0 + HID*BPITCH*2)
#define PE_SMEM (PE_B1 + HID*BPITCH*2)

__global__ void __launch_bounds__(256, 2) k_pe_mma(
    const float* __restrict__ pos, const void* __restrict__ idx,
    const float* __restrict__ dist,
    const float* __restrict__ W1, const float* __restrict__ b1,
    const float* __restrict__ b2) {
    extern __shared__ __align__(16) unsigned char dsm[];
    __shared__ float W1s[HID * 10];
    __shared__ float b1s[HID];
    __shared__ float b2s[CD];
    __shared__ float feats[128][12];
    const uint32_t sb = smem_u32(dsm);
    const int tid = threadIdx.x;
    const int wid = tid >> 5, lane = tid & 31;
    const size_t g0 = (size_t)blockIdx.x * 128;
    const int m0 = wid * 16;

    for (int v = tid; v < HID * 10; v += 256) W1s[v] = W1[v];
    if (tid < HID) b1s[tid] = b1[tid];
    if (tid < CD)  b2s[tid] = b2[tid];
    if (tid < 128) {
        size_t g = g0 + tid;
        int b = (int)(g >> 16);
        int n = (int)((g >> 4) & (NN - 1));
        int j = ld_idx(idx, g);
        const float* pc = &pos[((size_t)b * NN + n) * 3];
        const float* pn = &pos[((size_t)b * NN + j) * 3];
        float a0 = pc[0], a1 = pc[1], a2 = pc[2];
        float q0 = pn[0], q1 = pn[1], q2 = pn[2];
        feats[tid][0] = a0;  feats[tid][1] = a1;  feats[tid][2] = a2;
        feats[tid][3] = q0;  feats[tid][4] = q1;  feats[tid][5] = q2;
        feats[tid][6] = a0 - q0; feats[tid][7] = a1 - q1; feats[tid][8] = a2 - q2;
        feats[tid][9] = dist[g];
    }
    {
        uint4* Bh = (uint4*)(dsm + PE_B0);
        uint4* Bl = (uint4*)(dsm + PE_B1);
        const uint4* sh = (const uint4*)&g_w2b[0][0];
        const uint4* sl = (const uint4*)&g_w2b[1][0];
        for (int e = tid; e < (HID * BPITCH * 2) / 16; e += 256) {
            Bh[e] = sh[e];
            Bl[e] = sl[e];
        }
    }
    __syncthreads();
    {
        unsigned short* Ah = (unsigned short*)(dsm + PE_A0);
        unsigned short* Al = (unsigned short*)(dsm + PE_A1);
#pragma unroll
        for (int p = 0; p < 32; p++) {
            int v = tid + p * 256;
            int j = v & 63, r = v >> 6;
            float s = b1s[j];
#pragma unroll
            for (int i = 0; i < 10; i++) s += feats[r][i] * W1s[j * 10 + i];
            s = fmaxf(s, 0.0f);
            unsigned short h, l;
            bf_split(s, h, l);
            Ah[r * APITCH + j] = h;
            Al[r * APITCH + j] = l;
        }
    }
    __syncthreads();
    const int rowSel = lane & 15;
    const int colSel = (lane >> 4) << 3;
    const uint32_t aTerm = (uint32_t)(((m0 + rowSel) * APITCH + colSel) * 2);
    const uint32_t bTerm = (uint32_t)((rowSel * BPITCH + colSel) * 2);
    float facc[16][4] = {};
#pragma unroll
    for (int cc = 0; cc < 4; cc++) {
        uint32_t ah0, ah1, ah2, ah3, al0, al1, al2, al3;
        uint32_t aAddr = sb + PE_A0 + aTerm + (uint32_t)(cc * 16 * 2);
        LDSM_X4(ah0, ah1, ah2, ah3, aAddr);
        LDSM_X4(al0, al1, al2, al3, aAddr + (PE_A1 - PE_A0));
        uint32_t bBase = sb + PE_B0 + bTerm + (uint32_t)(cc * 16 * BPITCH * 2);
#pragma unroll
        for (int dblk = 0; dblk < 8; dblk++) {
            uint32_t bh0, bh1, bh2, bh3, bl0, bl1, bl2, bl3;
            uint32_t bAddr = bBase + (uint32_t)(dblk * 16 * 2);
            LDSM_X4T(bh0, bh1, bh2, bh3, bAddr);
            LDSM_X4T(bl0, bl1, bl2, bl3, bAddr + (PE_B1 - PE_B0));
            float* d0 = facc[dblk * 2];
            float* d1 = facc[dblk * 2 + 1];
            MMA_BF16(d0, ah0, ah1, ah2, ah3, bh0, bh1);
            MMA_BF16(d1, ah0, ah1, ah2, ah3, bh2, bh3);
            MMA_BF16(d0, al0, al1, al2, al3, bh0, bh1);
            MMA_BF16(d1, al0, al1, al2, al3, bh2, bh3);
            MMA_BF16(d0, ah0, ah1, ah2, ah3, bl0, bl1);
            MMA_BF16(d1, ah0, ah1, ah2, ah3, bl2, bl3);
        }
    }
    const int g = lane >> 2, t = lane & 3;
    size_t r0b = (g0 + m0 + g) * CD;
#pragma unroll
    for (int dt = 0; dt < 16; dt++) {
        int col = dt * 8 + t * 2;
        float bx = b2s[col], by = b2s[col + 1];
        *(float2*)&g_pe[r0b + col] = make_float2(facc[dt][0] + bx, facc[dt][1] + by);
        *(float2*)&g_pe[r0b + 8 * CD + col] = make_float2(facc[dt][2] + bx, facc[dt][3] + by);
    }
}

// ---------------- K3: kv outer product via mma.sync bf16 hi/lo --------------
__global__ void __launch_bounds__(256, 2) k_kv_mma(const void* __restrict__ idx) {
    __shared__ unsigned short KnH[16 * BPITCH];
    __shared__ unsigned short KnL[16 * BPITCH];
    __shared__ unsigned short VrH[16 * BPITCH];
    __shared__ unsigned short VrL[16 * BPITCH];
    const int p = blockIdx.y;
    const int s = blockIdx.x;
    const int b = p >> 4, kslot = p & 15;
    const int tid = threadIdx.x;
    const int lane = tid & 31, warp = tid >> 5;
    const int c4 = lane * 4;
    const int m0 = warp * 16;

    const uint32_t knh = smem_u32(KnH), knl = smem_u32(KnL);
    const uint32_t vrh = smem_u32(VrH), vrl = smem_u32(VrL);
    const int rowSel = lane & 15;
    const int colSel = (lane >> 4) << 3;
    const uint32_t aTerm = (uint32_t)((rowSel * BPITCH + m0 + colSel) * 2);
    const uint32_t bTerm = (uint32_t)((rowSel * BPITCH + colSel) * 2);

    float facc[16][4] = {};

    const int n0 = s * (NN / NSPLIT);
    const int NSTEP = (NN / NSPLIT) / 16;
    for (int step = 0; step < NSTEP; step++) {
        const int nbase = n0 + step * 16;
        __syncthreads();
#pragma unroll
        for (int rr = 0; rr < 2; rr++) {
            int row = warp * 2 + rr;
            int n = nbase + row;
            size_t g = ((size_t)(b * NN + n)) * NBK + kslot;
            int j = ld_idx(idx, g);
            float4 pe = ld4(&g_pe[g * CD + c4]);
            const float* qrow = &g_qkv[((size_t)b * NN + j) * (3 * CD)];
            float4 kg = ld4(&qrow[CD + c4]);
            float4 vg = ld4(&qrow[2 * CD + c4]);
            float k0 = kg.x + pe.x, k1 = kg.y + pe.y, k2 = kg.z + pe.z, k3 = kg.w + pe.w;
            float v0 = fmaxf(vg.x + pe.x, 0.f), v1 = fmaxf(vg.y + pe.y, 0.f);
            float v2 = fmaxf(vg.z + pe.z, 0.f), v3 = fmaxf(vg.w + pe.w, 0.f);
            float ss = k0 * k0 + k1 * k1 + k2 * k2 + k3 * k3;
#pragma unroll
            for (int o = 16; o; o >>= 1) ss += __shfl_xor_sync(0xffffffffu, ss, o);
            float sc = 1.0f / fmaxf(sqrtf(ss), 1e-12f);
            k0 *= sc; k1 *= sc; k2 *= sc; k3 *= sc;
            unsigned short kh[4], kl[4], vh[4], vl[4];
            bf_split(k0, kh[0], kl[0]); bf_split(k1, kh[1], kl[1]);
            bf_split(k2, kh[2], kl[2]); bf_split(k3, kh[3], kl[3]);
            bf_split(v0, vh[0], vl[0]); bf_split(v1, vh[1], vl[1]);
            bf_split(v2, vh[2], vl[2]); bf_split(v3, vh[3], vl[3]);
            int off = row * BPITCH + c4;
            *(uint2*)&KnH[off] = make_uint2((uint32_t)kh[0] | ((uint32_t)kh[1] << 16),
                                            (uint32_t)kh[2] | ((uint32_t)kh[3] << 16));
            *(uint2*)&KnL[off] = make_uint2((uint32_t)kl[0] | ((uint32_t)kl[1] << 16),
                                            (uint32_t)kl[2] | ((uint32_t)kl[3] << 16));
            *(uint2*)&VrH[off] = make_uint2((uint32_t)vh[0] | ((uint32_t)vh[1] << 16),
                                            (uint32_t)vh[2] | ((uint32_t)vh[3] << 16));
            *(uint2*)&VrL[off] = make_uint2((uint32_t)vl[0] | ((uint32_t)vl[1] << 16),
                                            (uint32_t)vl[2] | ((uint32_t)vl[3] << 16));
        }
        __syncthreads();
        uint32_t t0, t1, t2, t3;
        uint32_t ah0, ah1, ah2, ah3, al0, al1, al2, al3;
        LDSM_X4T(t0, t1, t2, t3, knh + aTerm);
        ah0 = t0; ah1 = t2; ah2 = t1; ah3 = t3;
        LDSM_X4T(t0, t1, t2, t3, knl + aTerm);
        al0 = t0; al1 = t2; al2 = t1; al3 = t3;
#pragma unroll
        for (int dblk = 0; dblk < 8; dblk++) {
            uint32_t bh0, bh1, bh2, bh3, bl0, bl1, bl2, bl3;
            uint32_t bOff = bTerm + (uint32_t)(dblk * 16 * 2);
            LDSM_X4T(bh0, bh1, bh2, bh3, vrh + bOff);
            LDSM_X4T(bl0, bl1, bl2, bl3, vrl + bOff);
            float* d0 = facc[dblk * 2];
            float* d1 = facc[dblk * 2 + 1];
            MMA_BF16(d0, ah0, ah1, ah2, ah3, bh0, bh1);
            MMA_BF16(d1, ah0, ah1, ah2, ah3, bh2, bh3);
            MMA_BF16(d0, al0, al1, al2, al3, bh0, bh1);
            MMA_BF16(d1, al0, al1, al2, al3, bh2, bh3);
            MMA_BF16(d0, ah0, ah1, ah2, ah3, bl0, bl1);
            MMA_BF16(d1, ah0, ah1, ah2, ah3, bl2, bl3);
        }
    }
    float* op = &g_kvp[s][(size_t)p * CD * CD];
    const int g = lane >> 2, t = lane & 3;
#pragma unroll
    for (int dt = 0; dt < 16; dt++) {
        int col = dt * 8 + t * 2;
        *(float2*)&op[(size_t)(m0 + g) * CD + col]     = make_float2(facc[dt][0], facc[dt][1]);
        *(float2*)&op[(size_t)(m0 + 8 + g) * CD + col] = make_float2(facc[dt][2], facc[dt][3]);
    }
}

// ---------------- K3b: reduce partials + split to bf16 hi/lo images ---------
__global__ void __launch_bounds__(256) k_redsplit() {
    const int p = blockIdx.x;
    const int tid = threadIdx.x;
    for (int e = tid; e < CD * CD; e += 256) {
        int c = e >> 7, d = e & 127;
        float s = 0.0f;
#pragma unroll
        for (int t = 0; t < NSPLIT; t++) s += g_kvp[t][(size_t)p * CD * CD + e];
        unsigned short h, l;
        bf_split(s, h, l);
        g_kvb[p][0][c * BPITCH + d] = h;
        g_kvb[p][1][c * BPITCH + d] = l;
    }
}

// ---------------- K4: agg via mma.sync bf16 hi/lo ---------------------------
#define AGG_A0 0
#define AGG_A1 34816
#define AGG_B0 69632
#define AGG_B1 104448
#define AGG_SMEM 139264

__global__ void __launch_bounds__(256, 1) k_agg_mma(const void* __restrict__ idx) {
    extern __shared__ __align__(16) unsigned char dsm[];
    __shared__ int   jr[128];
    __shared__ float sc[128];
    const uint32_t sb = smem_u32(dsm);
    const int tid = threadIdx.x;
    const int wid = tid >> 5, lane = tid & 31;
    const int row0 = blockIdx.x * 128;
    const int b = row0 >> 12;
    const int m0 = wid * 16;

    const int rowSel = lane & 15;
    const int colSel = (lane >> 4) << 3;
    const uint32_t aTerm = (uint32_t)(((m0 + rowSel) * BPITCH + colSel) * 2);
    const uint32_t bTerm = (uint32_t)((rowSel * BPITCH + colSel) * 2);

    float facc[16][4] = {};

    const int arow = tid >> 1, ahalf = tid & 1;

    for (int k = 0; k < NBK; k++) {
        __syncthreads();
        if (tid < 128) {
            int j = ld_idx(idx, ((size_t)(row0 + tid)) * NBK + k);
            jr[tid] = j;
            sc[tid] = g_invq[b * NN + j];
        }
        __syncthreads();
        {
            int j = jr[arow];
            float s = sc[arow];
            const float* qrow = &g_qkv[((size_t)b * NN + j) * (3 * CD) + ahalf * 64];
            unsigned char* Ah = dsm + AGG_A0;
            unsigned char* Al = dsm + AGG_A1;
#pragma unroll
            for (int gg = 0; gg < 8; gg++) {
                float4 qa = ld4(qrow + gg * 8);
                float4 qb = ld4(qrow + gg * 8 + 4);
                float xs[8] = {qa.x*s, qa.y*s, qa.z*s, qa.w*s, qb.x*s, qb.y*s, qb.z*s, qb.w*s};
                unsigned short h[8], l[8];
#pragma unroll
                for (int q = 0; q < 8; q++) bf_split(xs[q], h[q], l[q]);
                uint4 vh, vl;
                vh.x = (uint32_t)h[0] | ((uint32_t)h[1] << 16);
                vh.y = (uint32_t)h[2] | ((uint32_t)h[3] << 16);
                vh.z = (uint32_t)h[4] | ((uint32_t)h[5] << 16);
                vh.w = (uint32_t)h[6] | ((uint32_t)h[7] << 16);
                vl.x = (uint32_t)l[0] | ((uint32_t)l[1] << 16);
                vl.y = (uint32_t)l[2] | ((uint32_t)l[3] << 16);
                vl.z = (uint32_t)l[4] | ((uint32_t)l[5] << 16);
                vl.w = (uint32_t)l[6] | ((uint32_t)l[7] << 16);
                uint32_t off = (uint32_t)((arow * BPITCH + ahalf * 64 + gg * 8) * 2);
                *(uint4*)(Ah + off) = vh;
                *(uint4*)(Al + off) = vl;
            }
        }
        {
            const int p = b * NBK + k;
            uint4* Bh = (uint4*)(dsm + AGG_B0);
            uint4* Bl = (uint4*)(dsm + AGG_B1);
            const uint4* sh = (const uint4*)&g_kvb[p][0][0];
            const uint4* sl = (const uint4*)&g_kvb[p][1][0];
            for (int e = tid; e < (128 * BPITCH * 2) / 16; e += 256) {
                Bh[e] = sh[e];
                Bl[e] = sl[e];
            }
        }
        __syncthreads();
#pragma unroll 1
        for (int cc = 0; cc < 8; cc++) {
            uint32_t ah0, ah1, ah2, ah3, al0, al1, al2, al3;
            uint32_t aAddr = sb + AGG_A0 + aTerm + (uint32_t)(cc * 16 * 2);
            LDSM_X4(ah0, ah1, ah2, ah3, aAddr);
            LDSM_X4(al0, al1, al2, al3, aAddr + (AGG_A1 - AGG_A0));
            uint32_t bBase = sb + AGG_B0 + bTerm + (uint32_t)(cc * 16 * BPITCH * 2);
#pragma unroll
            for (int dblk = 0; dblk < 8; dblk++) {
                uint32_t bh0, bh1, bh2, bh3, bl0, bl1, bl2, bl3;
                uint32_t bAddr = bBase + (uint32_t)(dblk * 16 * 2);
                LDSM_X4T(bh0, bh1, bh2, bh3, bAddr);
                LDSM_X4T(bl0, bl1, bl2, bl3, bAddr + (AGG_B1 - AGG_B0));
                float* d0 = facc[dblk * 2];
                float* d1 = facc[dblk * 2 + 1];
                MMA_BF16(d0, ah0, ah1, ah2, ah3, bh0, bh1);
                MMA_BF16(d1, ah0, ah1, ah2, ah3, bh2, bh3);
                MMA_BF16(d0, al0, al1, al2, al3, bh0, bh1);
                MMA_BF16(d1, al0, al1, al2, al3, bh2, bh3);
                MMA_BF16(d0, ah0, ah1, ah2, ah3, bl0, bl1);
                MMA_BF16(d1, ah0, ah1, ah2, ah3, bl2, bl3);
            }
        }
    }
    const float inv = 1.0f / (float)NN;
    const int g = lane >> 2, t = lane & 3;
    size_t r0b = (size_t)(row0 + m0 + g) * CD;
#pragma unroll
    for (int dt = 0; dt < 16; dt++) {
        int col = dt * 8 + t * 2;
        *(float2*)&g_agg[r0b + col] = make_float2(facc[dt][0] * inv, facc[dt][1] * inv);
        *(float2*)&g_agg[r0b + 8 * CD + col] = make_float2(facc[dt][2] * inv, facc[dt][3] * inv);
    }
}

// ---------------- K5: fused out MLP via mma.sync ----------------------------
// per block 128 rows; 4 o-chunks of 128: mlp1 GEMM -> relu/split h -> mlp2 GEMM
#define MLP_A0 0
#define MLP_A1 34816
#define MLP_B0 69632
#define MLP_B1 104448
#define MLP_H0 139264
#define MLP_H1 174080
#define MLP_SMEM 208896
#define EP 129

__global__ void __launch_bounds__(256, 1) k_mlp_mma(const float* __restrict__ bm1,
                                                    const float* __restrict__ bm2,
                                                    const float* __restrict__ x,
                                                    float* __restrict__ out) {
    extern __shared__ __align__(16) unsigned char dsm[];
    __shared__ float bm1s[4 * CD];
    __shared__ float bm2s[CD];
    const uint32_t sb = smem_u32(dsm);
    const int tid = threadIdx.x;
    const int wid = tid >> 5, lane = tid & 31;
    const int row0 = blockIdx.x * 128;
    const int b = row0 >> 12;
    const int n0 = row0 & (NN - 1);
    const int m0 = wid * 16;

    if (tid < CD) bm2s[tid] = bm2[tid];
    for (int v = tid; v < 4 * CD; v += 256) bm1s[v] = bm1[v];

    // stage A = agg rows, bf16 hi/lo
    {
        const int arow = tid >> 1, ahalf = tid & 1;
        const float* src = &g_agg[(size_t)(row0 + arow) * CD + ahalf * 64];
        unsigned char* Ah = dsm + MLP_A0;
        unsigned char* Al = dsm + MLP_A1;
#pragma unroll
        for (int gg = 0; gg < 8; gg++) {
            float4 qa = ld4(src + gg * 8);
            float4 qb = ld4(src + gg * 8 + 4);
            float xs[8] = {qa.x, qa.y, qa.z, qa.w, qb.x, qb.y, qb.z, qb.w};
            unsigned short h[8], l[8];
#pragma unroll
            for (int q = 0; q < 8; q++) bf_split(xs[q], h[q], l[q]);
            uint4 vh, vl;
            vh.x = (uint32_t)h[0] | ((uint32_t)h[1] << 16);
            vh.y = (uint32_t)h[2] | ((uint32_t)h[3] << 16);
            vh.z = (uint32_t)h[4] | ((uint32_t)h[5] << 16);
            vh.w = (uint32_t)h[6] | ((uint32_t)h[7] << 16);
            vl.x = (uint32_t)l[0] | ((uint32_t)l[1] << 16);
            vl.y = (uint32_t)l[2] | ((uint32_t)l[3] << 16);
            vl.z = (uint32_t)l[4] | ((uint32_t)l[5] << 16);
            vl.w = (uint32_t)l[6] | ((uint32_t)l[7] << 16);
            uint32_t off = (uint32_t)((arow * BPITCH + ahalf * 64 + gg * 8) * 2);
            *(uint4*)(Ah + off) = vh;
            *(uint4*)(Al + off) = vl;
        }
    }

    const int rowSel = lane & 15;
    const int colSel = (lane >> 4) << 3;
    const uint32_t aTerm = (uint32_t)(((m0 + rowSel) * BPITCH + colSel) * 2);
    const uint32_t bTerm = (uint32_t)((rowSel * BPITCH + colSel) * 2);
    const int g = lane >> 2, t = lane & 3;

    float facc2[16][4] = {};

    for (int oc = 0; oc < 4; oc++) {
        __syncthreads();   // A staging (oc=0) / prior chunk reads done
        {
            uint4* Bh = (uint4*)(dsm + MLP_B0);
            uint4* Bl = (uint4*)(dsm + MLP_B1);
            const uint4* sh = (const uint4*)&g_wm1b[oc][0][0];
            const uint4* sl = (const uint4*)&g_wm1b[oc][1][0];
            for (int e = tid; e < (128 * BPITCH * 2) / 16; e += 256) {
                Bh[e] = sh[e];
                Bl[e] = sl[e];
            }
        }
        __syncthreads();
        // mlp1 GEMM: h_chunk = A @ Wm1chunk^T
        float facc1[16][4] = {};
#pragma unroll 1
        for (int cc = 0; cc < 8; cc++) {
            uint32_t ah0, ah1, ah2, ah3, al0, al1, al2, al3;
            uint32_t aAddr = sb + MLP_A0 + aTerm + (uint32_t)(cc * 16 * 2);
            LDSM_X4(ah0, ah1, ah2, ah3, aAddr);
            LDSM_X4(al0, al1, al2, al3, aAddr + (MLP_A1 - MLP_A0));
            uint32_t bBase = sb + MLP_B0 + bTerm + (uint32_t)(cc * 16 * BPITCH * 2);
#pragma unroll
            for (int dblk = 0; dblk < 8; dblk++) {
                uint32_t bh0, bh1, bh2, bh3, bl0, bl1, bl2, bl3;
                uint32_t bAddr = bBase + (uint32_t)(dblk * 16 * 2);
                LDSM_X4T(bh0, bh1, bh2, bh3, bAddr);
                LDSM_X4T(bl0, bl1, bl2, bl3, bAddr + (MLP_B1 - MLP_B0));
                float* d0 = facc1[dblk * 2];
                float* d1 = facc1[dblk * 2 + 1];
                MMA_BF16(d0, ah0, ah1, ah2, ah3, bh0, bh1);
                MMA_BF16(d1, ah0, ah1, ah2, ah3, bh2, bh3);
                MMA_BF16(d0, al0, al1, al2, al3, bh0, bh1);
                MMA_BF16(d1, al0, al1, al2, al3, bh2, bh3);
                MMA_BF16(d0, ah0, ah1, ah2, ah3, bl0, bl1);
                MMA_BF16(d1, ah0, ah1, ah2, ah3, bl2, bl3);
            }
        }
        // bias + relu + split -> H tiles
        {
            unsigned short* Hh = (unsigned short*)(dsm + MLP_H0);
            unsigned short* Hl = (unsigned short*)(dsm + MLP_H1);
#pragma unroll
            for (int dt = 0; dt < 16; dt++) {
                int col = dt * 8 + t * 2;
                float bx = bm1s[oc * 128 + col], by = bm1s[oc * 128 + col + 1];
                float h0 = fmaxf(facc1[dt][0] + bx, 0.f);
                float h1 = fmaxf(facc1[dt][1] + by, 0.f);
                float h2 = fmaxf(facc1[dt][2] + bx, 0.f);
                float h3 = fmaxf(facc1[dt][3] + by, 0.f);
                unsigned short hh0, hl0, hh1, hl1, hh2, hl2, hh3, hl3;
                bf_split(h0, hh0, hl0); bf_split(h1, hh1, hl1);
                bf_split(h2, hh2, hl2); bf_split(h3, hh3, hl3);
                int r1 = m0 + g, r2 = m0 + 8 + g;
                *(uint32_t*)&Hh[r1 * BPITCH + col] = (uint32_t)hh0 | ((uint32_t)hh1 << 16);
                *(uint32_t*)&Hl[r1 * BPITCH + col] = (uint32_t)hl0 | ((uint32_t)hl1 << 16);
                *(uint32_t*)&Hh[r2 * BPITCH + col] = (uint32_t)hh2 | ((uint32_t)hh3 << 16);
                *(uint32_t*)&Hl[r2 * BPITCH + col] = (uint32_t)hl2 | ((uint32_t)hl3 << 16);
            }
        }
        __syncthreads();   // mlp1 B reads + H writes complete
        {
            uint4* Bh = (uint4*)(dsm + MLP_B0);
            uint4* Bl = (uint4*)(dsm + MLP_B1);
            const uint4* sh = (const uint4*)&g_wm2b[oc][0][0];
            const uint4* sl = (const uint4*)&g_wm2b[oc][1][0];
            for (int e = tid; e < (128 * BPITCH * 2) / 16; e += 256) {
                Bh[e] = sh[e];
                Bl[e] = sl[e];
            }
        }
        __syncthreads();
        // mlp2 GEMM: facc2 += H @ Wm2chunk^T
#pragma unroll 1
        for (int cc = 0; cc < 8; cc++) {
            uint32_t ah0, ah1, ah2, ah3, al0, al1, al2, al3;
            uint32_t aAddr = sb + MLP_H0 + aTerm + (uint32_t)(cc * 16 * 2);
            LDSM_X4(ah0, ah1, ah2, ah3, aAddr);
            LDSM_X4(al0, al1, al2, al3, aAddr + (MLP_H1 - MLP_H0));
            uint32_t bBase = sb + MLP_B0 + bTerm + (uint32_t)(cc * 16 * BPITCH * 2);
#pragma unroll
            for (int dblk = 0; dblk < 8; dblk++) {
                uint32_t bh0, bh1, bh2, bh3, bl0, bl1, bl2, bl3;
                uint32_t bAddr = bBase + (uint32_t)(dblk * 16 * 2);
                LDSM_X4T(bh0, bh1, bh2, bh3, bAddr);
                LDSM_X4T(bl0, bl1, bl2, bl3, bAddr + (MLP_B1 - MLP_B0));
                float* d0 = facc2[dblk * 2];
                float* d1 = facc2[dblk * 2 + 1];
                MMA_BF16(d0, ah0, ah1, ah2, ah3, bh0, bh1);
                MMA_BF16(d1, ah0, ah1, ah2, ah3, bh2, bh3);
                MMA_BF16(d0, al0, al1, al2, al3, bh0, bh1);
                MMA_BF16(d1, al0, al1, al2, al3, bh2, bh3);
                MMA_BF16(d0, ah0, ah1, ah2, ah3, bl0, bl1);
                MMA_BF16(d1, ah0, ah1, ah2, ah3, bl2, bl3);
            }
        }
    }
    // epilogue: + bm2, stage to fp32 (reuse A region), transposed store + x
    __syncthreads();
    {
        float* Cst = (float*)(dsm + MLP_A0);
#pragma unroll
        for (int dt = 0; dt < 16; dt++) {
            int col = dt * 8 + t * 2;
            float bx = bm2s[col], by = bm2s[col + 1];
            int r1 = m0 + g, r2 = m0 + 8 + g;
            Cst[r1 * EP + col]     = facc2[dt][0] + bx;
            Cst[r1 * EP + col + 1] = facc2[dt][1] + by;
            Cst[r2 * EP + col]     = facc2[dt][2] + bx;
            Cst[r2 * EP + col + 1] = facc2[dt][3] + by;
        }
    }
    __syncthreads();
    {
        const float* Cst = (const float*)(dsm + MLP_A0);
        for (int v = tid; v < 128 * CD; v += 256) {
            int dd = v >> 7, nn = v & 127;
            size_t oa = ((size_t)b * CD + dd) * NN + n0 + nn;
            out[oa] = Cst[nn * EP + dd] + x[oa];
        }
    }
}

// ---------------- launcher ---------------------------------------------------
extern "C" void kernel_launch(void* const* d_in, const int* in_sizes, int n_in,
                              void* d_out, int out_size) {
    (void)in_sizes; (void)n_in; (void)out_size;
    const float* pos  = (const float*)d_in[0];
    const float* x    = (const float*)d_in[1];
    const void*  idx  = d_in[2];
    const float* dist = (const float*)d_in[3];
    const float* Wqkv = (const float*)d_in[4];
    const float* W1   = (const float*)d_in[5];
    const float* b1   = (const float*)d_in[6];
    const float* W2   = (const float*)d_in[7];
    const float* b2   = (const float*)d_in[8];
    const float* Wm1  = (const float*)d_in[9];
    const float* bm1  = (const float*)d_in[10];
    const float* Wm2  = (const float*)d_in[11];
    const float* bm2  = (const float*)d_in[12];
    float* out = (float*)d_out;

    cudaFuncSetAttribute(k_agg_mma, cudaFuncAttributeMaxDynamicSharedMemorySize, AGG_SMEM);
    cudaFuncSetAttribute(k_pe_mma,  cudaFuncAttributeMaxDynamicSharedMemorySize, PE_SMEM);
    cudaFuncSetAttribute(k_mlp_mma, cudaFuncAttributeMaxDynamicSharedMemorySize, MLP_SMEM);

    k_detect  <<<1, 256>>>((const unsigned int*)idx);
    k_qkv     <<<dim3(6, NN / 64, BB), 256>>>(x, Wqkv);
    k_invq    <<<ROWS / 8, 256>>>();
    k_wsplit  <<<dim3(2, 9), 256>>>(W2, Wm1, Wm2);
    k_pe_mma  <<<GROWS / 128, 256, PE_SMEM>>>(pos, idx, dist, W1, b1, b2);
    k_kv_mma  <<<dim3(NSPLIT, PAIRS), 256>>>(idx);
    k_redsplit<<<PAIRS, 256>>>();
    k_agg_mma <<<ROWS / 128, 256, AGG_SMEM>>>(idx);
    k_mlp_mma <<<ROWS / 128, 256, MLP_SMEM>>>(bm1, bm2, x, out);
}

// round 14
// speedup vs baseline: 2.2297x; 1.1052x over previous
#include <cuda_runtime.h>
#include <cuda_bf16.h>
#include <cstdint>

#define BB  4
#define NN  4096
#define NBK 16
#define CD  128
#define HID 64
#define ROWS (BB*NN)            // 16384
#define GROWS (BB*NN*NBK)       // 262144
#define PAIRS (BB*NBK)          // 64
#define NSPLIT 8
#define BPITCH 136              // bf16 tile pitch (272 B rows)
#define APITCH 72               // hs tile pitch (144 B rows)

// ---------------- scratch (device globals; no allocation allowed) ----------
__device__ float g_qkv [ROWS*3*CD];                 // 25 MB
__device__ unsigned short g_qb[ROWS][2][CD];        // prescaled Qn bf16 hi/lo, 8.4 MB
__device__ float g_pe  [(size_t)GROWS*CD];          // pos_emb, 134 MB
__device__ float g_kvp [NSPLIT][PAIRS*CD*CD];       // split partials 32 MB
__device__ unsigned short g_kvb[PAIRS][2][128*BPITCH]; // bf16 hi/lo kv images
__device__ unsigned short g_w2b[2][HID*BPITCH];     // bf16 hi/lo W2^T images
__device__ unsigned short g_wm1b[4][2][128*BPITCH]; // Wm1^T chunk images [c][o]
__device__ unsigned short g_wm2b[4][2][128*BPITCH]; // Wm2^T chunk images [o][d]
__device__ float g_agg [ROWS*CD];                   // 8 MB
__device__ int   g_idx64;

typedef unsigned long long u64;
__device__ __forceinline__ float4 ld4(const float* p) { return *(const float4*)p; }
__device__ __forceinline__ void   st4(float* p, float4 v) { *(float4*)p = v; }
__device__ __forceinline__ u64 splat2(float a) {
    u64 r; asm("mov.b64 %0, {%1, %1};" : "=l"(r) : "f"(a)); return r;
}
__device__ __forceinline__ u64 pack2(float lo, float hi) {
    u64 r; asm("mov.b64 %0, {%1, %2};" : "=l"(r) : "f"(lo), "f"(hi)); return r;
}
__device__ __forceinline__ void fma2(u64& d, u64 a, u64 b) {
    asm("fma.rn.f32x2 %0, %1, %2, %0;" : "+l"(d) : "l"(a), "l"(b));
}
__device__ __forceinline__ void unp(u64 v, float& lo, float& hi) {
    asm("mov.b64 {%0, %1}, %2;" : "=f"(lo), "=f"(hi) : "l"(v));
}
__device__ __forceinline__ int ld_idx(const void* p, size_t pos) {
    if (g_idx64) return (int)((const long long*)p)[pos];
    return ((const int*)p)[pos];
}
__device__ __forceinline__ uint32_t smem_u32(const void* p) {
    uint32_t a;
    asm("{ .reg .u64 t; cvta.to.shared.u64 t, %1; cvt.u32.u64 %0, t; }" : "=r"(a) : "l"(p));
    return a;
}
__device__ __forceinline__ void bf_split(float x, unsigned short& h, unsigned short& l) {
    __nv_bfloat16 bh = __float2bfloat16(x);
    h = __bfloat16_as_ushort(bh);
    l = __bfloat16_as_ushort(__float2bfloat16(x - __bfloat162float(bh)));
}

#define LDSM_X4(r0,r1,r2,r3, a) \
    asm volatile("ldmatrix.sync.aligned.m8n8.x4.shared.b16 {%0,%1,%2,%3}, [%4];" \
        : "=r"(r0),"=r"(r1),"=r"(r2),"=r"(r3) : "r"(a))
#define LDSM_X4T(r0,r1,r2,r3, a) \
    asm volatile("ldmatrix.sync.aligned.m8n8.x4.trans.shared.b16 {%0,%1,%2,%3}, [%4];" \
        : "=r"(r0),"=r"(r1),"=r"(r2),"=r"(r3) : "r"(a))
#define MMA_BF16(d, a0,a1,a2,a3, b0,b1) \
    asm volatile("mma.sync.aligned.m16n8k16.row.col.f32.bf16.bf16.f32 " \
        "{%0,%1,%2,%3}, {%4,%5,%6,%7}, {%8,%9}, {%0,%1,%2,%3};" \
        : "+f"((d)[0]),"+f"((d)[1]),"+f"((d)[2]),"+f"((d)[3]) \
        : "r"(a0),"r"(a1),"r"(a2),"r"(a3), "r"(b0),"r"(b1))

// ---------------- idx dtype autodetect -------------------------------------
__global__ void k_detect(const unsigned int* __restrict__ w) {
    __shared__ int any;
    if (threadIdx.x == 0) any = 0;
    __syncthreads();
    unsigned int v = w[1 + 2 * threadIdx.x];
    if (v != 0u) any = 1;
    __syncthreads();
    if (threadIdx.x == 0) g_idx64 = (any ? 0 : 1);
}

// ---------------- K1: qkv = x^T @ Wqkv^T ------------------------------------
__global__ void __launch_bounds__(256) k_qkv(const float* __restrict__ x,
                                             const float* __restrict__ Wqkv) {
    __shared__ float As[32][64];
    __shared__ float Bs[32][68];
    const int b  = blockIdx.z;
    const int n0 = blockIdx.y * 64;
    const int o0 = blockIdx.x * 64;
    const int tid = threadIdx.x;
    const int tx = tid & 15, ty = tid >> 4;
    u64 acc[4][2] = {};
    for (int c0 = 0; c0 < CD; c0 += 32) {
#pragma unroll
        for (int p = 0; p < 8; p++) {
            int v = tid + p * 256;
            int cc = v >> 6, i = v & 63;
            As[cc][i] = x[((size_t)b * CD + c0 + cc) * NN + n0 + i];
        }
#pragma unroll
        for (int p = 0; p < 8; p++) {
            int v = tid + p * 256;
            int cc = v & 31, j = v >> 5;
            Bs[cc][j] = Wqkv[(size_t)(o0 + j) * CD + c0 + cc];
        }
        __syncthreads();
#pragma unroll
        for (int kk = 0; kk < 32; kk++) {
            float4 a = ld4(&As[kk][ty * 4]);
            const u64* wp = (const u64*)&Bs[kk][tx * 4];
            u64 w0 = wp[0], w1 = wp[1];
            u64 s;
            s = splat2(a.x); fma2(acc[0][0], s, w0); fma2(acc[0][1], s, w1);
            s = splat2(a.y); fma2(acc[1][0], s, w0); fma2(acc[1][1], s, w1);
            s = splat2(a.z); fma2(acc[2][0], s, w0); fma2(acc[2][1], s, w1);
            s = splat2(a.w); fma2(acc[3][0], s, w0); fma2(acc[3][1], s, w1);
        }
        __syncthreads();
    }
#pragma unroll
    for (int i = 0; i < 4; i++) {
        float4 o; unp(acc[i][0], o.x, o.y); unp(acc[i][1], o.z, o.w);
        size_t ob = ((size_t)b * NN + n0 + ty * 4 + i) * (3 * CD) + o0 + tx * 4;
        st4(&g_qkv[ob], o);
    }
}

// ---------------- K1b: Qn = Q/||Q|| -> bf16 hi/lo images --------------------
__global__ void __launch_bounds__(256) k_qsplit() {
    int row  = blockIdx.x * 8 + (threadIdx.x >> 5);
    int lane = threadIdx.x & 31;
    float4 q = ld4(&g_qkv[(size_t)row * (3 * CD) + lane * 4]);
    float s = q.x * q.x + q.y * q.y + q.z * q.z + q.w * q.w;
#pragma unroll
    for (int o = 16; o; o >>= 1) s += __shfl_xor_sync(0xffffffffu, s, o);
    float sc = 1.0f / fmaxf(sqrtf(s), 1e-12f);
    float xs[4] = {q.x * sc, q.y * sc, q.z * sc, q.w * sc};
    unsigned short h[4], l[4];
#pragma unroll
    for (int i = 0; i < 4; i++) bf_split(xs[i], h[i], l[i]);
    uint2 vh = make_uint2((uint32_t)h[0] | ((uint32_t)h[1] << 16),
                          (uint32_t)h[2] | ((uint32_t)h[3] << 16));
    uint2 vl = make_uint2((uint32_t)l[0] | ((uint32_t)l[1] << 16),
                          (uint32_t)l[2] | ((uint32_t)l[3] << 16));
    *(uint2*)&g_qb[row][0][lane * 4] = vh;
    *(uint2*)&g_qb[row][1][lane * 4] = vl;
}

// ---------------- K1c: weight bf16 hi/lo pre-splits (4-way z-split) ---------
__global__ void __launch_bounds__(256) k_wsplit(const float* __restrict__ W2,
                                                const float* __restrict__ Wm1,
                                                const float* __restrict__ Wm2) {
    const int v = blockIdx.x;
    const int w = blockIdx.y;
    const int tid = (int)(blockIdx.z * 256 + threadIdx.x);
    const int stride = 1024;
    if (w == 0) {
        for (int e = tid; e < CD * HID; e += stride) {
            int j = e >> 7, c = e & 127;
            float x = W2[(size_t)c * HID + j];
            __nv_bfloat16 bh = __float2bfloat16(x);
            unsigned short bits = v == 0 ? __bfloat16_as_ushort(bh)
                : __bfloat16_as_ushort(__float2bfloat16(x - __bfloat162float(bh)));
            g_w2b[v][j * BPITCH + c] = bits;
        }
    } else if (w <= 4) {
        const int oc = w - 1;
        for (int e = tid; e < CD * CD; e += stride) {
            int c = e >> 7, o = e & 127;
            float x = Wm1[(size_t)(oc * 128 + o) * CD + c];
            __nv_bfloat16 bh = __float2bfloat16(x);
            unsigned short bits = v == 0 ? __bfloat16_as_ushort(bh)
                : __bfloat16_as_ushort(__float2bfloat16(x - __bfloat162float(bh)));
            g_wm1b[oc][v][c * BPITCH + o] = bits;
        }
    } else {
        const int oc = w - 5;
        for (int e = tid; e < CD * CD; e += stride) {
            int ol = e >> 7, d = e & 127;
            float x = Wm2[(size_t)d * (4 * CD) + oc * 128 + ol];
            __nv_bfloat16 bh = __float2bfloat16(x);
            unsigned short bits = v == 0 ? __bfloat16_as_ushort(bh)
                : __bfloat16_as_ushort(__float2bfloat16(x - __bfloat162float(bh)));
            g_wm2b[oc][v][ol * BPITCH + d] = bits;
        }
    }
}

// ---------------- K2: pos-MLP via mma.sync -> g_pe --------------------------
#define PE_A0 0
#define PE_A1 (128*APITCH*2)
#define PE_B0 (2*128*APITCH*2)
#define PE_B1 (PE_B0 + HID*BPITCH*2)
#define PE_SMEM (PE_B1 + HID*BPITCH*2)

__global__ void __launch_bounds__(256, 2) k_pe_mma(
    const float* __restrict__ pos, const void* __restrict__ idx,
    const float* __restrict__ dist,
    const float* __restrict__ W1, const float* __restrict__ b1,
    const float* __restrict__ b2) {
    extern __shared__ __align__(16) unsigned char dsm[];
    __shared__ float W1s[HID * 10];
    __shared__ float b1s[HID];
    __shared__ float b2s[CD];
    __shared__ float feats[128][12];
    const uint32_t sb = smem_u32(dsm);
    const int tid = threadIdx.x;
    const int wid = tid >> 5, lane = tid & 31;
    const size_t g0 = (size_t)blockIdx.x * 128;
    const int m0 = wid * 16;

    for (int v = tid; v < HID * 10; v += 256) W1s[v] = W1[v];
    if (tid < HID) b1s[tid] = b1[tid];
    if (tid < CD)  b2s[tid] = b2[tid];
    if (tid < 128) {
        size_t g = g0 + tid;
        int b = (int)(g >> 16);
        int n = (int)((g >> 4) & (NN - 1));
        int j = ld_idx(idx, g);
        const float* pc = &pos[((size_t)b * NN + n) * 3];
        const float* pn = &pos[((size_t)b * NN + j) * 3];
        float a0 = pc[0], a1 = pc[1], a2 = pc[2];
        float q0 = pn[0], q1 = pn[1], q2 = pn[2];
        feats[tid][0] = a0;  feats[tid][1] = a1;  feats[tid][2] = a2;
        feats[tid][3] = q0;  feats[tid][4] = q1;  feats[tid][5] = q2;
        feats[tid][6] = a0 - q0; feats[tid][7] = a1 - q1; feats[tid][8] = a2 - q2;
        feats[tid][9] = dist[g];
    }
    {
        uint4* Bh = (uint4*)(dsm + PE_B0);
        uint4* Bl = (uint4*)(dsm + PE_B1);
        const uint4* sh = (const uint4*)&g_w2b[0][0];
        const uint4* sl = (const uint4*)&g_w2b[1][0];
        for (int e = tid; e < (HID * BPITCH * 2) / 16; e += 256) {
            Bh[e] = sh[e];
            Bl[e] = sl[e];
        }
    }
    __syncthreads();
    {
        unsigned short* Ah = (unsigned short*)(dsm + PE_A0);
        unsigned short* Al = (unsigned short*)(dsm + PE_A1);
#pragma unroll
        for (int p = 0; p < 32; p++) {
            int v = tid + p * 256;
            int j = v & 63, r = v >> 6;
            float s = b1s[j];
#pragma unroll
            for (int i = 0; i < 10; i++) s += feats[r][i] * W1s[j * 10 + i];
            s = fmaxf(s, 0.0f);
            unsigned short h, l;
            bf_split(s, h, l);
            Ah[r * APITCH + j] = h;
            Al[r * APITCH + j] = l;
        }
    }
    __syncthreads();
    const int rowSel = lane & 15;
    const int colSel = (lane >> 4) << 3;
    const uint32_t aTerm = (uint32_t)(((m0 + rowSel) * APITCH + colSel) * 2);
    const uint32_t bTerm = (uint32_t)((rowSel * BPITCH + colSel) * 2);
    float facc[16][4] = {};
#pragma unroll
    for (int cc = 0; cc < 4; cc++) {
        uint32_t ah0, ah1, ah2, ah3, al0, al1, al2, al3;
        uint32_t aAddr = sb + PE_A0 + aTerm + (uint32_t)(cc * 16 * 2);
        LDSM_X4(ah0, ah1, ah2, ah3, aAddr);
        LDSM_X4(al0, al1, al2, al3, aAddr + (PE_A1 - PE_A0));
        uint32_t bBase = sb + PE_B0 + bTerm + (uint32_t)(cc * 16 * BPITCH * 2);
#pragma unroll
        for (int dblk = 0; dblk < 8; dblk++) {
            uint32_t bh0, bh1, bh2, bh3, bl0, bl1, bl2, bl3;
            uint32_t bAddr = bBase + (uint32_t)(dblk * 16 * 2);
            LDSM_X4T(bh0, bh1, bh2, bh3, bAddr);
            LDSM_X4T(bl0, bl1, bl2, bl3, bAddr + (PE_B1 - PE_B0));
            float* d0 = facc[dblk * 2];
            float* d1 = facc[dblk * 2 + 1];
            MMA_BF16(d0, ah0, ah1, ah2, ah3, bh0, bh1);
            MMA_BF16(d1, ah0, ah1, ah2, ah3, bh2, bh3);
            MMA_BF16(d0, al0, al1, al2, al3, bh0, bh1);
            MMA_BF16(d1, al0, al1, al2, al3, bh2, bh3);
            MMA_BF16(d0, ah0, ah1, ah2, ah3, bl0, bl1);
            MMA_BF16(d1, ah0, ah1, ah2, ah3, bl2, bl3);
        }
    }
    const int g = lane >> 2, t = lane & 3;
    size_t r0b = (g0 + m0 + g) * CD;
#pragma unroll
    for (int dt = 0; dt < 16; dt++) {
        int col = dt * 8 + t * 2;
        float bx = b2s[col], by = b2s[col + 1];
        *(float2*)&g_pe[r0b + col] = make_float2(facc[dt][0] + bx, facc[dt][1] + by);
        *(float2*)&g_pe[r0b + 8 * CD + col] = make_float2(facc[dt][2] + bx, facc[dt][3] + by);
    }
}

// ---------------- K3: kv outer product via mma.sync (32-row steps) ----------
__global__ void __launch_bounds__(256, 2) k_kv_mma(const void* __restrict__ idx) {
    __shared__ unsigned short KnH[32 * BPITCH];
    __shared__ unsigned short KnL[32 * BPITCH];
    __shared__ unsigned short VrH[32 * BPITCH];
    __shared__ unsigned short VrL[32 * BPITCH];
    const int p = blockIdx.y;
    const int s = blockIdx.x;
    const int b = p >> 4, kslot = p & 15;
    const int tid = threadIdx.x;
    const int lane = tid & 31, warp = tid >> 5;
    const int c4 = lane * 4;
    const int m0 = warp * 16;

    const uint32_t knh = smem_u32(KnH), knl = smem_u32(KnL);
    const uint32_t vrh = smem_u32(VrH), vrl = smem_u32(VrL);
    const int rowSel = lane & 15;
    const int colSel = (lane >> 4) << 3;
    const uint32_t aTerm = (uint32_t)((rowSel * BPITCH + m0 + colSel) * 2);
    const uint32_t bTerm = (uint32_t)((rowSel * BPITCH + colSel) * 2);

    float facc[16][4] = {};

    const int n0 = s * (NN / NSPLIT);
    const int NSTEP = (NN / NSPLIT) / 32;
    for (int step = 0; step < NSTEP; step++) {
        const int nbase = n0 + step * 32;
        __syncthreads();
#pragma unroll
        for (int rr = 0; rr < 4; rr++) {
            int row = warp * 4 + rr;
            int n = nbase + row;
            size_t g = ((size_t)(b * NN + n)) * NBK + kslot;
            int j = ld_idx(idx, g);
            float4 pe = ld4(&g_pe[g * CD + c4]);
            const float* qrow = &g_qkv[((size_t)b * NN + j) * (3 * CD)];
            float4 kg = ld4(&qrow[CD + c4]);
            float4 vg = ld4(&qrow[2 * CD + c4]);
            float k0 = kg.x + pe.x, k1 = kg.y + pe.y, k2 = kg.z + pe.z, k3 = kg.w + pe.w;
            float v0 = fmaxf(vg.x + pe.x, 0.f), v1 = fmaxf(vg.y + pe.y, 0.f);
            float v2 = fmaxf(vg.z + pe.z, 0.f), v3 = fmaxf(vg.w + pe.w, 0.f);
            float ss = k0 * k0 + k1 * k1 + k2 * k2 + k3 * k3;
#pragma unroll
            for (int o = 16; o; o >>= 1) ss += __shfl_xor_sync(0xffffffffu, ss, o);
            float sc = 1.0f / fmaxf(sqrtf(ss), 1e-12f);
            k0 *= sc; k1 *= sc; k2 *= sc; k3 *= sc;
            unsigned short kh[4], kl[4], vh[4], vl[4];
            bf_split(k0, kh[0], kl[0]); bf_split(k1, kh[1], kl[1]);
            bf_split(k2, kh[2], kl[2]); bf_split(k3, kh[3], kl[3]);
            bf_split(v0, vh[0], vl[0]); bf_split(v1, vh[1], vl[1]);
            bf_split(v2, vh[2], vl[2]); bf_split(v3, vh[3], vl[3]);
            int off = row * BPITCH + c4;
            *(uint2*)&KnH[off] = make_uint2((uint32_t)kh[0] | ((uint32_t)kh[1] << 16),
                                            (uint32_t)kh[2] | ((uint32_t)kh[3] << 16));
            *(uint2*)&KnL[off] = make_uint2((uint32_t)kl[0] | ((uint32_t)kl[1] << 16),
                                            (uint32_t)kl[2] | ((uint32_t)kl[3] << 16));
            *(uint2*)&VrH[off] = make_uint2((uint32_t)vh[0] | ((uint32_t)vh[1] << 16),
                                            (uint32_t)vh[2] | ((uint32_t)vh[3] << 16));
            *(uint2*)&VrL[off] = make_uint2((uint32_t)vl[0] | ((uint32_t)vl[1] << 16),
                                            (uint32_t)vl[2] | ((uint32_t)vl[3] << 16));
        }
        __syncthreads();
#pragma unroll
        for (int cc = 0; cc < 2; cc++) {
            const uint32_t cOff = (uint32_t)(cc * 16 * BPITCH * 2);
            uint32_t t0, t1, t2, t3;
            uint32_t ah0, ah1, ah2, ah3, al0, al1, al2, al3;
            LDSM_X4T(t0, t1, t2, t3, knh + aTerm + cOff);
            ah0 = t0; ah1 = t2; ah2 = t1; ah3 = t3;
            LDSM_X4T(t0, t1, t2, t3, knl + aTerm + cOff);
            al0 = t0; al1 = t2; al2 = t1; al3 = t3;
#pragma unroll
            for (int dblk = 0; dblk < 8; dblk++) {
                uint32_t bh0, bh1, bh2, bh3, bl0, bl1, bl2, bl3;
                uint32_t bOff = bTerm + cOff + (uint32_t)(dblk * 16 * 2);
                LDSM_X4T(bh0, bh1, bh2, bh3, vrh + bOff);
                LDSM_X4T(bl0, bl1, bl2, bl3, vrl + bOff);
                float* d0 = facc[dblk * 2];
                float* d1 = facc[dblk * 2 + 1];
                MMA_BF16(d0, ah0, ah1, ah2, ah3, bh0, bh1);
                MMA_BF16(d1, ah0, ah1, ah2, ah3, bh2, bh3);
                MMA_BF16(d0, al0, al1, al2, al3, bh0, bh1);
                MMA_BF16(d1, al0, al1, al2, al3, bh2, bh3);
                MMA_BF16(d0, ah0, ah1, ah2, ah3, bl0, bl1);
                MMA_BF16(d1, ah0, ah1, ah2, ah3, bl2, bl3);
            }
        }
    }
    float* op = &g_kvp[s][(size_t)p * CD * CD];
    const int g = lane >> 2, t = lane & 3;
#pragma unroll
    for (int dt = 0; dt < 16; dt++) {
        int col = dt * 8 + t * 2;
        *(float2*)&op[(size_t)(m0 + g) * CD + col]     = make_float2(facc[dt][0], facc[dt][1]);
        *(float2*)&op[(size_t)(m0 + 8 + g) * CD + col] = make_float2(facc[dt][2], facc[dt][3]);
    }
}

// ---------------- K3b: reduce partials + split to bf16 hi/lo (4-way) --------
__global__ void __launch_bounds__(256) k_redsplit() {
    const int p = blockIdx.x;
    const int e0 = (int)blockIdx.y * 4096;
    const int tid = threadIdx.x;
    for (int e = e0 + tid; e < e0 + 4096; e += 256) {
        int c = e >> 7, d = e & 127;
        float s = 0.0f;
#pragma unroll
        for (int t = 0; t < NSPLIT; t++) s += g_kvp[t][(size_t)p * CD * CD + e];
        unsigned short h, l;
        bf_split(s, h, l);
        g_kvb[p][0][c * BPITCH + d] = h;
        g_kvb[p][1][c * BPITCH + d] = l;
    }
}

// ---------------- K4: agg via mma.sync (A from presplit g_qb) ---------------
#define AGG_A0 0
#define AGG_A1 34816
#define AGG_B0 69632
#define AGG_B1 104448
#define AGG_SMEM 139264

__global__ void __launch_bounds__(256, 1) k_agg_mma(const void* __restrict__ idx) {
    extern __shared__ __align__(16) unsigned char dsm[];
    __shared__ int jr[128];
    const uint32_t sb = smem_u32(dsm);
    const int tid = threadIdx.x;
    const int wid = tid >> 5, lane = tid & 31;
    const int row0 = blockIdx.x * 128;
    const int b = row0 >> 12;
    const int m0 = wid * 16;

    const int rowSel = lane & 15;
    const int colSel = (lane >> 4) << 3;
    const uint32_t aTerm = (uint32_t)(((m0 + rowSel) * BPITCH + colSel) * 2);
    const uint32_t bTerm = (uint32_t)((rowSel * BPITCH + colSel) * 2);

    float facc[16][4] = {};

    const int arow = tid >> 1, ahalf = tid & 1;

    for (int k = 0; k < NBK; k++) {
        __syncthreads();
        if (tid < 128) {
            jr[tid] = ld_idx(idx, ((size_t)(row0 + tid)) * NBK + k);
        }
        __syncthreads();
        // A staging: pure gather-copy of presplit Qn rows
        {
            int j = b * NN + jr[arow];
            const uint4* srcH = (const uint4*)&g_qb[j][0][ahalf * 64];
            const uint4* srcL = (const uint4*)&g_qb[j][1][ahalf * 64];
            uint4* dH = (uint4*)(dsm + AGG_A0 + (uint32_t)((arow * BPITCH + ahalf * 64) * 2));
            uint4* dL = (uint4*)(dsm + AGG_A1 + (uint32_t)((arow * BPITCH + ahalf * 64) * 2));
#pragma unroll
            for (int g = 0; g < 8; g++) {
                dH[g] = srcH[g];
                dL[g] = srcL[g];
            }
        }
        {
            const int p = b * NBK + k;
            uint4* Bh = (uint4*)(dsm + AGG_B0);
            uint4* Bl = (uint4*)(dsm + AGG_B1);
            const uint4* sh = (const uint4*)&g_kvb[p][0][0];
            const uint4* sl = (const uint4*)&g_kvb[p][1][0];
            for (int e = tid; e < (128 * BPITCH * 2) / 16; e += 256) {
                Bh[e] = sh[e];
                Bl[e] = sl[e];
            }
        }
        __syncthreads();
#pragma unroll 1
        for (int cc = 0; cc < 8; cc++) {
            uint32_t ah0, ah1, ah2, ah3, al0, al1, al2, al3;
            uint32_t aAddr = sb + AGG_A0 + aTerm + (uint32_t)(cc * 16 * 2);
            LDSM_X4(ah0, ah1, ah2, ah3, aAddr);
            LDSM_X4(al0, al1, al2, al3, aAddr + (AGG_A1 - AGG_A0));
            uint32_t bBase = sb + AGG_B0 + bTerm + (uint32_t)(cc * 16 * BPITCH * 2);
#pragma unroll
            for (int dblk = 0; dblk < 8; dblk++) {
                uint32_t bh0, bh1, bh2, bh3, bl0, bl1, bl2, bl3;
                uint32_t bAddr = bBase + (uint32_t)(dblk * 16 * 2);
                LDSM_X4T(bh0, bh1, bh2, bh3, bAddr);
                LDSM_X4T(bl0, bl1, bl2, bl3, bAddr + (AGG_B1 - AGG_B0));
                float* d0 = facc[dblk * 2];
                float* d1 = facc[dblk * 2 + 1];
                MMA_BF16(d0, ah0, ah1, ah2, ah3, bh0, bh1);
                MMA_BF16(d1, ah0, ah1, ah2, ah3, bh2, bh3);
                MMA_BF16(d0, al0, al1, al2, al3, bh0, bh1);
                MMA_BF16(d1, al0, al1, al2, al3, bh2, bh3);
                MMA_BF16(d0, ah0, ah1, ah2, ah3, bl0, bl1);
                MMA_BF16(d1, ah0, ah1, ah2, ah3, bl2, bl3);
            }
        }
    }
    const float inv = 1.0f / (float)NN;
    const int g = lane >> 2, t = lane & 3;
    size_t r0b = (size_t)(row0 + m0 + g) * CD;
#pragma unroll
    for (int dt = 0; dt < 16; dt++) {
        int col = dt * 8 + t * 2;
        *(float2*)&g_agg[r0b + col] = make_float2(facc[dt][0] * inv, facc[dt][1] * inv);
        *(float2*)&g_agg[r0b + 8 * CD + col] = make_float2(facc[dt][2] * inv, facc[dt][3] * inv);
    }
}

// ---------------- K5: fused out MLP via mma.sync ----------------------------
#define MLP_A0 0
#define MLP_A1 34816
#define MLP_B0 69632
#define MLP_B1 104448
#define MLP_H0 139264
#define MLP_H1 174080
#define MLP_SMEM 208896
#define EP 129

__global__ void __launch_bounds__(256, 1) k_mlp_mma(const float* __restrict__ bm1,
                                                    const float* __restrict__ bm2,
                                                    const float* __restrict__ x,
                                                    float* __restrict__ out) {
    extern __shared__ __align__(16) unsigned char dsm[];
    __shared__ float bm1s[4 * CD];
    __shared__ float bm2s[CD];
    const uint32_t sb = smem_u32(dsm);
    const int tid = threadIdx.x;
    const int wid = tid >> 5, lane = tid & 31;
    const int row0 = blockIdx.x * 128;
    const int b = row0 >> 12;
    const int n0 = row0 & (NN - 1);
    const int m0 = wid * 16;

    if (tid < CD) bm2s[tid] = bm2[tid];
    for (int v = tid; v < 4 * CD; v += 256) bm1s[v] = bm1[v];

    {
        const int arow = tid >> 1, ahalf = tid & 1;
        const float* src = &g_agg[(size_t)(row0 + arow) * CD + ahalf * 64];
        unsigned char* Ah = dsm + MLP_A0;
        unsigned char* Al = dsm + MLP_A1;
#pragma unroll
        for (int gg = 0; gg < 8; gg++) {
            float4 qa = ld4(src + gg * 8);
            float4 qb = ld4(src + gg * 8 + 4);
            float xs[8] = {qa.x, qa.y, qa.z, qa.w, qb.x, qb.y, qb.z, qb.w};
            unsigned short h[8], l[8];
#pragma unroll
            for (int q = 0; q < 8; q++) bf_split(xs[q], h[q], l[q]);
            uint4 vh, vl;
            vh.x = (uint32_t)h[0] | ((uint32_t)h[1] << 16);
            vh.y = (uint32_t)h[2] | ((uint32_t)h[3] << 16);
            vh.z = (uint32_t)h[4] | ((uint32_t)h[5] << 16);
            vh.w = (uint32_t)h[6] | ((uint32_t)h[7] << 16);
            vl.x = (uint32_t)l[0] | ((uint32_t)l[1] << 16);
            vl.y = (uint32_t)l[2] | ((uint32_t)l[3] << 16);
            vl.z = (uint32_t)l[4] | ((uint32_t)l[5] << 16);
            vl.w = (uint32_t)l[6] | ((uint32_t)l[7] << 16);
            uint32_t off = (uint32_t)((arow * BPITCH + ahalf * 64 + gg * 8) * 2);
            *(uint4*)(Ah + off) = vh;
            *(uint4*)(Al + off) = vl;
        }
    }

    const int rowSel = lane & 15;
    const int colSel = (lane >> 4) << 3;
    const uint32_t aTerm = (uint32_t)(((m0 + rowSel) * BPITCH + colSel) * 2);
    const uint32_t bTerm = (uint32_t)((rowSel * BPITCH + colSel) * 2);
    const int g = lane >> 2, t = lane & 3;

    float facc2[16][4] = {};

    for (int oc = 0; oc < 4; oc++) {
        __syncthreads();
        {
            uint4* Bh = (uint4*)(dsm + MLP_B0);
            uint4* Bl = (uint4*)(dsm + MLP_B1);
            const uint4* sh = (const uint4*)&g_wm1b[oc][0][0];
            const uint4* sl = (const uint4*)&g_wm1b[oc][1][0];
            for (int e = tid; e < (128 * BPITCH * 2) / 16; e += 256) {
                Bh[e] = sh[e];
                Bl[e] = sl[e];
            }
        }
        __syncthreads();
        float facc1[16][4] = {};
#pragma unroll 1
        for (int cc = 0; cc < 8; cc++) {
            uint32_t ah0, ah1, ah2, ah3, al0, al1, al2, al3;
            uint32_t aAddr = sb + MLP_A0 + aTerm + (uint32_t)(cc * 16 * 2);
            LDSM_X4(ah0, ah1, ah2, ah3, aAddr);
            LDSM_X4(al0, al1, al2, al3, aAddr + (MLP_A1 - MLP_A0));
            uint32_t bBase = sb + MLP_B0 + bTerm + (uint32_t)(cc * 16 * BPITCH * 2);
#pragma unroll
            for (int dblk = 0; dblk < 8; dblk++) {
                uint32_t bh0, bh1, bh2, bh3, bl0, bl1, bl2, bl3;
                uint32_t bAddr = bBase + (uint32_t)(dblk * 16 * 2);
                LDSM_X4T(bh0, bh1, bh2, bh3, bAddr);
                LDSM_X4T(bl0, bl1, bl2, bl3, bAddr + (MLP_B1 - MLP_B0));
                float* d0 = facc1[dblk * 2];
                float* d1 = facc1[dblk * 2 + 1];
                MMA_BF16(d0, ah0, ah1, ah2, ah3, bh0, bh1);
                MMA_BF16(d1, ah0, ah1, ah2, ah3, bh2, bh3);
                MMA_BF16(d0, al0, al1, al2, al3, bh0, bh1);
                MMA_BF16(d1, al0, al1, al2, al3, bh2, bh3);
                MMA_BF16(d0, ah0, ah1, ah2, ah3, bl0, bl1);
                MMA_BF16(d1, ah0, ah1, ah2, ah3, bl2, bl3);
            }
        }
        {
            unsigned short* Hh = (unsigned short*)(dsm + MLP_H0);
            unsigned short* Hl = (unsigned short*)(dsm + MLP_H1);
#pragma unroll
            for (int dt = 0; dt < 16; dt++) {
                int col = dt * 8 + t * 2;
                float bx = bm1s[oc * 128 + col], by = bm1s[oc * 128 + col + 1];
                float h0 = fmaxf(facc1[dt][0] + bx, 0.f);
                float h1 = fmaxf(facc1[dt][1] + by, 0.f);
                float h2 = fmaxf(facc1[dt][2] + bx, 0.f);
                float h3 = fmaxf(facc1[dt][3] + by, 0.f);
                unsigned short hh0, hl0, hh1, hl1, hh2, hl2, hh3, hl3;
                bf_split(h0, hh0, hl0); bf_split(h1, hh1, hl1);
                bf_split(h2, hh2, hl2); bf_split(h3, hh3, hl3);
                int r1 = m0 + g, r2 = m0 + 8 + g;
                *(uint32_t*)&Hh[r1 * BPITCH + col] = (uint32_t)hh0 | ((uint32_t)hh1 << 16);
                *(uint32_t*)&Hl[r1 * BPITCH + col] = (uint32_t)hl0 | ((uint32_t)hl1 << 16);
                *(uint32_t*)&Hh[r2 * BPITCH + col] = (uint32_t)hh2 | ((uint32_t)hh3 << 16);
                *(uint32_t*)&Hl[r2 * BPITCH + col] = (uint32_t)hl2 | ((uint32_t)hl3 << 16);
            }
        }
        __syncthreads();
        {
            uint4* Bh = (uint4*)(dsm + MLP_B0);
            uint4* Bl = (uint4*)(dsm + MLP_B1);
            const uint4* sh = (const uint4*)&g_wm2b[oc][0][0];
            const uint4* sl = (const uint4*)&g_wm2b[oc][1][0];
            for (int e = tid; e < (128 * BPITCH * 2) / 16; e += 256) {
                Bh[e] = sh[e];
                Bl[e] = sl[e];
            }
        }
        __syncthreads();
#pragma unroll 1
        for (int cc = 0; cc < 8; cc++) {
            uint32_t ah0, ah1, ah2, ah3, al0, al1, al2, al3;
            uint32_t aAddr = sb + MLP_H0 + aTerm + (uint32_t)(cc * 16 * 2);
            LDSM_X4(ah0, ah1, ah2, ah3, aAddr);
            LDSM_X4(al0, al1, al2, al3, aAddr + (MLP_H1 - MLP_H0));
            uint32_t bBase = sb + MLP_B0 + bTerm + (uint32_t)(cc * 16 * BPITCH * 2);
#pragma unroll
            for (int dblk = 0; dblk < 8; dblk++) {
                uint32_t bh0, bh1, bh2, bh3, bl0, bl1, bl2, bl3;
                uint32_t bAddr = bBase + (uint32_t)(dblk * 16 * 2);
                LDSM_X4T(bh0, bh1, bh2, bh3, bAddr);
                LDSM_X4T(bl0, bl1, bl2, bl3, bAddr + (MLP_B1 - MLP_B0));
                float* d0 = facc2[dblk * 2];
                float* d1 = facc2[dblk * 2 + 1];
                MMA_BF16(d0, ah0, ah1, ah2, ah3, bh0, bh1);
                MMA_BF16(d1, ah0, ah1, ah2, ah3, bh2, bh3);
                MMA_BF16(d0, al0, al1, al2, al3, bh0, bh1);
                MMA_BF16(d1, al0, al1, al2, al3, bh2, bh3);
                MMA_BF16(d0, ah0, ah1, ah2, ah3, bl0, bl1);
                MMA_BF16(d1, ah0, ah1, ah2, ah3, bl2, bl3);
            }
        }
    }
    __syncthreads();
    {
        float* Cst = (float*)(dsm + MLP_A0);
#pragma unroll
        for (int dt = 0; dt < 16; dt++) {
            int col = dt * 8 + t * 2;
            float bx = bm2s[col], by = bm2s[col + 1];
            int r1 = m0 + g, r2 = m0 + 8 + g;
            Cst[r1 * EP + col]     = facc2[dt][0] + bx;
            Cst[r1 * EP + col + 1] = facc2[dt][1] + by;
            Cst[r2 * EP + col]     = facc2[dt][2] + bx;
            Cst[r2 * EP + col + 1] = facc2[dt][3] + by;
        }
    }
    __syncthreads();
    {
        const float* Cst = (const float*)(dsm + MLP_A0);
        for (int v = tid; v < 128 * CD; v += 256) {
            int dd = v >> 7, nn = v & 127;
            size_t oa = ((size_t)b * CD + dd) * NN + n0 + nn;
            out[oa] = Cst[nn * EP + dd] + x[oa];
        }
    }
}

// ---------------- launcher ---------------------------------------------------
extern "C" void kernel_launch(void* const* d_in, const int* in_sizes, int n_in,
                              void* d_out, int out_size) {
    (void)in_sizes; (void)n_in; (void)out_size;
    const float* pos  = (const float*)d_in[0];
    const float* x    = (const float*)d_in[1];
    const void*  idx  = d_in[2];
    const float* dist = (const float*)d_in[3];
    const float* Wqkv = (const float*)d_in[4];
    const float* W1   = (const float*)d_in[5];
    const float* b1   = (const float*)d_in[6];
    const float* W2   = (const float*)d_in[7];
    const float* b2   = (const float*)d_in[8];
    const float* Wm1  = (const float*)d_in[9];
    const float* bm1  = (const float*)d_in[10];
    const float* Wm2  = (const float*)d_in[11];
    const float* bm2  = (const float*)d_in[12];
    float* out = (float*)d_out;

    cudaFuncSetAttribute(k_agg_mma, cudaFuncAttributeMaxDynamicSharedMemorySize, AGG_SMEM);
    cudaFuncSetAttribute(k_pe_mma,  cudaFuncAttributeMaxDynamicSharedMemorySize, PE_SMEM);
    cudaFuncSetAttribute(k_mlp_mma, cudaFuncAttributeMaxDynamicSharedMemorySize, MLP_SMEM);

    k_detect  <<<1, 256>>>((const unsigned int*)idx);
    k_qkv     <<<dim3(6, NN / 64, BB), 256>>>(x, Wqkv);
    k_qsplit  <<<ROWS / 8, 256>>>();
    k_wsplit  <<<dim3(2, 9, 4), 256>>>(W2, Wm1, Wm2);
    k_pe_mma  <<<GROWS / 128, 256, PE_SMEM>>>(pos, idx, dist, W1, b1, b2);
    k_kv_mma  <<<dim3(NSPLIT, PAIRS), 256>>>(idx);
    k_redsplit<<<dim3(PAIRS, 4), 256>>>();
    k_agg_mma <<<ROWS / 128, 256, AGG_SMEM>>>(idx);
    k_mlp_mma <<<ROWS / 128, 256, MLP_SMEM>>>(bm1, bm2, x, out);
}

// round 15
// speedup vs baseline: 2.4509x; 1.0992x over previous
#include <cuda_runtime.h>
#include <cuda_bf16.h>
#include <cstdint>

#define BB  4
#define NN  4096
#define NBK 16
#define CD  128
#define HID 64
#define ROWS (BB*NN)            // 16384
#define GROWS (BB*NN*NBK)       // 262144
#define PAIRS (BB*NBK)          // 64
#define NSPLIT 8
#define BPITCH 136              // bf16 tile pitch (272 B rows)
#define HPITCH 72               // hs tile pitch (144 B rows)

// ---------------- scratch (device globals; no allocation allowed) ----------
__device__ float g_qkv [ROWS*3*CD];                 // 25 MB
__device__ unsigned short g_qb[ROWS][2][CD];        // prescaled Qn bf16 hi/lo, 8.4 MB
__device__ float g_kvp [NSPLIT][PAIRS*CD*CD];       // split partials 32 MB
__device__ unsigned short g_kvb[PAIRS][2][128*BPITCH]; // bf16 hi/lo kv images
__device__ unsigned short g_w2b[2][HID*BPITCH];     // bf16 hi/lo W2^T images
__device__ unsigned short g_wm1b[4][2][128*BPITCH]; // Wm1^T chunk images [c][o]
__device__ unsigned short g_wm2b[4][2][128*BPITCH]; // Wm2^T chunk images [o][d]
__device__ float g_agg [ROWS*CD];                   // 8 MB
__device__ int   g_idx64;

typedef unsigned long long u64;
__device__ __forceinline__ float4 ld4(const float* p) { return *(const float4*)p; }
__device__ __forceinline__ void   st4(float* p, float4 v) { *(float4*)p = v; }
__device__ __forceinline__ u64 splat2(float a) {
    u64 r; asm("mov.b64 %0, {%1, %1};" : "=l"(r) : "f"(a)); return r;
}
__device__ __forceinline__ void fma2(u64& d, u64 a, u64 b) {
    asm("fma.rn.f32x2 %0, %1, %2, %0;" : "+l"(d) : "l"(a), "l"(b));
}
__device__ __forceinline__ void unp(u64 v, float& lo, float& hi) {
    asm("mov.b64 {%0, %1}, %2;" : "=f"(lo), "=f"(hi) : "l"(v));
}
__device__ __forceinline__ int ld_idx(const void* p, size_t pos) {
    if (g_idx64) return (int)((const long long*)p)[pos];
    return ((const int*)p)[pos];
}
__device__ __forceinline__ uint32_t smem_u32(const void* p) {
    uint32_t a;
    asm("{ .reg .u64 t; cvta.to.shared.u64 t, %1; cvt.u32.u64 %0, t; }" : "=r"(a) : "l"(p));
    return a;
}
__device__ __forceinline__ void bf_split(float x, unsigned short& h, unsigned short& l) {
    __nv_bfloat16 bh = __float2bfloat16(x);
    h = __bfloat16_as_ushort(bh);
    l = __bfloat16_as_ushort(__float2bfloat16(x - __bfloat162float(bh)));
}

#define LDSM_X4(r0,r1,r2,r3, a) \
    asm volatile("ldmatrix.sync.aligned.m8n8.x4.shared.b16 {%0,%1,%2,%3}, [%4];" \
        : "=r"(r0),"=r"(r1),"=r"(r2),"=r"(r3) : "r"(a))
#define LDSM_X4T(r0,r1,r2,r3, a) \
    asm volatile("ldmatrix.sync.aligned.m8n8.x4.trans.shared.b16 {%0,%1,%2,%3}, [%4];" \
        : "=r"(r0),"=r"(r1),"=r"(r2),"=r"(r3) : "r"(a))
#define MMA_BF16(d, a0,a1,a2,a3, b0,b1) \
    asm volatile("mma.sync.aligned.m16n8k16.row.col.f32.bf16.bf16.f32 " \
        "{%0,%1,%2,%3}, {%4,%5,%6,%7}, {%8,%9}, {%0,%1,%2,%3};" \
        : "+f"((d)[0]),"+f"((d)[1]),"+f"((d)[2]),"+f"((d)[3]) \
        : "r"(a0),"r"(a1),"r"(a2),"r"(a3), "r"(b0),"r"(b1))

// ---------------- idx dtype autodetect -------------------------------------
__global__ void k_detect(const unsigned int* __restrict__ w) {
    __shared__ int any;
    if (threadIdx.x == 0) any = 0;
    __syncthreads();
    unsigned int v = w[1 + 2 * threadIdx.x];
    if (v != 0u) any = 1;
    __syncthreads();
    if (threadIdx.x == 0) g_idx64 = (any ? 0 : 1);
}

// ---------------- K1: qkv = x^T @ Wqkv^T ------------------------------------
__global__ void __launch_bounds__(256) k_qkv(const float* __restrict__ x,
                                             const float* __restrict__ Wqkv) {
    __shared__ float As[32][64];
    __shared__ float Bs[32][68];
    const int b  = blockIdx.z;
    const int n0 = blockIdx.y * 64;
    const int o0 = blockIdx.x * 64;
    const int tid = threadIdx.x;
    const int tx = tid & 15, ty = tid >> 4;
    u64 acc[4][2] = {};
    for (int c0 = 0; c0 < CD; c0 += 32) {
#pragma unroll
        for (int p = 0; p < 8; p++) {
            int v = tid + p * 256;
            int cc = v >> 6, i = v & 63;
            As[cc][i] = x[((size_t)b * CD + c0 + cc) * NN + n0 + i];
        }
#pragma unroll
        for (int p = 0; p < 8; p++) {
            int v = tid + p * 256;
            int cc = v & 31, j = v >> 5;
            Bs[cc][j] = Wqkv[(size_t)(o0 + j) * CD + c0 + cc];
        }
        __syncthreads();
#pragma unroll
        for (int kk = 0; kk < 32; kk++) {
            float4 a = ld4(&As[kk][ty * 4]);
            const u64* wp = (const u64*)&Bs[kk][tx * 4];
            u64 w0 = wp[0], w1 = wp[1];
            u64 s;
            s = splat2(a.x); fma2(acc[0][0], s, w0); fma2(acc[0][1], s, w1);
            s = splat2(a.y); fma2(acc[1][0], s, w0); fma2(acc[1][1], s, w1);
            s = splat2(a.z); fma2(acc[2][0], s, w0); fma2(acc[2][1], s, w1);
            s = splat2(a.w); fma2(acc[3][0], s, w0); fma2(acc[3][1], s, w1);
        }
        __syncthreads();
    }
#pragma unroll
    for (int i = 0; i < 4; i++) {
        float4 o; unp(acc[i][0], o.x, o.y); unp(acc[i][1], o.z, o.w);
        size_t ob = ((size_t)b * NN + n0 + ty * 4 + i) * (3 * CD) + o0 + tx * 4;
        st4(&g_qkv[ob], o);
    }
}

// ---------------- K1b: Qn = Q/||Q|| -> bf16 hi/lo images --------------------
__global__ void __launch_bounds__(256) k_qsplit() {
    int row  = blockIdx.x * 8 + (threadIdx.x >> 5);
    int lane = threadIdx.x & 31;
    float4 q = ld4(&g_qkv[(size_t)row * (3 * CD) + lane * 4]);
    float s = q.x * q.x + q.y * q.y + q.z * q.z + q.w * q.w;
#pragma unroll
    for (int o = 16; o; o >>= 1) s += __shfl_xor_sync(0xffffffffu, s, o);
    float sc = 1.0f / fmaxf(sqrtf(s), 1e-12f);
    float xs[4] = {q.x * sc, q.y * sc, q.z * sc, q.w * sc};
    unsigned short h[4], l[4];
#pragma unroll
    for (int i = 0; i < 4; i++) bf_split(xs[i], h[i], l[i]);
    uint2 vh = make_uint2((uint32_t)h[0] | ((uint32_t)h[1] << 16),
                          (uint32_t)h[2] | ((uint32_t)h[3] << 16));
    uint2 vl = make_uint2((uint32_t)l[0] | ((uint32_t)l[1] << 16),
                          (uint32_t)l[2] | ((uint32_t)l[3] << 16));
    *(uint2*)&g_qb[row][0][lane * 4] = vh;
    *(uint2*)&g_qb[row][1][lane * 4] = vl;
}

// ---------------- K1c: weight bf16 hi/lo pre-splits (4-way z-split) ---------
__global__ void __launch_bounds__(256) k_wsplit(const float* __restrict__ W2,
                                                const float* __restrict__ Wm1,
                                                const float* __restrict__ Wm2) {
    const int v = blockIdx.x;
    const int w = blockIdx.y;
    const int tid = (int)(blockIdx.z * 256 + threadIdx.x);
    const int stride = 1024;
    if (w == 0) {
        for (int e = tid; e < CD * HID; e += stride) {
            int j = e >> 7, c = e & 127;
            float x = W2[(size_t)c * HID + j];
            __nv_bfloat16 bh = __float2bfloat16(x);
            unsigned short bits = v == 0 ? __bfloat16_as_ushort(bh)
                : __bfloat16_as_ushort(__float2bfloat16(x - __bfloat162float(bh)));
            g_w2b[v][j * BPITCH + c] = bits;
        }
    } else if (w <= 4) {
        const int oc = w - 1;
        for (int e = tid; e < CD * CD; e += stride) {
            int c = e >> 7, o = e & 127;
            float x = Wm1[(size_t)(oc * 128 + o) * CD + c];
            __nv_bfloat16 bh = __float2bfloat16(x);
            unsigned short bits = v == 0 ? __bfloat16_as_ushort(bh)
                : __bfloat16_as_ushort(__float2bfloat16(x - __bfloat162float(bh)));
            g_wm1b[oc][v][c * BPITCH + o] = bits;
        }
    } else {
        const int oc = w - 5;
        for (int e = tid; e < CD * CD; e += stride) {
            int ol = e >> 7, d = e & 127;
            float x = Wm2[(size_t)d * (4 * CD) + oc * 128 + ol];
            __nv_bfloat16 bh = __float2bfloat16(x);
            unsigned short bits = v == 0 ? __bfloat16_as_ushort(bh)
                : __bfloat16_as_ushort(__float2bfloat16(x - __bfloat162float(bh)));
            g_wm2b[oc][v][ol * BPITCH + d] = bits;
        }
    }
}

// ---------------- K3: FUSED pos-MLP + kv outer product via mma.sync ---------
// grid (NSPLIT, PAIRS); per 32-row step:
//   feats -> MLP1(hi/lo smem) -> pe GEMM (mma, W2 images) -> PE fp32 smem
//   -> gather/norm/split staging -> kv GEMM.
#define KV_KN_H 0
#define KV_KN_L (32*BPITCH*2)
#define KV_VR_H (2*32*BPITCH*2)
#define KV_VR_L (3*32*BPITCH*2)
#define KV_W2_H (4*32*BPITCH*2)                // 34816
#define KV_W2_L (KV_W2_H + HID*BPITCH*2)
#define KV_HS_H (KV_W2_H + 2*HID*BPITCH*2)     // 69632+... = 104448? compute: 34816+34816=69632
#define KV_HS_L (KV_HS_H + 32*HPITCH*2)
#define KV_PE   (KV_HS_H + 2*32*HPITCH*2)
#define KV_SMEM (KV_PE + 32*132*4)
#define PEP 132

__global__ void __launch_bounds__(256, 2) k_kv_mma(
    const float* __restrict__ pos, const void* __restrict__ idx,
    const float* __restrict__ dist,
    const float* __restrict__ W1, const float* __restrict__ b1,
    const float* __restrict__ b2) {
    extern __shared__ __align__(16) unsigned char dsm[];
    __shared__ float W1s[HID * 10];
    __shared__ float b1s[HID];
    __shared__ float b2s[CD];
    __shared__ float feats[32][12];
    __shared__ int   jr[32];
    const uint32_t sb = smem_u32(dsm);
    const int p = blockIdx.y;
    const int s = blockIdx.x;
    const int b = p >> 4, kslot = p & 15;
    const int tid = threadIdx.x;
    const int lane = tid & 31, warp = tid >> 5;
    const int c4 = lane * 4;
    const int m0 = warp * 16;

    for (int v = tid; v < HID * 10; v += 256) W1s[v] = W1[v];
    if (tid < HID) b1s[tid] = b1[tid];
    if (tid < CD)  b2s[tid] = b2[tid];
    // resident W2^T hi/lo images
    {
        uint4* Wh = (uint4*)(dsm + KV_W2_H);
        uint4* Wl = (uint4*)(dsm + KV_W2_L);
        const uint4* sh = (const uint4*)&g_w2b[0][0];
        const uint4* sl = (const uint4*)&g_w2b[1][0];
        for (int e = tid; e < (HID * BPITCH * 2) / 16; e += 256) {
            Wh[e] = sh[e];
            Wl[e] = sl[e];
        }
    }

    const int rowSel = lane & 15;
    const int colSel = (lane >> 4) << 3;
    const uint32_t aTerm = (uint32_t)((rowSel * BPITCH + m0 + colSel) * 2);  // kv A (Kn trans)
    const uint32_t bTerm = (uint32_t)((rowSel * BPITCH + colSel) * 2);       // kv/pe B
    // pe GEMM decomposition: warp = (m-tile mt, 32-col group ng)
    const int mt = warp & 1, ng = warp >> 1;
    const uint32_t aTermP = (uint32_t)(((mt * 16 + rowSel) * HPITCH + colSel) * 2);
    const uint32_t bTermP = (uint32_t)((rowSel * BPITCH + ng * 32 + colSel) * 2);
    const int g = lane >> 2, t = lane & 3;

    float facc[16][4] = {};

    const int n0 = s * (NN / NSPLIT);
    const int NSTEP = (NN / NSPLIT) / 32;
    for (int step = 0; step < NSTEP; step++) {
        const int nbase = n0 + step * 32;
        __syncthreads();   // prior-step tiles consumed; PE/hs free
        if (tid < 32) {
            int n = nbase + tid;
            size_t gg = ((size_t)(b * NN + n)) * NBK + kslot;
            int j = ld_idx(idx, gg);
            jr[tid] = j;
            const float* pc = &pos[((size_t)b * NN + n) * 3];
            const float* pn = &pos[((size_t)b * NN + j) * 3];
            float a0 = pc[0], a1 = pc[1], a2 = pc[2];
            float q0 = pn[0], q1 = pn[1], q2 = pn[2];
            feats[tid][0] = a0;  feats[tid][1] = a1;  feats[tid][2] = a2;
            feats[tid][3] = q0;  feats[tid][4] = q1;  feats[tid][5] = q2;
            feats[tid][6] = a0 - q0; feats[tid][7] = a1 - q1; feats[tid][8] = a2 - q2;
            feats[tid][9] = dist[gg];
        }
        __syncthreads();
        // MLP1: 32 rows x 64 hid -> hi/lo hs tiles [row][j]
        {
            unsigned short* Hh = (unsigned short*)(dsm + KV_HS_H);
            unsigned short* Hl = (unsigned short*)(dsm + KV_HS_L);
#pragma unroll
            for (int pp = 0; pp < 8; pp++) {
                int v = tid + pp * 256;
                int j = v & 63, r = v >> 6;
                float sm = b1s[j];
#pragma unroll
                for (int i = 0; i < 10; i++) sm += feats[r][i] * W1s[j * 10 + i];
                sm = fmaxf(sm, 0.0f);
                unsigned short h, l;
                bf_split(sm, h, l);
                Hh[r * HPITCH + j] = h;
                Hl[r * HPITCH + j] = l;
            }
        }
        __syncthreads();
        // pe GEMM: PE[32][128] = hs @ W2^T + b2 (3-product hi/lo)
        {
            float pacc[2][2][4] = {};
#pragma unroll
            for (int cc = 0; cc < 4; cc++) {
                uint32_t ah0, ah1, ah2, ah3, al0, al1, al2, al3;
                uint32_t aAddr = sb + KV_HS_H + aTermP + (uint32_t)(cc * 16 * 2);
                LDSM_X4(ah0, ah1, ah2, ah3, aAddr);
                LDSM_X4(al0, al1, al2, al3, aAddr + (KV_HS_L - KV_HS_H));
                uint32_t bBase = sb + KV_W2_H + bTermP + (uint32_t)(cc * 16 * BPITCH * 2);
#pragma unroll
                for (int d2 = 0; d2 < 2; d2++) {
                    uint32_t bh0, bh1, bh2, bh3, bl0, bl1, bl2, bl3;
                    uint32_t bAddr = bBase + (uint32_t)(d2 * 16 * 2);
                    LDSM_X4T(bh0, bh1, bh2, bh3, bAddr);
                    LDSM_X4T(bl0, bl1, bl2, bl3, bAddr + (KV_W2_L - KV_W2_H));
                    float* d0 = pacc[d2][0];
                    float* d1 = pacc[d2][1];
                    MMA_BF16(d0, ah0, ah1, ah2, ah3, bh0, bh1);
                    MMA_BF16(d1, ah0, ah1, ah2, ah3, bh2, bh3);
                    MMA_BF16(d0, al0, al1, al2, al3, bh0, bh1);
                    MMA_BF16(d1, al0, al1, al2, al3, bh2, bh3);
                    MMA_BF16(d0, ah0, ah1, ah2, ah3, bl0, bl1);
                    MMA_BF16(d1, ah0, ah1, ah2, ah3, bl2, bl3);
                }
            }
            float* PE = (float*)(dsm + KV_PE);
#pragma unroll
            for (int d2 = 0; d2 < 2; d2++)
#pragma unroll
                for (int hf = 0; hf < 2; hf++) {
                    int col = ng * 32 + d2 * 16 + hf * 8 + t * 2;
                    float bx = b2s[col], by = b2s[col + 1];
                    int r1 = mt * 16 + g, r2 = mt * 16 + 8 + g;
                    *(float2*)&PE[r1 * PEP + col] =
                        make_float2(pacc[d2][hf][0] + bx, pacc[d2][hf][1] + by);
                    *(float2*)&PE[r2 * PEP + col] =
                        make_float2(pacc[d2][hf][2] + bx, pacc[d2][hf][3] + by);
                }
        }
        __syncthreads();
        // staging: gather K/V, add pe, norm/relu, split into Kn/Vr tiles
        {
            unsigned short* KnH = (unsigned short*)(dsm + KV_KN_H);
            unsigned short* KnL = (unsigned short*)(dsm + KV_KN_L);
            unsigned short* VrH = (unsigned short*)(dsm + KV_VR_H);
            unsigned short* VrL = (unsigned short*)(dsm + KV_VR_L);
            const float* PE = (const float*)(dsm + KV_PE);
#pragma unroll
            for (int rr = 0; rr < 4; rr++) {
                int row = warp * 4 + rr;
                int j = jr[row];
                float4 pe = ld4(&PE[row * PEP + c4]);
                const float* qrow = &g_qkv[((size_t)b * NN + j) * (3 * CD)];
                float4 kg = ld4(&qrow[CD + c4]);
                float4 vg = ld4(&qrow[2 * CD + c4]);
                float k0 = kg.x + pe.x, k1 = kg.y + pe.y, k2 = kg.z + pe.z, k3 = kg.w + pe.w;
                float v0 = fmaxf(vg.x + pe.x, 0.f), v1 = fmaxf(vg.y + pe.y, 0.f);
                float v2 = fmaxf(vg.z + pe.z, 0.f), v3 = fmaxf(vg.w + pe.w, 0.f);
                float ss = k0 * k0 + k1 * k1 + k2 * k2 + k3 * k3;
#pragma unroll
                for (int o = 16; o; o >>= 1) ss += __shfl_xor_sync(0xffffffffu, ss, o);
                float sc = 1.0f / fmaxf(sqrtf(ss), 1e-12f);
                k0 *= sc; k1 *= sc; k2 *= sc; k3 *= sc;
                unsigned short kh[4], kl[4], vh[4], vl[4];
                bf_split(k0, kh[0], kl[0]); bf_split(k1, kh[1], kl[1]);
                bf_split(k2, kh[2], kl[2]); bf_split(k3, kh[3], kl[3]);
                bf_split(v0, vh[0], vl[0]); bf_split(v1, vh[1], vl[1]);
                bf_split(v2, vh[2], vl[2]); bf_split(v3, vh[3], vl[3]);
                int off = row * BPITCH + c4;
                *(uint2*)&KnH[off] = make_uint2((uint32_t)kh[0] | ((uint32_t)kh[1] << 16),
                                                (uint32_t)kh[2] | ((uint32_t)kh[3] << 16));
                *(uint2*)&KnL[off] = make_uint2((uint32_t)kl[0] | ((uint32_t)kl[1] << 16),
                                                (uint32_t)kl[2] | ((uint32_t)kl[3] << 16));
                *(uint2*)&VrH[off] = make_uint2((uint32_t)vh[0] | ((uint32_t)vh[1] << 16),
                                                (uint32_t)vh[2] | ((uint32_t)vh[3] << 16));
                *(uint2*)&VrL[off] = make_uint2((uint32_t)vl[0] | ((uint32_t)vl[1] << 16),
                                                (uint32_t)vl[2] | ((uint32_t)vl[3] << 16));
            }
        }
        __syncthreads();
        // kv GEMM accumulate (validated A-trans reorder)
#pragma unroll
        for (int cc = 0; cc < 2; cc++) {
            const uint32_t cOff = (uint32_t)(cc * 16 * BPITCH * 2);
            uint32_t t0, t1, t2, t3;
            uint32_t ah0, ah1, ah2, ah3, al0, al1, al2, al3;
            LDSM_X4T(t0, t1, t2, t3, sb + KV_KN_H + aTerm + cOff);
            ah0 = t0; ah1 = t2; ah2 = t1; ah3 = t3;
            LDSM_X4T(t0, t1, t2, t3, sb + KV_KN_L + aTerm + cOff);
            al0 = t0; al1 = t2; al2 = t1; al3 = t3;
#pragma unroll
            for (int dblk = 0; dblk < 8; dblk++) {
                uint32_t bh0, bh1, bh2, bh3, bl0, bl1, bl2, bl3;
                uint32_t bOff = bTerm + cOff + (uint32_t)(dblk * 16 * 2);
                LDSM_X4T(bh0, bh1, bh2, bh3, sb + KV_VR_H + bOff);
                LDSM_X4T(bl0, bl1, bl2, bl3, sb + KV_VR_L + bOff);
                float* d0 = facc[dblk * 2];
                float* d1 = facc[dblk * 2 + 1];
                MMA_BF16(d0, ah0, ah1, ah2, ah3, bh0, bh1);
                MMA_BF16(d1, ah0, ah1, ah2, ah3, bh2, bh3);
                MMA_BF16(d0, al0, al1, al2, al3, bh0, bh1);
                MMA_BF16(d1, al0, al1, al2, al3, bh2, bh3);
                MMA_BF16(d0, ah0, ah1, ah2, ah3, bl0, bl1);
                MMA_BF16(d1, ah0, ah1, ah2, ah3, bl2, bl3);
            }
        }
    }
    float* op = &g_kvp[s][(size_t)p * CD * CD];
#pragma unroll
    for (int dt = 0; dt < 16; dt++) {
        int col = dt * 8 + t * 2;
        *(float2*)&op[(size_t)(m0 + g) * CD + col]     = make_float2(facc[dt][0], facc[dt][1]);
        *(float2*)&op[(size_t)(m0 + 8 + g) * CD + col] = make_float2(facc[dt][2], facc[dt][3]);
    }
}

// ---------------- K3b: reduce partials + split to bf16 hi/lo (4-way) --------
__global__ void __launch_bounds__(256) k_redsplit() {
    const int p = blockIdx.x;
    const int e0 = (int)blockIdx.y * 4096;
    const int tid = threadIdx.x;
    for (int e = e0 + tid; e < e0 + 4096; e += 256) {
        int c = e >> 7, d = e & 127;
        float s = 0.0f;
#pragma unroll
        for (int t = 0; t < NSPLIT; t++) s += g_kvp[t][(size_t)p * CD * CD + e];
        unsigned short h, l;
        bf_split(s, h, l);
        g_kvb[p][0][c * BPITCH + d] = h;
        g_kvb[p][1][c * BPITCH + d] = l;
    }
}

// ---------------- K4: agg via mma.sync (A from presplit g_qb) ---------------
#define AGG_A0 0
#define AGG_A1 34816
#define AGG_B0 69632
#define AGG_B1 104448
#define AGG_SMEM 139264

__global__ void __launch_bounds__(256, 1) k_agg_mma(const void* __restrict__ idx) {
    extern __shared__ __align__(16) unsigned char dsm[];
    __shared__ int jr[128];
    const uint32_t sb = smem_u32(dsm);
    const int tid = threadIdx.x;
    const int wid = tid >> 5, lane = tid & 31;
    const int row0 = blockIdx.x * 128;
    const int b = row0 >> 12;
    const int m0 = wid * 16;

    const int rowSel = lane & 15;
    const int colSel = (lane >> 4) << 3;
    const uint32_t aTerm = (uint32_t)(((m0 + rowSel) * BPITCH + colSel) * 2);
    const uint32_t bTerm = (uint32_t)((rowSel * BPITCH + colSel) * 2);

    float facc[16][4] = {};

    const int arow = tid >> 1, ahalf = tid & 1;

    for (int k = 0; k < NBK; k++) {
        __syncthreads();
        if (tid < 128) {
            jr[tid] = ld_idx(idx, ((size_t)(row0 + tid)) * NBK + k);
        }
        __syncthreads();
        {
            int j = b * NN + jr[arow];
            const uint4* srcH = (const uint4*)&g_qb[j][0][ahalf * 64];
            const uint4* srcL = (const uint4*)&g_qb[j][1][ahalf * 64];
            uint4* dH = (uint4*)(dsm + AGG_A0 + (uint32_t)((arow * BPITCH + ahalf * 64) * 2));
            uint4* dL = (uint4*)(dsm + AGG_A1 + (uint32_t)((arow * BPITCH + ahalf * 64) * 2));
#pragma unroll
            for (int g = 0; g < 8; g++) {
                dH[g] = srcH[g];
                dL[g] = srcL[g];
            }
        }
        {
            const int p = b * NBK + k;
            uint4* Bh = (uint4*)(dsm + AGG_B0);
            uint4* Bl = (uint4*)(dsm + AGG_B1);
            const uint4* sh = (const uint4*)&g_kvb[p][0][0];
            const uint4* sl = (const uint4*)&g_kvb[p][1][0];
            for (int e = tid; e < (128 * BPITCH * 2) / 16; e += 256) {
                Bh[e] = sh[e];
                Bl[e] = sl[e];
            }
        }
        __syncthreads();
#pragma unroll 1
        for (int cc = 0; cc < 8; cc++) {
            uint32_t ah0, ah1, ah2, ah3, al0, al1, al2, al3;
            uint32_t aAddr = sb + AGG_A0 + aTerm + (uint32_t)(cc * 16 * 2);
            LDSM_X4(ah0, ah1, ah2, ah3, aAddr);
            LDSM_X4(al0, al1, al2, al3, aAddr + (AGG_A1 - AGG_A0));
            uint32_t bBase = sb + AGG_B0 + bTerm + (uint32_t)(cc * 16 * BPITCH * 2);
#pragma unroll
            for (int dblk = 0; dblk < 8; dblk++) {
                uint32_t bh0, bh1, bh2, bh3, bl0, bl1, bl2, bl3;
                uint32_t bAddr = bBase + (uint32_t)(dblk * 16 * 2);
                LDSM_X4T(bh0, bh1, bh2, bh3, bAddr);
                LDSM_X4T(bl0, bl1, bl2, bl3, bAddr + (AGG_B1 - AGG_B0));
                float* d0 = facc[dblk * 2];
                float* d1 = facc[dblk * 2 + 1];
                MMA_BF16(d0, ah0, ah1, ah2, ah3, bh0, bh1);
                MMA_BF16(d1, ah0, ah1, ah2, ah3, bh2, bh3);
                MMA_BF16(d0, al0, al1, al2, al3, bh0, bh1);
                MMA_BF16(d1, al0, al1, al2, al3, bh2, bh3);
                MMA_BF16(d0, ah0, ah1, ah2, ah3, bl0, bl1);
                MMA_BF16(d1, ah0, ah1, ah2, ah3, bl2, bl3);
            }
        }
    }
    const float inv = 1.0f / (float)NN;
    const int g = lane >> 2, t = lane & 3;
    size_t r0b = (size_t)(row0 + m0 + g) * CD;
#pragma unroll
    for (int dt = 0; dt < 16; dt++) {
        int col = dt * 8 + t * 2;
        *(float2*)&g_agg[r0b + col] = make_float2(facc[dt][0] * inv, facc[dt][1] * inv);
        *(float2*)&g_agg[r0b + 8 * CD + col] = make_float2(facc[dt][2] * inv, facc[dt][3] * inv);
    }
}

// ---------------- K5: fused out MLP via mma.sync ----------------------------
#define MLP_A0 0
#define MLP_A1 34816
#define MLP_B0 69632
#define MLP_B1 104448
#define MLP_H0 139264
#define MLP_H1 174080
#define MLP_SMEM 208896
#define EP 129

__global__ void __launch_bounds__(256, 1) k_mlp_mma(const float* __restrict__ bm1,
                                                    const float* __restrict__ bm2,
                                                    const float* __restrict__ x,
                                                    float* __restrict__ out) {
    extern __shared__ __align__(16) unsigned char dsm[];
    __shared__ float bm1s[4 * CD];
    __shared__ float bm2s[CD];
    const uint32_t sb = smem_u32(dsm);
    const int tid = threadIdx.x;
    const int wid = tid >> 5, lane = tid & 31;
    const int row0 = blockIdx.x * 128;
    const int b = row0 >> 12;
    const int n0 = row0 & (NN - 1);
    const int m0 = wid * 16;

    if (tid < CD) bm2s[tid] = bm2[tid];
    for (int v = tid; v < 4 * CD; v += 256) bm1s[v] = bm1[v];

    {
        const int arow = tid >> 1, ahalf = tid & 1;
        const float* src = &g_agg[(size_t)(row0 + arow) * CD + ahalf * 64];
        unsigned char* Ah = dsm + MLP_A0;
        unsigned char* Al = dsm + MLP_A1;
#pragma unroll
        for (int gg = 0; gg < 8; gg++) {
            float4 qa = ld4(src + gg * 8);
            float4 qb = ld4(src + gg * 8 + 4);
            float xs[8] = {qa.x, qa.y, qa.z, qa.w, qb.x, qb.y, qb.z, qb.w};
            unsigned short h[8], l[8];
#pragma unroll
            for (int q = 0; q < 8; q++) bf_split(xs[q], h[q], l[q]);
            uint4 vh, vl;
            vh.x = (uint32_t)h[0] | ((uint32_t)h[1] << 16);
            vh.y = (uint32_t)h[2] | ((uint32_t)h[3] << 16);
            vh.z = (uint32_t)h[4] | ((uint32_t)h[5] << 16);
            vh.w = (uint32_t)h[6] | ((uint32_t)h[7] << 16);
            vl.x = (uint32_t)l[0] | ((uint32_t)l[1] << 16);
            vl.y = (uint32_t)l[2] | ((uint32_t)l[3] << 16);
            vl.z = (uint32_t)l[4] | ((uint32_t)l[5] << 16);
            vl.w = (uint32_t)l[6] | ((uint32_t)l[7] << 16);
            uint32_t off = (uint32_t)((arow * BPITCH + ahalf * 64 + gg * 8) * 2);
            *(uint4*)(Ah + off) = vh;
            *(uint4*)(Al + off) = vl;
        }
    }

    const int rowSel = lane & 15;
    const int colSel = (lane >> 4) << 3;
    const uint32_t aTerm = (uint32_t)(((m0 + rowSel) * BPITCH + colSel) * 2);
    const uint32_t bTerm = (uint32_t)((rowSel * BPITCH + colSel) * 2);
    const int g = lane >> 2, t = lane & 3;

    float facc2[16][4] = {};

    for (int oc = 0; oc < 4; oc++) {
        __syncthreads();
        {
            uint4* Bh = (uint4*)(dsm + MLP_B0);
            uint4* Bl = (uint4*)(dsm + MLP_B1);
            const uint4* sh = (const uint4*)&g_wm1b[oc][0][0];
            const uint4* sl = (const uint4*)&g_wm1b[oc][1][0];
            for (int e = tid; e < (128 * BPITCH * 2) / 16; e += 256) {
                Bh[e] = sh[e];
                Bl[e] = sl[e];
            }
        }
        __syncthreads();
        float facc1[16][4] = {};
#pragma unroll 1
        for (int cc = 0; cc < 8; cc++) {
            uint32_t ah0, ah1, ah2, ah3, al0, al1, al2, al3;
            uint32_t aAddr = sb + MLP_A0 + aTerm + (uint32_t)(cc * 16 * 2);
            LDSM_X4(ah0, ah1, ah2, ah3, aAddr);
            LDSM_X4(al0, al1, al2, al3, aAddr + (MLP_A1 - MLP_A0));
            uint32_t bBase = sb + MLP_B0 + bTerm + (uint32_t)(cc * 16 * BPITCH * 2);
#pragma unroll
            for (int dblk = 0; dblk < 8; dblk++) {
                uint32_t bh0, bh1, bh2, bh3, bl0, bl1, bl2, bl3;
                uint32_t bAddr = bBase + (uint32_t)(dblk * 16 * 2);
                LDSM_X4T(bh0, bh1, bh2, bh3, bAddr);
                LDSM_X4T(bl0, bl1, bl2, bl3, bAddr + (MLP_B1 - MLP_B0));
                float* d0 = facc1[dblk * 2];
                float* d1 = facc1[dblk * 2 + 1];
                MMA_BF16(d0, ah0, ah1, ah2, ah3, bh0, bh1);
                MMA_BF16(d1, ah0, ah1, ah2, ah3, bh2, bh3);
                MMA_BF16(d0, al0, al1, al2, al3, bh0, bh1);
                MMA_BF16(d1, al0, al1, al2, al3, bh2, bh3);
                MMA_BF16(d0, ah0, ah1, ah2, ah3, bl0, bl1);
                MMA_BF16(d1, ah0, ah1, ah2, ah3, bl2, bl3);
            }
        }
        {
            unsigned short* Hh = (unsigned short*)(dsm + MLP_H0);
            unsigned short* Hl = (unsigned short*)(dsm + MLP_H1);
#pragma unroll
            for (int dt = 0; dt < 16; dt++) {
                int col = dt * 8 + t * 2;
                float bx = bm1s[oc * 128 + col], by = bm1s[oc * 128 + col + 1];
                float h0 = fmaxf(facc1[dt][0] + bx, 0.f);
                float h1 = fmaxf(facc1[dt][1] + by, 0.f);
                float h2 = fmaxf(facc1[dt][2] + bx, 0.f);
                float h3 = fmaxf(facc1[dt][3] + by, 0.f);
                unsigned short hh0, hl0, hh1, hl1, hh2, hl2, hh3, hl3;
                bf_split(h0, hh0, hl0); bf_split(h1, hh1, hl1);
                bf_split(h2, hh2, hl2); bf_split(h3, hh3, hl3);
                int r1 = m0 + g, r2 = m0 + 8 + g;
                *(uint32_t*)&Hh[r1 * BPITCH + col] = (uint32_t)hh0 | ((uint32_t)hh1 << 16);
                *(uint32_t*)&Hl[r1 * BPITCH + col] = (uint32_t)hl0 | ((uint32_t)hl1 << 16);
                *(uint32_t*)&Hh[r2 * BPITCH + col] = (uint32_t)hh2 | ((uint32_t)hh3 << 16);
                *(uint32_t*)&Hl[r2 * BPITCH + col] = (uint32_t)hl2 | ((uint32_t)hl3 << 16);
            }
        }
        __syncthreads();
        {
            uint4* Bh = (uint4*)(dsm + MLP_B0);
            uint4* Bl = (uint4*)(dsm + MLP_B1);
            const uint4* sh = (const uint4*)&g_wm2b[oc][0][0];
            const uint4* sl = (const uint4*)&g_wm2b[oc][1][0];
            for (int e = tid; e < (128 * BPITCH * 2) / 16; e += 256) {
                Bh[e] = sh[e];
                Bl[e] = sl[e];
            }
        }
        __syncthreads();
#pragma unroll 1
        for (int cc = 0; cc < 8; cc++) {
            uint32_t ah0, ah1, ah2, ah3, al0, al1, al2, al3;
            uint32_t aAddr = sb + MLP_H0 + aTerm + (uint32_t)(cc * 16 * 2);
            LDSM_X4(ah0, ah1, ah2, ah3, aAddr);
            LDSM_X4(al0, al1, al2, al3, aAddr + (MLP_H1 - MLP_H0));
            uint32_t bBase = sb + MLP_B0 + bTerm + (uint32_t)(cc * 16 * BPITCH * 2);
#pragma unroll
            for (int dblk = 0; dblk < 8; dblk++) {
                uint32_t bh0, bh1, bh2, bh3, bl0, bl1, bl2, bl3;
                uint32_t bAddr = bBase + (uint32_t)(dblk * 16 * 2);
                LDSM_X4T(bh0, bh1, bh2, bh3, bAddr);
                LDSM_X4T(bl0, bl1, bl2, bl3, bAddr + (MLP_B1 - MLP_B0));
                float* d0 = facc2[dblk * 2];
                float* d1 = facc2[dblk * 2 + 1];
                MMA_BF16(d0, ah0, ah1, ah2, ah3, bh0, bh1);
                MMA_BF16(d1, ah0, ah1, ah2, ah3, bh2, bh3);
                MMA_BF16(d0, al0, al1, al2, al3, bh0, bh1);
                MMA_BF16(d1, al0, al1, al2, al3, bh2, bh3);
                MMA_BF16(d0, ah0, ah1, ah2, ah3, bl0, bl1);
                MMA_BF16(d1, ah0, ah1, ah2, ah3, bl2, bl3);
            }
        }
    }
    __syncthreads();
    {
        float* Cst = (float*)(dsm + MLP_A0);
#pragma unroll
        for (int dt = 0; dt < 16; dt++) {
            int col = dt * 8 + t * 2;
            float bx = bm2s[col], by = bm2s[col + 1];
            int r1 = m0 + g, r2 = m0 + 8 + g;
            Cst[r1 * EP + col]     = facc2[dt][0] + bx;
            Cst[r1 * EP + col + 1] = facc2[dt][1] + by;
            Cst[r2 * EP + col]     = facc2[dt][2] + bx;
            Cst[r2 * EP + col + 1] = facc2[dt][3] + by;
        }
    }
    __syncthreads();
    {
        const float* Cst = (const float*)(dsm + MLP_A0);
        for (int v = tid; v < 128 * CD; v += 256) {
            int dd = v >> 7, nn = v & 127;
            size_t oa = ((size_t)b * CD + dd) * NN + n0 + nn;
            out[oa] = Cst[nn * EP + dd] + x[oa];
        }
    }
}

// ---------------- launcher ---------------------------------------------------
extern "C" void kernel_launch(void* const* d_in, const int* in_sizes, int n_in,
                              void* d_out, int out_size) {
    (void)in_sizes; (void)n_in; (void)out_size;
    const float* pos  = (const float*)d_in[0];
    const float* x    = (const float*)d_in[1];
    const void*  idx  = d_in[2];
    const float* dist = (const float*)d_in[3];
    const float* Wqkv = (const float*)d_in[4];
    const float* W1   = (const float*)d_in[5];
    const float* b1   = (const float*)d_in[6];
    const float* W2   = (const float*)d_in[7];
    const float* b2   = (const float*)d_in[8];
    const float* Wm1  = (const float*)d_in[9];
    const float* bm1  = (const float*)d_in[10];
    const float* Wm2  = (const float*)d_in[11];
    const float* bm2  = (const float*)d_in[12];
    float* out = (float*)d_out;

    cudaFuncSetAttribute(k_kv_mma,  cudaFuncAttributeMaxDynamicSharedMemorySize, KV_SMEM);
    cudaFuncSetAttribute(k_agg_mma, cudaFuncAttributeMaxDynamicSharedMemorySize, AGG_SMEM);
    cudaFuncSetAttribute(k_mlp_mma, cudaFuncAttributeMaxDynamicSharedMemorySize, MLP_SMEM);

    k_detect  <<<1, 256>>>((const unsigned int*)idx);
    k_qkv     <<<dim3(6, NN / 64, BB), 256>>>(x, Wqkv);
    k_qsplit  <<<ROWS / 8, 256>>>();
    k_wsplit  <<<dim3(2, 9, 4), 256>>>(W2, Wm1, Wm2);
    k_kv_mma  <<<dim3(NSPLIT, PAIRS), 256, KV_SMEM>>>(pos, idx, dist, W1, b1, b2);
    k_redsplit<<<dim3(PAIRS, 4), 256>>>();
    k_agg_mma <<<ROWS / 128, 256, AGG_SMEM>>>(idx);
    k_mlp_mma <<<ROWS / 128, 256, MLP_SMEM>>>(bm1, bm2, x, out);
}

// round 16
// speedup vs baseline: 2.4729x; 1.0090x over previous
#include <cuda_runtime.h>
#include <cuda_bf16.h>
#include <cstdint>

#define BB  4
#define NN  4096
#define NBK 16
#define CD  128
#define HID 64
#define ROWS (BB*NN)            // 16384
#define GROWS (BB*NN*NBK)       // 262144
#define PAIRS (BB*NBK)          // 64
#define NSPLIT 8
#define BPITCH 136              // bf16 tile pitch (272 B rows)
#define HPITCH 72               // hs tile pitch (144 B rows)

// ---------------- scratch (device globals; no allocation allowed) ----------
__device__ float g_qkv [ROWS*3*CD];                 // 25 MB
__device__ unsigned short g_qb[ROWS][2][CD];        // prescaled Qn bf16 hi/lo
__device__ float g_kvp [NSPLIT][PAIRS*CD*CD];       // split partials 32 MB
__device__ unsigned short g_kvb[PAIRS][2][128*BPITCH]; // bf16 hi/lo kv images
__device__ unsigned short g_w2b[2][HID*BPITCH];     // W2^T images
__device__ unsigned short g_wm1b[4][2][128*BPITCH]; // Wm1^T chunk images [c][o]
__device__ unsigned short g_wm2b[4][2][128*BPITCH]; // Wm2^T chunk images [o][d]
__device__ unsigned short g_wqb[3][2][128*BPITCH];  // Wqkv^T chunk images [c][o]
__device__ int   g_idx64;

typedef unsigned long long u64;
__device__ __forceinline__ float4 ld4(const float* p) { return *(const float4*)p; }
__device__ __forceinline__ int ld_idx(const void* p, size_t pos) {
    if (g_idx64) return (int)((const long long*)p)[pos];
    return ((const int*)p)[pos];
}
__device__ __forceinline__ uint32_t smem_u32(const void* p) {
    uint32_t a;
    asm("{ .reg .u64 t; cvta.to.shared.u64 t, %1; cvt.u32.u64 %0, t; }" : "=r"(a) : "l"(p));
    return a;
}
__device__ __forceinline__ void bf_split(float x, unsigned short& h, unsigned short& l) {
    __nv_bfloat16 bh = __float2bfloat16(x);
    h = __bfloat16_as_ushort(bh);
    l = __bfloat16_as_ushort(__float2bfloat16(x - __bfloat162float(bh)));
}

#define LDSM_X4(r0,r1,r2,r3, a) \
    asm volatile("ldmatrix.sync.aligned.m8n8.x4.shared.b16 {%0,%1,%2,%3}, [%4];" \
        : "=r"(r0),"=r"(r1),"=r"(r2),"=r"(r3) : "r"(a))
#define LDSM_X4T(r0,r1,r2,r3, a) \
    asm volatile("ldmatrix.sync.aligned.m8n8.x4.trans.shared.b16 {%0,%1,%2,%3}, [%4];" \
        : "=r"(r0),"=r"(r1),"=r"(r2),"=r"(r3) : "r"(a))
#define MMA_BF16(d, a0,a1,a2,a3, b0,b1) \
    asm volatile("mma.sync.aligned.m16n8k16.row.col.f32.bf16.bf16.f32 " \
        "{%0,%1,%2,%3}, {%4,%5,%6,%7}, {%8,%9}, {%0,%1,%2,%3};" \
        : "+f"((d)[0]),"+f"((d)[1]),"+f"((d)[2]),"+f"((d)[3]) \
        : "r"(a0),"r"(a1),"r"(a2),"r"(a3), "r"(b0),"r"(b1))

// ---------------- idx dtype autodetect -------------------------------------
__global__ void k_detect(const unsigned int* __restrict__ w) {
    __shared__ int any;
    if (threadIdx.x == 0) any = 0;
    __syncthreads();
    unsigned int v = w[1 + 2 * threadIdx.x];
    if (v != 0u) any = 1;
    __syncthreads();
    if (threadIdx.x == 0) g_idx64 = (any ? 0 : 1);
}

// ---------------- K0: weight bf16 hi/lo pre-splits (runs first) -------------
// grid (2 variants, 12 targets, 4 z): 0=W2^T, 1..4=Wm1^T, 5..8=Wm2^T, 9..11=Wqkv^T
__global__ void __launch_bounds__(256) k_wsplit(const float* __restrict__ W2,
                                                const float* __restrict__ Wm1,
                                                const float* __restrict__ Wm2,
                                                const float* __restrict__ Wqkv) {
    const int v = blockIdx.x;
    const int w = blockIdx.y;
    const int tid = (int)(blockIdx.z * 256 + threadIdx.x);
    const int stride = 1024;
    if (w == 0) {
        for (int e = tid; e < CD * HID; e += stride) {
            int j = e >> 7, c = e & 127;
            float x = W2[(size_t)c * HID + j];
            __nv_bfloat16 bh = __float2bfloat16(x);
            unsigned short bits = v == 0 ? __bfloat16_as_ushort(bh)
                : __bfloat16_as_ushort(__float2bfloat16(x - __bfloat162float(bh)));
            g_w2b[v][j * BPITCH + c] = bits;
        }
    } else if (w <= 4) {
        const int oc = w - 1;
        for (int e = tid; e < CD * CD; e += stride) {
            int c = e >> 7, o = e & 127;
            float x = Wm1[(size_t)(oc * 128 + o) * CD + c];
            __nv_bfloat16 bh = __float2bfloat16(x);
            unsigned short bits = v == 0 ? __bfloat16_as_ushort(bh)
                : __bfloat16_as_ushort(__float2bfloat16(x - __bfloat162float(bh)));
            g_wm1b[oc][v][c * BPITCH + o] = bits;
        }
    } else if (w <= 8) {
        const int oc = w - 5;
        for (int e = tid; e < CD * CD; e += stride) {
            int ol = e >> 7, d = e & 127;
            float x = Wm2[(size_t)d * (4 * CD) + oc * 128 + ol];
            __nv_bfloat16 bh = __float2bfloat16(x);
            unsigned short bits = v == 0 ? __bfloat16_as_ushort(bh)
                : __bfloat16_as_ushort(__float2bfloat16(x - __bfloat162float(bh)));
            g_wm2b[oc][v][ol * BPITCH + d] = bits;
        }
    } else {
        const int oc = w - 9;
        for (int e = tid; e < CD * CD; e += stride) {
            int c = e >> 7, o = e & 127;
            float x = Wqkv[(size_t)(oc * 128 + o) * CD + c];
            __nv_bfloat16 bh = __float2bfloat16(x);
            unsigned short bits = v == 0 ? __bfloat16_as_ushort(bh)
                : __bfloat16_as_ushort(__float2bfloat16(x - __bfloat162float(bh)));
            g_wqb[oc][v][c * BPITCH + o] = bits;
        }
    }
}

// ---------------- K1: qkv via mma.sync --------------------------------------
// grid (128 row-blocks, 3 o-chunks); A = x[c][n] tiles (trans+reorder), B = g_wqb
#define QK_A_H 0
#define QK_A_L (32*BPITCH*2)
#define QK_B_H (2*32*BPITCH*2)
#define QK_B_L (QK_B_H + 128*BPITCH*2)
#define QK_SMEM (QK_B_H + 2*128*BPITCH*2)

__global__ void __launch_bounds__(256, 2) k_qkv_mma(const float* __restrict__ x) {
    extern __shared__ __align__(16) unsigned char dsm[];
    const uint32_t sb = smem_u32(dsm);
    const int tid = threadIdx.x;
    const int wid = tid >> 5, lane = tid & 31;
    const int row0 = blockIdx.x * 128;          // flattened b*NN + n
    const int b = row0 >> 12;
    const int n0 = row0 & (NN - 1);
    const int oc = blockIdx.y;
    const int m0 = wid * 16;

    // resident B images
    {
        uint4* Bh = (uint4*)(dsm + QK_B_H);
        uint4* Bl = (uint4*)(dsm + QK_B_L);
        const uint4* sh = (const uint4*)&g_wqb[oc][0][0];
        const uint4* sl = (const uint4*)&g_wqb[oc][1][0];
        for (int e = tid; e < (128 * BPITCH * 2) / 16; e += 256) {
            Bh[e] = sh[e];
            Bl[e] = sl[e];
        }
    }

    const int rowSel = lane & 15;
    const int colSel = (lane >> 4) << 3;
    const uint32_t aTerm = (uint32_t)((rowSel * BPITCH + m0 + colSel) * 2);
    const uint32_t bTerm = (uint32_t)((rowSel * BPITCH + colSel) * 2);
    const int g = lane >> 2, t = lane & 3;

    float facc[16][4] = {};

    for (int cstep = 0; cstep < 4; cstep++) {
        __syncthreads();     // prior A reads done (and B load on cstep 0)
        // stage A: 32 c-rows x 128 n, hi/lo, layout [cc][n]
        {
            unsigned short* Ah = (unsigned short*)(dsm + QK_A_H);
            unsigned short* Al = (unsigned short*)(dsm + QK_A_L);
#pragma unroll
            for (int p = 0; p < 16; p++) {
                int v = tid + p * 256;
                int cc = v >> 7, n = v & 127;
                float xv = x[((size_t)b * CD + cstep * 32 + cc) * NN + n0 + n];
                unsigned short h, l;
                bf_split(xv, h, l);
                Ah[cc * BPITCH + n] = h;
                Al[cc * BPITCH + n] = l;
            }
        }
        __syncthreads();
#pragma unroll
        for (int c2 = 0; c2 < 2; c2++) {
            const uint32_t cOffA = (uint32_t)(c2 * 16 * BPITCH * 2);
            uint32_t t0, t1, t2, t3;
            uint32_t ah0, ah1, ah2, ah3, al0, al1, al2, al3;
            LDSM_X4T(t0, t1, t2, t3, sb + QK_A_H + aTerm + cOffA);
            ah0 = t0; ah1 = t2; ah2 = t1; ah3 = t3;
            LDSM_X4T(t0, t1, t2, t3, sb + QK_A_L + aTerm + cOffA);
            al0 = t0; al1 = t2; al2 = t1; al3 = t3;
            const uint32_t bBase = sb + QK_B_H + bTerm
                + (uint32_t)((cstep * 32 + c2 * 16) * BPITCH * 2);
#pragma unroll
            for (int dblk = 0; dblk < 8; dblk++) {
                uint32_t bh0, bh1, bh2, bh3, bl0, bl1, bl2, bl3;
                uint32_t bAddr = bBase + (uint32_t)(dblk * 16 * 2);
                LDSM_X4T(bh0, bh1, bh2, bh3, bAddr);
                LDSM_X4T(bl0, bl1, bl2, bl3, bAddr + (QK_B_L - QK_B_H));
                float* d0 = facc[dblk * 2];
                float* d1 = facc[dblk * 2 + 1];
                MMA_BF16(d0, ah0, ah1, ah2, ah3, bh0, bh1);
                MMA_BF16(d1, ah0, ah1, ah2, ah3, bh2, bh3);
                MMA_BF16(d0, al0, al1, al2, al3, bh0, bh1);
                MMA_BF16(d1, al0, al1, al2, al3, bh2, bh3);
                MMA_BF16(d0, ah0, ah1, ah2, ah3, bl0, bl1);
                MMA_BF16(d1, ah0, ah1, ah2, ah3, bl2, bl3);
            }
        }
    }
#pragma unroll
    for (int dt = 0; dt < 16; dt++) {
        int col = oc * 128 + dt * 8 + t * 2;
        size_t r1 = (size_t)(row0 + m0 + g) * (3 * CD) + col;
        size_t r2 = (size_t)(row0 + m0 + 8 + g) * (3 * CD) + col;
        *(float2*)&g_qkv[r1] = make_float2(facc[dt][0], facc[dt][1]);
        *(float2*)&g_qkv[r2] = make_float2(facc[dt][2], facc[dt][3]);
    }
}

// ---------------- K1b: Qn = Q/||Q|| -> bf16 hi/lo images --------------------
__global__ void __launch_bounds__(256) k_qsplit() {
    int row  = blockIdx.x * 8 + (threadIdx.x >> 5);
    int lane = threadIdx.x & 31;
    float4 q = ld4(&g_qkv[(size_t)row * (3 * CD) + lane * 4]);
    float s = q.x * q.x + q.y * q.y + q.z * q.z + q.w * q.w;
#pragma unroll
    for (int o = 16; o; o >>= 1) s += __shfl_xor_sync(0xffffffffu, s, o);
    float sc = 1.0f / fmaxf(sqrtf(s), 1e-12f);
    float xs[4] = {q.x * sc, q.y * sc, q.z * sc, q.w * sc};
    unsigned short h[4], l[4];
#pragma unroll
    for (int i = 0; i < 4; i++) bf_split(xs[i], h[i], l[i]);
    uint2 vh = make_uint2((uint32_t)h[0] | ((uint32_t)h[1] << 16),
                          (uint32_t)h[2] | ((uint32_t)h[3] << 16));
    uint2 vl = make_uint2((uint32_t)l[0] | ((uint32_t)l[1] << 16),
                          (uint32_t)l[2] | ((uint32_t)l[3] << 16));
    *(uint2*)&g_qb[row][0][lane * 4] = vh;
    *(uint2*)&g_qb[row][1][lane * 4] = vl;
}

// ---------------- K3: FUSED pos-MLP + kv outer product via mma.sync ---------
#define KV_KN_H 0
#define KV_KN_L (32*BPITCH*2)
#define KV_VR_H (2*32*BPITCH*2)
#define KV_VR_L (3*32*BPITCH*2)
#define KV_W2_H (4*32*BPITCH*2)
#define KV_W2_L (KV_W2_H + HID*BPITCH*2)
#define KV_HS_H (KV_W2_H + 2*HID*BPITCH*2)
#define KV_HS_L (KV_HS_H + 32*HPITCH*2)
#define KV_PE   (KV_HS_H + 2*32*HPITCH*2)
#define KV_SMEM (KV_PE + 32*132*4)
#define PEP 132

__global__ void __launch_bounds__(256, 2) k_kv_mma(
    const float* __restrict__ pos, const void* __restrict__ idx,
    const float* __restrict__ dist,
    const float* __restrict__ W1, const float* __restrict__ b1,
    const float* __restrict__ b2) {
    extern __shared__ __align__(16) unsigned char dsm[];
    __shared__ float W1s[HID * 10];
    __shared__ float b1s[HID];
    __shared__ float b2s[CD];
    __shared__ float feats[32][12];
    __shared__ int   jr[32];
    const uint32_t sb = smem_u32(dsm);
    const int p = blockIdx.y;
    const int s = blockIdx.x;
    const int b = p >> 4, kslot = p & 15;
    const int tid = threadIdx.x;
    const int lane = tid & 31, warp = tid >> 5;
    const int c4 = lane * 4;
    const int m0 = warp * 16;

    for (int v = tid; v < HID * 10; v += 256) W1s[v] = W1[v];
    if (tid < HID) b1s[tid] = b1[tid];
    if (tid < CD)  b2s[tid] = b2[tid];
    {
        uint4* Wh = (uint4*)(dsm + KV_W2_H);
        uint4* Wl = (uint4*)(dsm + KV_W2_L);
        const uint4* sh = (const uint4*)&g_w2b[0][0];
        const uint4* sl = (const uint4*)&g_w2b[1][0];
        for (int e = tid; e < (HID * BPITCH * 2) / 16; e += 256) {
            Wh[e] = sh[e];
            Wl[e] = sl[e];
        }
    }

    const int rowSel = lane & 15;
    const int colSel = (lane >> 4) << 3;
    const uint32_t aTerm = (uint32_t)((rowSel * BPITCH + m0 + colSel) * 2);
    const uint32_t bTerm = (uint32_t)((rowSel * BPITCH + colSel) * 2);
    const int mt = warp & 1, ng = warp >> 1;
    const uint32_t aTermP = (uint32_t)(((mt * 16 + rowSel) * HPITCH + colSel) * 2);
    const uint32_t bTermP = (uint32_t)((rowSel * BPITCH + ng * 32 + colSel) * 2);
    const int g = lane >> 2, t = lane & 3;

    float facc[16][4] = {};

    const int n0 = s * (NN / NSPLIT);
    const int NSTEP = (NN / NSPLIT) / 32;
    for (int step = 0; step < NSTEP; step++) {
        const int nbase = n0 + step * 32;
        __syncthreads();
        if (tid < 32) {
            int n = nbase + tid;
            size_t gg = ((size_t)(b * NN + n)) * NBK + kslot;
            int j = ld_idx(idx, gg);
            jr[tid] = j;
            const float* pc = &pos[((size_t)b * NN + n) * 3];
            const float* pn = &pos[((size_t)b * NN + j) * 3];
            float a0 = pc[0], a1 = pc[1], a2 = pc[2];
            float q0 = pn[0], q1 = pn[1], q2 = pn[2];
            feats[tid][0] = a0;  feats[tid][1] = a1;  feats[tid][2] = a2;
            feats[tid][3] = q0;  feats[tid][4] = q1;  feats[tid][5] = q2;
            feats[tid][6] = a0 - q0; feats[tid][7] = a1 - q1; feats[tid][8] = a2 - q2;
            feats[tid][9] = dist[gg];
        }
        __syncthreads();
        {
            unsigned short* Hh = (unsigned short*)(dsm + KV_HS_H);
            unsigned short* Hl = (unsigned short*)(dsm + KV_HS_L);
#pragma unroll
            for (int pp = 0; pp < 8; pp++) {
                int v = tid + pp * 256;
                int j = v & 63, r = v >> 6;
                float sm = b1s[j];
#pragma unroll
                for (int i = 0; i < 10; i++) sm += feats[r][i] * W1s[j * 10 + i];
                sm = fmaxf(sm, 0.0f);
                unsigned short h, l;
                bf_split(sm, h, l);
                Hh[r * HPITCH + j] = h;
                Hl[r * HPITCH + j] = l;
            }
        }
        __syncthreads();
        {
            float pacc[2][2][4] = {};
#pragma unroll
            for (int cc = 0; cc < 4; cc++) {
                uint32_t ah0, ah1, ah2, ah3, al0, al1, al2, al3;
                uint32_t aAddr = sb + KV_HS_H + aTermP + (uint32_t)(cc * 16 * 2);
                LDSM_X4(ah0, ah1, ah2, ah3, aAddr);
                LDSM_X4(al0, al1, al2, al3, aAddr + (KV_HS_L - KV_HS_H));
                uint32_t bBase = sb + KV_W2_H + bTermP + (uint32_t)(cc * 16 * BPITCH * 2);
#pragma unroll
                for (int d2 = 0; d2 < 2; d2++) {
                    uint32_t bh0, bh1, bh2, bh3, bl0, bl1, bl2, bl3;
                    uint32_t bAddr = bBase + (uint32_t)(d2 * 16 * 2);
                    LDSM_X4T(bh0, bh1, bh2, bh3, bAddr);
                    LDSM_X4T(bl0, bl1, bl2, bl3, bAddr + (KV_W2_L - KV_W2_H));
                    float* d0 = pacc[d2][0];
                    float* d1 = pacc[d2][1];
                    MMA_BF16(d0, ah0, ah1, ah2, ah3, bh0, bh1);
                    MMA_BF16(d1, ah0, ah1, ah2, ah3, bh2, bh3);
                    MMA_BF16(d0, al0, al1, al2, al3, bh0, bh1);
                    MMA_BF16(d1, al0, al1, al2, al3, bh2, bh3);
                    MMA_BF16(d0, ah0, ah1, ah2, ah3, bl0, bl1);
                    MMA_BF16(d1, ah0, ah1, ah2, ah3, bl2, bl3);
                }
            }
            float* PE = (float*)(dsm + KV_PE);
#pragma unroll
            for (int d2 = 0; d2 < 2; d2++)
#pragma unroll
                for (int hf = 0; hf < 2; hf++) {
                    int col = ng * 32 + d2 * 16 + hf * 8 + t * 2;
                    float bx = b2s[col], by = b2s[col + 1];
                    int r1 = mt * 16 + g, r2 = mt * 16 + 8 + g;
                    *(float2*)&PE[r1 * PEP + col] =
                        make_float2(pacc[d2][hf][0] + bx, pacc[d2][hf][1] + by);
                    *(float2*)&PE[r2 * PEP + col] =
                        make_float2(pacc[d2][hf][2] + bx, pacc[d2][hf][3] + by);
                }
        }
        __syncthreads();
        {
            unsigned short* KnH = (unsigned short*)(dsm + KV_KN_H);
            unsigned short* KnL = (unsigned short*)(dsm + KV_KN_L);
            unsigned short* VrH = (unsigned short*)(dsm + KV_VR_H);
            unsigned short* VrL = (unsigned short*)(dsm + KV_VR_L);
            const float* PE = (const float*)(dsm + KV_PE);
#pragma unroll
            for (int rr = 0; rr < 4; rr++) {
                int row = warp * 4 + rr;
                int j = jr[row];
                float4 pe = ld4(&PE[row * PEP + c4]);
                const float* qrow = &g_qkv[((size_t)b * NN + j) * (3 * CD)];
                float4 kg = ld4(&qrow[CD + c4]);
                float4 vg = ld4(&qrow[2 * CD + c4]);
                float k0 = kg.x + pe.x, k1 = kg.y + pe.y, k2 = kg.z + pe.z, k3 = kg.w + pe.w;
                float v0 = fmaxf(vg.x + pe.x, 0.f), v1 = fmaxf(vg.y + pe.y, 0.f);
                float v2 = fmaxf(vg.z + pe.z, 0.f), v3 = fmaxf(vg.w + pe.w, 0.f);
                float ss = k0 * k0 + k1 * k1 + k2 * k2 + k3 * k3;
#pragma unroll
                for (int o = 16; o; o >>= 1) ss += __shfl_xor_sync(0xffffffffu, ss, o);
                float sc = 1.0f / fmaxf(sqrtf(ss), 1e-12f);
                k0 *= sc; k1 *= sc; k2 *= sc; k3 *= sc;
                unsigned short kh[4], kl[4], vh[4], vl[4];
                bf_split(k0, kh[0], kl[0]); bf_split(k1, kh[1], kl[1]);
                bf_split(k2, kh[2], kl[2]); bf_split(k3, kh[3], kl[3]);
                bf_split(v0, vh[0], vl[0]); bf_split(v1, vh[1], vl[1]);
                bf_split(v2, vh[2], vl[2]); bf_split(v3, vh[3], vl[3]);
                int off = row * BPITCH + c4;
                *(uint2*)&KnH[off] = make_uint2((uint32_t)kh[0] | ((uint32_t)kh[1] << 16),
                                                (uint32_t)kh[2] | ((uint32_t)kh[3] << 16));
                *(uint2*)&KnL[off] = make_uint2((uint32_t)kl[0] | ((uint32_t)kl[1] << 16),
                                                (uint32_t)kl[2] | ((uint32_t)kl[3] << 16));
                *(uint2*)&VrH[off] = make_uint2((uint32_t)vh[0] | ((uint32_t)vh[1] << 16),
                                                (uint32_t)vh[2] | ((uint32_t)vh[3] << 16));
                *(uint2*)&VrL[off] = make_uint2((uint32_t)vl[0] | ((uint32_t)vl[1] << 16),
                                                (uint32_t)vl[2] | ((uint32_t)vl[3] << 16));
            }
        }
        __syncthreads();
#pragma unroll
        for (int cc = 0; cc < 2; cc++) {
            const uint32_t cOff = (uint32_t)(cc * 16 * BPITCH * 2);
            uint32_t t0, t1, t2, t3;
            uint32_t ah0, ah1, ah2, ah3, al0, al1, al2, al3;
            LDSM_X4T(t0, t1, t2, t3, sb + KV_KN_H + aTerm + cOff);
            ah0 = t0; ah1 = t2; ah2 = t1; ah3 = t3;
            LDSM_X4T(t0, t1, t2, t3, sb + KV_KN_L + aTerm + cOff);
            al0 = t0; al1 = t2; al2 = t1; al3 = t3;
#pragma unroll
            for (int dblk = 0; dblk < 8; dblk++) {
                uint32_t bh0, bh1, bh2, bh3, bl0, bl1, bl2, bl3;
                uint32_t bOff = bTerm + cOff + (uint32_t)(dblk * 16 * 2);
                LDSM_X4T(bh0, bh1, bh2, bh3, sb + KV_VR_H + bOff);
                LDSM_X4T(bl0, bl1, bl2, bl3, sb + KV_VR_L + bOff);
                float* d0 = facc[dblk * 2];
                float* d1 = facc[dblk * 2 + 1];
                MMA_BF16(d0, ah0, ah1, ah2, ah3, bh0, bh1);
                MMA_BF16(d1, ah0, ah1, ah2, ah3, bh2, bh3);
                MMA_BF16(d0, al0, al1, al2, al3, bh0, bh1);
                MMA_BF16(d1, al0, al1, al2, al3, bh2, bh3);
                MMA_BF16(d0, ah0, ah1, ah2, ah3, bl0, bl1);
                MMA_BF16(d1, ah0, ah1, ah2, ah3, bl2, bl3);
            }
        }
    }
    float* op = &g_kvp[s][(size_t)p * CD * CD];
#pragma unroll
    for (int dt = 0; dt < 16; dt++) {
        int col = dt * 8 + t * 2;
        *(float2*)&op[(size_t)(m0 + g) * CD + col]     = make_float2(facc[dt][0], facc[dt][1]);
        *(float2*)&op[(size_t)(m0 + 8 + g) * CD + col] = make_float2(facc[dt][2], facc[dt][3]);
    }
}

// ---------------- K3b: reduce partials + split to bf16 hi/lo (4-way) --------
__global__ void __launch_bounds__(256) k_redsplit() {
    const int p = blockIdx.x;
    const int e0 = (int)blockIdx.y * 4096;
    const int tid = threadIdx.x;
    for (int e = e0 + tid; e < e0 + 4096; e += 256) {
        int c = e >> 7, d = e & 127;
        float s = 0.0f;
#pragma unroll
        for (int t = 0; t < NSPLIT; t++) s += g_kvp[t][(size_t)p * CD * CD + e];
        unsigned short h, l;
        bf_split(s, h, l);
        g_kvb[p][0][c * BPITCH + d] = h;
        g_kvb[p][1][c * BPITCH + d] = l;
    }
}

// ---------------- K4: FUSED agg + out-MLP via mma.sync ----------------------
#define MLP_A0 0
#define MLP_A1 34816
#define MLP_B0 69632
#define MLP_B1 104448
#define MLP_H0 139264
#define MLP_H1 174080
#define MLP_SMEM 208896
#define EP 129

__global__ void __launch_bounds__(256, 1) k_aggmlp_mma(
    const void* __restrict__ idx,
    const float* __restrict__ bm1, const float* __restrict__ bm2,
    const float* __restrict__ x, float* __restrict__ out) {
    extern __shared__ __align__(16) unsigned char dsm[];
    __shared__ int jr[128];
    __shared__ float bm1s[4 * CD];
    __shared__ float bm2s[CD];
    const uint32_t sb = smem_u32(dsm);
    const int tid = threadIdx.x;
    const int wid = tid >> 5, lane = tid & 31;
    const int row0 = blockIdx.x * 128;
    const int b = row0 >> 12;
    const int n0 = row0 & (NN - 1);
    const int m0 = wid * 16;

    if (tid < CD) bm2s[tid] = bm2[tid];
    for (int v = tid; v < 4 * CD; v += 256) bm1s[v] = bm1[v];

    const int rowSel = lane & 15;
    const int colSel = (lane >> 4) << 3;
    const uint32_t aTerm = (uint32_t)(((m0 + rowSel) * BPITCH + colSel) * 2);
    const uint32_t bTerm = (uint32_t)((rowSel * BPITCH + colSel) * 2);
    const int g = lane >> 2, t = lane & 3;
    const int arow = tid >> 1, ahalf = tid & 1;

    // ===== agg phase =====
    float facc[16][4] = {};
    for (int k = 0; k < NBK; k++) {
        __syncthreads();
        if (tid < 128) {
            jr[tid] = ld_idx(idx, ((size_t)(row0 + tid)) * NBK + k);
        }
        __syncthreads();
        {
            int j = b * NN + jr[arow];
            const uint4* srcH = (const uint4*)&g_qb[j][0][ahalf * 64];
            const uint4* srcL = (const uint4*)&g_qb[j][1][ahalf * 64];
            uint4* dH = (uint4*)(dsm + MLP_A0 + (uint32_t)((arow * BPITCH + ahalf * 64) * 2));
            uint4* dL = (uint4*)(dsm + MLP_A1 + (uint32_t)((arow * BPITCH + ahalf * 64) * 2));
#pragma unroll
            for (int q = 0; q < 8; q++) {
                dH[q] = srcH[q];
                dL[q] = srcL[q];
            }
        }
        {
            const int p = b * NBK + k;
            uint4* Bh = (uint4*)(dsm + MLP_B0);
            uint4* Bl = (uint4*)(dsm + MLP_B1);
            const uint4* sh = (const uint4*)&g_kvb[p][0][0];
            const uint4* sl = (const uint4*)&g_kvb[p][1][0];
            for (int e = tid; e < (128 * BPITCH * 2) / 16; e += 256) {
                Bh[e] = sh[e];
                Bl[e] = sl[e];
            }
        }
        __syncthreads();
#pragma unroll 1
        for (int cc = 0; cc < 8; cc++) {
            uint32_t ah0, ah1, ah2, ah3, al0, al1, al2, al3;
            uint32_t aAddr = sb + MLP_A0 + aTerm + (uint32_t)(cc * 16 * 2);
            LDSM_X4(ah0, ah1, ah2, ah3, aAddr);
            LDSM_X4(al0, al1, al2, al3, aAddr + (MLP_A1 - MLP_A0));
            uint32_t bBase = sb + MLP_B0 + bTerm + (uint32_t)(cc * 16 * BPITCH * 2);
#pragma unroll
            for (int dblk = 0; dblk < 8; dblk++) {
                uint32_t bh0, bh1, bh2, bh3, bl0, bl1, bl2, bl3;
                uint32_t bAddr = bBase + (uint32_t)(dblk * 16 * 2);
                LDSM_X4T(bh0, bh1, bh2, bh3, bAddr);
                LDSM_X4T(bl0, bl1, bl2, bl3, bAddr + (MLP_B1 - MLP_B0));
                float* d0 = facc[dblk * 2];
                float* d1 = facc[dblk * 2 + 1];
                MMA_BF16(d0, ah0, ah1, ah2, ah3, bh0, bh1);
                MMA_BF16(d1, ah0, ah1, ah2, ah3, bh2, bh3);
                MMA_BF16(d0, al0, al1, al2, al3, bh0, bh1);
                MMA_BF16(d1, al0, al1, al2, al3, bh2, bh3);
                MMA_BF16(d0, ah0, ah1, ah2, ah3, bl0, bl1);
                MMA_BF16(d1, ah0, ah1, ah2, ah3, bl2, bl3);
            }
        }
    }
    // ===== transition: agg result (x 1/N) -> bf16 hi/lo A tiles (own rows) ===
    {
        const float inv = 1.0f / (float)NN;
        unsigned short* Ah = (unsigned short*)(dsm + MLP_A0);
        unsigned short* Al = (unsigned short*)(dsm + MLP_A1);
#pragma unroll
        for (int dt = 0; dt < 16; dt++) {
            int col = dt * 8 + t * 2;
            float a0 = facc[dt][0] * inv, a1 = facc[dt][1] * inv;
            float a2 = facc[dt][2] * inv, a3 = facc[dt][3] * inv;
            unsigned short h0, l0, h1, l1, h2, l2, h3, l3;
            bf_split(a0, h0, l0); bf_split(a1, h1, l1);
            bf_split(a2, h2, l2); bf_split(a3, h3, l3);
            int r1 = m0 + g, r2 = m0 + 8 + g;
            *(uint32_t*)&Ah[r1 * BPITCH + col] = (uint32_t)h0 | ((uint32_t)h1 << 16);
            *(uint32_t*)&Al[r1 * BPITCH + col] = (uint32_t)l0 | ((uint32_t)l1 << 16);
            *(uint32_t*)&Ah[r2 * BPITCH + col] = (uint32_t)h2 | ((uint32_t)h3 << 16);
            *(uint32_t*)&Al[r2 * BPITCH + col] = (uint32_t)l2 | ((uint32_t)l3 << 16);
        }
    }
    // ===== MLP phase =====
    float facc2[16][4] = {};
    for (int oc = 0; oc < 4; oc++) {
        __syncthreads();
        {
            uint4* Bh = (uint4*)(dsm + MLP_B0);
            uint4* Bl = (uint4*)(dsm + MLP_B1);
            const uint4* sh = (const uint4*)&g_wm1b[oc][0][0];
            const uint4* sl = (const uint4*)&g_wm1b[oc][1][0];
            for (int e = tid; e < (128 * BPITCH * 2) / 16; e += 256) {
                Bh[e] = sh[e];
                Bl[e] = sl[e];
            }
        }
        __syncthreads();
        float facc1[16][4] = {};
#pragma unroll 1
        for (int cc = 0; cc < 8; cc++) {
            uint32_t ah0, ah1, ah2, ah3, al0, al1, al2, al3;
            uint32_t aAddr = sb + MLP_A0 + aTerm + (uint32_t)(cc * 16 * 2);
            LDSM_X4(ah0, ah1, ah2, ah3, aAddr);
            LDSM_X4(al0, al1, al2, al3, aAddr + (MLP_A1 - MLP_A0));
            uint32_t bBase = sb + MLP_B0 + bTerm + (uint32_t)(cc * 16 * BPITCH * 2);
#pragma unroll
            for (int dblk = 0; dblk < 8; dblk++) {
                uint32_t bh0, bh1, bh2, bh3, bl0, bl1, bl2, bl3;
                uint32_t bAddr = bBase + (uint32_t)(dblk * 16 * 2);
                LDSM_X4T(bh0, bh1, bh2, bh3, bAddr);
                LDSM_X4T(bl0, bl1, bl2, bl3, bAddr + (MLP_B1 - MLP_B0));
                float* d0 = facc1[dblk * 2];
                float* d1 = facc1[dblk * 2 + 1];
                MMA_BF16(d0, ah0, ah1, ah2, ah3, bh0, bh1);
                MMA_BF16(d1, ah0, ah1, ah2, ah3, bh2, bh3);
                MMA_BF16(d0, al0, al1, al2, al3, bh0, bh1);
                MMA_BF16(d1, al0, al1, al2, al3, bh2, bh3);
                MMA_BF16(d0, ah0, ah1, ah2, ah3, bl0, bl1);
                MMA_BF16(d1, ah0, ah1, ah2, ah3, bl2, bl3);
            }
        }
        {
            unsigned short* Hh = (unsigned short*)(dsm + MLP_H0);
            unsigned short* Hl = (unsigned short*)(dsm + MLP_H1);
#pragma unroll
            for (int dt = 0; dt < 16; dt++) {
                int col = dt * 8 + t * 2;
                float bx = bm1s[oc * 128 + col], by = bm1s[oc * 128 + col + 1];
                float h0 = fmaxf(facc1[dt][0] + bx, 0.f);
                float h1 = fmaxf(facc1[dt][1] + by, 0.f);
                float h2 = fmaxf(facc1[dt][2] + bx, 0.f);
                float h3 = fmaxf(facc1[dt][3] + by, 0.f);
                unsigned short hh0, hl0, hh1, hl1, hh2, hl2, hh3, hl3;
                bf_split(h0, hh0, hl0); bf_split(h1, hh1, hl1);
                bf_split(h2, hh2, hl2); bf_split(h3, hh3, hl3);
                int r1 = m0 + g, r2 = m0 + 8 + g;
                *(uint32_t*)&Hh[r1 * BPITCH + col] = (uint32_t)hh0 | ((uint32_t)hh1 << 16);
                *(uint32_t*)&Hl[r1 * BPITCH + col] = (uint32_t)hl0 | ((uint32_t)hl1 << 16);
                *(uint32_t*)&Hh[r2 * BPITCH + col] = (uint32_t)hh2 | ((uint32_t)hh3 << 16);
                *(uint32_t*)&Hl[r2 * BPITCH + col] = (uint32_t)hl2 | ((uint32_t)hl3 << 16);
            }
        }
        __syncthreads();
        {
            uint4* Bh = (uint4*)(dsm + MLP_B0);
            uint4* Bl = (uint4*)(dsm + MLP_B1);
            const uint4* sh = (const uint4*)&g_wm2b[oc][0][0];
            const uint4* sl = (const uint4*)&g_wm2b[oc][1][0];
            for (int e = tid; e < (128 * BPITCH * 2) / 16; e += 256) {
                Bh[e] = sh[e];
                Bl[e] = sl[e];
            }
        }
        __syncthreads();
#pragma unroll 1
        for (int cc = 0; cc < 8; cc++) {
            uint32_t ah0, ah1, ah2, ah3, al0, al1, al2, al3;
            uint32_t aAddr = sb + MLP_H0 + aTerm + (uint32_t)(cc * 16 * 2);
            LDSM_X4(ah0, ah1, ah2, ah3, aAddr);
            LDSM_X4(al0, al1, al2, al3, aAddr + (MLP_H1 - MLP_H0));
            uint32_t bBase = sb + MLP_B0 + bTerm + (uint32_t)(cc * 16 * BPITCH * 2);
#pragma unroll
            for (int dblk = 0; dblk < 8; dblk++) {
                uint32_t bh0, bh1, bh2, bh3, bl0, bl1, bl2, bl3;
                uint32_t bAddr = bBase + (uint32_t)(dblk * 16 * 2);
                LDSM_X4T(bh0, bh1, bh2, bh3, bAddr);
                LDSM_X4T(bl0, bl1, bl2, bl3, bAddr + (MLP_B1 - MLP_B0));
                float* d0 = facc2[dblk * 2];
                float* d1 = facc2[dblk * 2 + 1];
                MMA_BF16(d0, ah0, ah1, ah2, ah3, bh0, bh1);
                MMA_BF16(d1, ah0, ah1, ah2, ah3, bh2, bh3);
                MMA_BF16(d0, al0, al1, al2, al3, bh0, bh1);
                MMA_BF16(d1, al0, al1, al2, al3, bh2, bh3);
                MMA_BF16(d0, ah0, ah1, ah2, ah3, bl0, bl1);
                MMA_BF16(d1, ah0, ah1, ah2, ah3, bl2, bl3);
            }
        }
    }
    __syncthreads();
    {
        float* Cst = (float*)(dsm + MLP_A0);
#pragma unroll
        for (int dt = 0; dt < 16; dt++) {
            int col = dt * 8 + t * 2;
            float bx = bm2s[col], by = bm2s[col + 1];
            int r1 = m0 + g, r2 = m0 + 8 + g;
            Cst[r1 * EP + col]     = facc2[dt][0] + bx;
            Cst[r1 * EP + col + 1] = facc2[dt][1] + by;
            Cst[r2 * EP + col]     = facc2[dt][2] + bx;
            Cst[r2 * EP + col + 1] = facc2[dt][3] + by;
        }
    }
    __syncthreads();
    {
        const float* Cst = (const float*)(dsm + MLP_A0);
        for (int v = tid; v < 128 * CD; v += 256) {
            int dd = v >> 7, nn = v & 127;
            size_t oa = ((size_t)b * CD + dd) * NN + n0 + nn;
            out[oa] = Cst[nn * EP + dd] + x[oa];
        }
    }
}

// ---------------- launcher ---------------------------------------------------
extern "C" void kernel_launch(void* const* d_in, const int* in_sizes, int n_in,
                              void* d_out, int out_size) {
    (void)in_sizes; (void)n_in; (void)out_size;
    const float* pos  = (const float*)d_in[0];
    const float* x    = (const float*)d_in[1];
    const void*  idx  = d_in[2];
    const float* dist = (const float*)d_in[3];
    const float* Wqkv = (const float*)d_in[4];
    const float* W1   = (const float*)d_in[5];
    const float* b1   = (const float*)d_in[6];
    const float* W2   = (const float*)d_in[7];
    const float* b2   = (const float*)d_in[8];
    const float* Wm1  = (const float*)d_in[9];
    const float* bm1  = (const float*)d_in[10];
    const float* Wm2  = (const float*)d_in[11];
    const float* bm2  = (const float*)d_in[12];
    float* out = (float*)d_out;

    cudaFuncSetAttribute(k_qkv_mma,    cudaFuncAttributeMaxDynamicSharedMemorySize, QK_SMEM);
    cudaFuncSetAttribute(k_kv_mma,     cudaFuncAttributeMaxDynamicSharedMemorySize, KV_SMEM);
    cudaFuncSetAttribute(k_aggmlp_mma, cudaFuncAttributeMaxDynamicSharedMemorySize, MLP_SMEM);

    k_detect   <<<1, 256>>>((const unsigned int*)idx);
    k_wsplit   <<<dim3(2, 12, 4), 256>>>(W2, Wm1, Wm2, Wqkv);
    k_qkv_mma  <<<dim3(ROWS / 128, 3), 256, QK_SMEM>>>(x);
    k_qsplit   <<<ROWS / 8, 256>>>();
    k_kv_mma   <<<dim3(NSPLIT, PAIRS), 256, KV_SMEM>>>(pos, idx, dist, W1, b1, b2);
    k_redsplit <<<dim3(PAIRS, 4), 256>>>();
    k_aggmlp_mma<<<ROWS / 128, 256, MLP_SMEM>>>(idx, bm1, bm2, x, out);
}